// round 2
// baseline (speedup 1.0000x reference)
#include <cuda_runtime.h>
#include <math.h>

#define L 2048
#define DM 512
#define NH 8
#define DH 64
#define MF 128
#define CHK 64
#define NC (L/CHK)   // 32

#define SCALE_QK 0.2102241038134287f     // 512^-0.25
#define NC_COEF  0.08838834764831845f    // 128^-0.5
#define KEPS 1e-4f
#define DEPS 1e-6f

// ---------------- device scratch (no allocations allowed) ----------------
__device__ float g_q[L*DM];
__device__ float g_k[L*DM];
__device__ float g_v[L*DM];
__device__ float g_rft[MF*DH];          // random_features transposed: [m][d]
__device__ float g_pq[NH*L*MF];         // proj_q -> q'
__device__ float g_pk[NH*L*MF];         // proj_k -> k'
__device__ float g_hk[NH*L];
__device__ unsigned g_kstab;
__device__ float g_S[NH*NC*MF*DH];      // per-chunk states -> exclusive prefix
__device__ float g_z[NH*NC*MF];
__device__ float g_ctx[L*DM];

// orderable float encoding for atomic max
__device__ __forceinline__ unsigned enc_f(float f){
    unsigned u = __float_as_uint(f);
    return (u & 0x80000000u) ? ~u : (u | 0x80000000u);
}
__device__ __forceinline__ float dec_f(unsigned k){
    unsigned u = (k & 0x80000000u) ? (k ^ 0x80000000u) : ~k;
    return __uint_as_float(u);
}

// ---------------- generic SGEMM: C = alpha*(A@B^T + bias) ----------------
// A: M x K row-major (lda), B: N x K row-major (ldb), C: M x N (ldc)
// BM=BN=128, BK=8, 256 threads, 8x8 per thread. Dims must divide tiles.
__global__ void sgemm_abt(const float* __restrict__ A, int lda, long long sA,
                          const float* __restrict__ B, int ldb, long long sB,
                          const float* __restrict__ bias,
                          float* __restrict__ C, int ldc, long long sC,
                          int K, float alpha)
{
    __shared__ float As[8][128];
    __shared__ float Bs[8][128];
    A += (long long)blockIdx.z * sA;
    B += (long long)blockIdx.z * sB;
    C += (long long)blockIdx.z * sC;
    int m0 = blockIdx.y * 128, n0 = blockIdx.x * 128;
    int tid = threadIdx.x;
    int ty = tid >> 4, tx = tid & 15;
    int lr = tid >> 1, lk = (tid & 1) * 4;

    float acc[8][8];
#pragma unroll
    for (int i = 0; i < 8; i++)
#pragma unroll
        for (int j = 0; j < 8; j++) acc[i][j] = 0.f;

    for (int k0 = 0; k0 < K; k0 += 8) {
        float4 av = *(const float4*)(A + (size_t)(m0 + lr) * lda + k0 + lk);
        float4 bv = *(const float4*)(B + (size_t)(n0 + lr) * ldb + k0 + lk);
        __syncthreads();
        As[lk+0][lr] = av.x; As[lk+1][lr] = av.y; As[lk+2][lr] = av.z; As[lk+3][lr] = av.w;
        Bs[lk+0][lr] = bv.x; Bs[lk+1][lr] = bv.y; Bs[lk+2][lr] = bv.z; Bs[lk+3][lr] = bv.w;
        __syncthreads();
#pragma unroll
        for (int kk = 0; kk < 8; kk++) {
            float a[8], b[8];
#pragma unroll
            for (int ii = 0; ii < 8; ii++) a[ii] = As[kk][ty + 16*ii];
#pragma unroll
            for (int jj = 0; jj < 8; jj++) b[jj] = Bs[kk][tx + 16*jj];
#pragma unroll
            for (int ii = 0; ii < 8; ii++)
#pragma unroll
                for (int jj = 0; jj < 8; jj++) acc[ii][jj] += a[ii] * b[jj];
        }
    }
#pragma unroll
    for (int ii = 0; ii < 8; ii++) {
        int m = m0 + ty + 16*ii;
#pragma unroll
        for (int jj = 0; jj < 8; jj++) {
            int n = n0 + tx + 16*jj;
            float bb = bias ? bias[n] : 0.f;
            C[(size_t)m * ldc + n] = alpha * (acc[ii][jj] + bb);
        }
    }
}

// ---------------- transpose random_features (d,m) -> (m,d) ----------------
__global__ void transpose_rf(const float* __restrict__ rf){
    int i = blockIdx.x * 256 + threadIdx.x;
    if (i < MF * DH) {
        int m = i >> 6, d = i & 63;
        g_rft[(size_t)m * DH + d] = rf[(size_t)d * MF + m];
    }
}

__global__ void reset_kstab(){ g_kstab = 0u; }

// ---------------- h_k per (head,row) + global max ----------------
__global__ void hk_max(){
    int l = blockIdx.x;
    int w = threadIdx.x >> 5, lane = threadIdx.x & 31;
    const float* kr = g_k + (size_t)l * DM + w * DH;
    float x0 = kr[lane], x1 = kr[lane + 32];
    float ss = x0*x0 + x1*x1;
#pragma unroll
    for (int o = 16; o; o >>= 1) ss += __shfl_xor_sync(0xffffffffu, ss, o);
    __shared__ float wm[8];
    if (lane == 0) { float hv = -0.5f * ss; g_hk[(size_t)w * L + l] = hv; wm[w] = hv; }
    __syncthreads();
    if (threadIdx.x == 0) {
        float mx = wm[0];
#pragma unroll
        for (int i = 1; i < 8; i++) mx = fmaxf(mx, wm[i]);
        atomicMax(&g_kstab, enc_f(mx));
    }
}

// ---------------- elementwise: q' and k' (in place over proj buffers) ----------------
__global__ void featurize(){
    size_t idx = (size_t)blockIdx.x * 256 + threadIdx.x;
    const size_t NQ = (size_t)NH * L * MF;
    if (idx < NQ) {
        // stabilizer h_q cancels exactly for q
        g_pq[idx] = NC_COEF * (expf(g_pq[idx]) + KEPS);
    } else {
        size_t i = idx - NQ;
        float kst = dec_f(g_kstab);
        float hk = g_hk[i >> 7];          // i>>7 == h*L + l  (MF=128)
        g_pk[i] = NC_COEF * (expf(hk + g_pk[i] - kst) + KEPS);
    }
}

// ---------------- per-(head,chunk) state: S = K'^T V, z = sum k' ----------------
__global__ void chunk_state(){
    __shared__ float Ks[32][128];
    __shared__ float Vs[32][64];
    int c = blockIdx.x, h = blockIdx.y;
    int tid = threadIdx.x;
    int l0 = c * CHK;
    int d = tid & 63, mg = tid >> 6;     // warp-uniform mg
    float acc[32];
#pragma unroll
    for (int j = 0; j < 32; j++) acc[j] = 0.f;
    float zacc = 0.f;

    for (int half = 0; half < 2; half++) {
        int lb = l0 + half * 32;
        const float4* srck = (const float4*)(g_pk + ((size_t)h * L + lb) * MF);
        float4* dstk = (float4*)&Ks[0][0];
        for (int i = tid; i < 1024; i += 256) dstk[i] = srck[i];
        for (int i = tid; i < 512; i += 256) {
            int r = i >> 4, c4 = (i & 15) * 4;
            *(float4*)&Vs[r][c4] = *(const float4*)(g_v + (size_t)(lb + r) * DM + h * DH + c4);
        }
        __syncthreads();
        for (int l = 0; l < 32; l++) {
            float vv = Vs[l][d];
#pragma unroll
            for (int j = 0; j < 32; j++) acc[j] += Ks[l][mg + 4*j] * vv;
        }
        if (tid < 128) {
            float s = 0.f;
            for (int l = 0; l < 32; l++) s += Ks[l][tid];
            zacc += s;
        }
        __syncthreads();
    }
    size_t base = ((size_t)(h * NC + c) * MF) * DH;
#pragma unroll
    for (int j = 0; j < 32; j++) g_S[base + (size_t)(mg + 4*j) * DH + d] = acc[j];
    if (tid < 128) g_z[(size_t)(h * NC + c) * MF + tid] = zacc;
}

// ---------------- exclusive prefix over chunks (in place) ----------------
__global__ void prefix_scan(){
    int h = blockIdx.y;
    int idx = blockIdx.x * 256 + threadIdx.x;
    if (idx < MF * DH) {
        float* p = g_S + (size_t)h * NC * MF * DH + idx;
        float prev = 0.f;
#pragma unroll
        for (int c = 0; c < NC; c++) {
            float cur = p[(size_t)c * MF * DH];
            p[(size_t)c * MF * DH] = prev;
            prev += cur;
        }
    } else if (idx < MF * DH + MF) {
        int m = idx - MF * DH;
        float* p = g_z + (size_t)h * NC * MF + m;
        float prev = 0.f;
#pragma unroll
        for (int c = 0; c < NC; c++) {
            float cur = p[c * MF];
            p[c * MF] = prev;
            prev += cur;
        }
    }
}

// ---------------- per-(head,chunk) output ----------------
// out = (tril(Q'K'^T) @ V + Q' @ S_prev) / (rowsum(tril A) + Q'.z_prev + eps)
#define SQ 129
#define SK 129
#define SA 65
#define CO_SMEM_FLOATS (64*SQ + 64*SK + 64*64 + 128*64 + 64*SA + 128 + 64)
__global__ void chunk_out(){
    extern __shared__ float sm[];
    float* Qs = sm;                    // 64 x SQ
    float* Ks = Qs + 64*SQ;            // 64 x SK
    float* Vs = Ks + 64*SK;            // 64 x 64
    float* Ss = Vs + 64*64;            // 128 x 64
    float* As = Ss + 128*64;           // 64 x SA
    float* zs = As + 64*SA;            // 128
    float* rs = zs + 128;              // 64

    int c = blockIdx.x, h = blockIdx.y;
    int tid = threadIdx.x;
    int l0 = c * CHK;

    {
        const float4* srcq = (const float4*)(g_pq + ((size_t)h * L + l0) * MF);
        const float4* srck = (const float4*)(g_pk + ((size_t)h * L + l0) * MF);
        for (int i = tid; i < 2048; i += 256) {
            int r = i >> 5, m4 = (i & 31) * 4;
            float4 a = srcq[i];
            Qs[r*SQ+m4] = a.x; Qs[r*SQ+m4+1] = a.y; Qs[r*SQ+m4+2] = a.z; Qs[r*SQ+m4+3] = a.w;
            float4 b = srck[i];
            Ks[r*SK+m4] = b.x; Ks[r*SK+m4+1] = b.y; Ks[r*SK+m4+2] = b.z; Ks[r*SK+m4+3] = b.w;
        }
        // V tile is 64 rows x 64 cols = 1024 float4 (Round-1 bug: only 512 were loaded)
        for (int i = tid; i < 1024; i += 256) {
            int r = i >> 4, c4 = (i & 15) * 4;
            *(float4*)&Vs[r*64 + c4] = *(const float4*)(g_v + (size_t)(l0 + r) * DM + h * DH + c4);
        }
        const float4* srcs = (const float4*)(g_S + (size_t)(h * NC + c) * MF * DH);
        float4* dsts = (float4*)Ss;
        for (int i = tid; i < 2048; i += 256) dsts[i] = srcs[i];
        if (tid < 128) zs[tid] = g_z[(size_t)(h * NC + c) * MF + tid];
    }
    __syncthreads();

    int ty = tid >> 4, tx = tid & 15;

    // Phase 1: A = Q' K'^T  (64x64, K=128)
    float acc[4][4];
#pragma unroll
    for (int ii = 0; ii < 4; ii++)
#pragma unroll
        for (int jj = 0; jj < 4; jj++) acc[ii][jj] = 0.f;

#pragma unroll 4
    for (int m = 0; m < 128; m++) {
        float qa[4], kb[4];
#pragma unroll
        for (int ii = 0; ii < 4; ii++) qa[ii] = Qs[(ty + 16*ii)*SQ + m];
#pragma unroll
        for (int jj = 0; jj < 4; jj++) kb[jj] = Ks[(tx + 16*jj)*SK + m];
#pragma unroll
        for (int ii = 0; ii < 4; ii++)
#pragma unroll
            for (int jj = 0; jj < 4; jj++) acc[ii][jj] += qa[ii] * kb[jj];
    }
#pragma unroll
    for (int ii = 0; ii < 4; ii++)
#pragma unroll
        for (int jj = 0; jj < 4; jj++) {
            int i = ty + 16*ii, j = tx + 16*jj;
            As[i*SA + j] = (j <= i) ? acc[ii][jj] : 0.f;
        }
    __syncthreads();

    // denominators
    if (tid < 64) {
        float s = 0.f;
        for (int j = 0; j < 64; j++) s += As[tid*SA + j];
        for (int m = 0; m < 128; m++) s += Qs[tid*SQ + m] * zs[m];
        rs[tid] = s + DEPS;
    }
    __syncthreads();

    // Phase 2: out = A @ V + Q' @ S_prev
    float4 o[4];
#pragma unroll
    for (int ii = 0; ii < 4; ii++) { o[ii].x = 0.f; o[ii].y = 0.f; o[ii].z = 0.f; o[ii].w = 0.f; }

#pragma unroll 2
    for (int j = 0; j < 64; j++) {
        float4 v4 = *(float4*)&Vs[j*64 + tx*4];
#pragma unroll
        for (int ii = 0; ii < 4; ii++) {
            float aa = As[(ty + 16*ii)*SA + j];
            o[ii].x += aa * v4.x; o[ii].y += aa * v4.y; o[ii].z += aa * v4.z; o[ii].w += aa * v4.w;
        }
    }
#pragma unroll 2
    for (int m = 0; m < 128; m++) {
        float4 s4 = *(float4*)&Ss[m*64 + tx*4];
#pragma unroll
        for (int ii = 0; ii < 4; ii++) {
            float qv = Qs[(ty + 16*ii)*SQ + m];
            o[ii].x += qv * s4.x; o[ii].y += qv * s4.y; o[ii].z += qv * s4.z; o[ii].w += qv * s4.w;
        }
    }
#pragma unroll
    for (int ii = 0; ii < 4; ii++) {
        int i = ty + 16*ii;
        float inv = 1.0f / rs[i];
        float4 w;
        w.x = o[ii].x * inv; w.y = o[ii].y * inv; w.z = o[ii].z * inv; w.w = o[ii].w * inv;
        *(float4*)(g_ctx + (size_t)(l0 + i) * DM + h * DH + tx*4) = w;
    }
}

// ---------------- launcher ----------------
extern "C" void kernel_launch(void* const* d_in, const int* in_sizes, int n_in,
                              void* d_out, int out_size)
{
    const float* query = (const float*)d_in[0];
    const float* key_i = (const float*)d_in[1];
    const float* value = (const float*)d_in[2];
    const float* Wq = (const float*)d_in[3];
    const float* bq = (const float*)d_in[4];
    const float* Wk = (const float*)d_in[5];
    const float* bk = (const float*)d_in[6];
    const float* Wv = (const float*)d_in[7];
    const float* bv = (const float*)d_in[8];
    const float* Wo = (const float*)d_in[9];
    const float* bo = (const float*)d_in[10];
    const float* rf = (const float*)d_in[11];
    float* out = (float*)d_out;

    void* p;
    cudaGetSymbolAddress(&p, g_q);   float* q   = (float*)p;
    cudaGetSymbolAddress(&p, g_k);   float* k   = (float*)p;
    cudaGetSymbolAddress(&p, g_v);   float* v   = (float*)p;
    cudaGetSymbolAddress(&p, g_rft); float* rft = (float*)p;
    cudaGetSymbolAddress(&p, g_pq);  float* pq  = (float*)p;
    cudaGetSymbolAddress(&p, g_pk);  float* pk  = (float*)p;
    cudaGetSymbolAddress(&p, g_ctx); float* ctx = (float*)p;

    // 1) input projections (scale folded in for q,k)
    sgemm_abt<<<dim3(DM/128, L/128, 1), 256>>>(query, DM, 0, Wq, DM, 0, bq, q, DM, 0, DM, SCALE_QK);
    sgemm_abt<<<dim3(DM/128, L/128, 1), 256>>>(key_i, DM, 0, Wk, DM, 0, bk, k, DM, 0, DM, SCALE_QK);
    sgemm_abt<<<dim3(DM/128, L/128, 1), 256>>>(value, DM, 0, Wv, DM, 0, bv, v, DM, 0, DM, 1.0f);

    // 2) random-feature projections (batched over heads via z)
    transpose_rf<<<(MF*DH + 255)/256, 256>>>(rf);
    sgemm_abt<<<dim3(1, L/128, NH), 256>>>(q, DM, 64, rft, DH, 0, nullptr, pq, MF, (long long)L*MF, DH, 1.0f);
    sgemm_abt<<<dim3(1, L/128, NH), 256>>>(k, DM, 64, rft, DH, 0, nullptr, pk, MF, (long long)L*MF, DH, 1.0f);

    // 3) k stabilizer (global max of h_k), then elementwise q'/k'
    reset_kstab<<<1, 1>>>();
    hk_max<<<L, 256>>>();
    featurize<<<(2*NH*L*MF)/256, 256>>>();

    // 4) chunked causal linear attention
    chunk_state<<<dim3(NC, NH), 256>>>();
    prefix_scan<<<dim3((MF*DH + MF + 255)/256, NH), 256>>>();
    cudaFuncSetAttribute(chunk_out, cudaFuncAttributeMaxDynamicSharedMemorySize, CO_SMEM_FLOATS * 4);
    chunk_out<<<dim3(NC, NH), 256, CO_SMEM_FLOATS * 4>>>();

    // 5) output projection
    sgemm_abt<<<dim3(DM/128, L/128, 1), 256>>>(ctx, DM, 0, Wo, DM, 0, bo, out, DM, 0, DM, 1.0f);
}

// round 3
// speedup vs baseline: 1.9288x; 1.9288x over previous
#include <cuda_runtime.h>
#include <math.h>

#define L 2048
#define DM 512
#define NH 8
#define DH 64
#define MF 128
#define CHK 64
#define NC (L/CHK)   // 32

#define SCALE_QK 0.2102241038134287f     // 512^-0.25
#define NC_COEF  0.08838834764831845f    // 128^-0.5
#define KEPS 1e-4f
#define DEPS 1e-6f

// ---------------- device scratch ----------------
__device__ float g_q[L*DM];
__device__ float g_k[L*DM];
__device__ float g_v[L*DM];
__device__ float g_pq[NH*L*MF];
__device__ float g_pk[NH*L*MF];
__device__ float g_hk[NH*L];
__device__ unsigned g_kstab;
__device__ float g_S[NH*NC*MF*DH];
__device__ float g_z[NH*NC*MF];
__device__ float g_ctx[L*DM];

__device__ __forceinline__ unsigned enc_f(float f){
    unsigned u = __float_as_uint(f);
    return (u & 0x80000000u) ? ~u : (u | 0x80000000u);
}
__device__ __forceinline__ float dec_f(unsigned k){
    unsigned u = (k & 0x80000000u) ? (k ^ 0x80000000u) : ~k;
    return __uint_as_float(u);
}

__global__ void reset_kstab(){ g_kstab = 0u; }

// ---------------- big GEMM: C = alpha*(A@W^T + bias) ----------------
// M=2048, N=512, K=512. Tiles 128M x 64N, BK=16, double-buffered.
// 256 threads, 8x4 micro-tile. z selects batch. z==1 (K-proj) also emits
// h_k = -0.5*||k||^2 per (head,row) and the global max (stabilizer).
struct G3 {
    const float* A[3]; const float* W[3]; const float* Bv[3]; float* C[3];
    float alpha[3];
};

__global__ __launch_bounds__(256) void gemm_big(G3 g, int do_hk)
{
    __shared__ float As[2][16][128];
    __shared__ float Bs[2][16][64];
    __shared__ float red[8];
    const int K = DM;
    int z = blockIdx.z;
    const float* A = g.A[z];
    const float* W = g.W[z];
    const float* bias = g.Bv[z];
    float* C = g.C[z];
    float alpha = g.alpha[z];
    int m0 = blockIdx.y * 128, n0 = blockIdx.x * 64;
    int tid = threadIdx.x;

    int ar = tid >> 1, ac = (tid & 1) * 8;
    int br = tid & 63, bc = (tid >> 6) * 4;
    const float* Ap = A + (size_t)(m0 + ar) * K + ac;
    const float* Wp = W + (size_t)(n0 + br) * K + bc;

    float4 a0 = *(const float4*)(Ap);
    float4 a1 = *(const float4*)(Ap + 4);
    float4 b0 = *(const float4*)(Wp);
    As[0][ac+0][ar]=a0.x; As[0][ac+1][ar]=a0.y; As[0][ac+2][ar]=a0.z; As[0][ac+3][ar]=a0.w;
    As[0][ac+4][ar]=a1.x; As[0][ac+5][ar]=a1.y; As[0][ac+6][ar]=a1.z; As[0][ac+7][ar]=a1.w;
    Bs[0][bc+0][br]=b0.x; Bs[0][bc+1][br]=b0.y; Bs[0][bc+2][br]=b0.z; Bs[0][bc+3][br]=b0.w;
    __syncthreads();

    int ty = tid >> 4, tx = tid & 15;
    float acc[8][4];
#pragma unroll
    for (int i = 0; i < 8; i++)
#pragma unroll
        for (int j = 0; j < 4; j++) acc[i][j] = 0.f;

    const int NKB = K / 16;
    for (int kb = 0; kb < NKB; kb++) {
        int cur = kb & 1;
        if (kb + 1 < NKB) {
            a0 = *(const float4*)(Ap + (kb+1)*16);
            a1 = *(const float4*)(Ap + (kb+1)*16 + 4);
            b0 = *(const float4*)(Wp + (kb+1)*16);
        }
#pragma unroll
        for (int kk = 0; kk < 16; kk++) {
            float4 x0 = *(const float4*)&As[cur][kk][ty*8];
            float4 x1 = *(const float4*)&As[cur][kk][ty*8+4];
            float4 y  = *(const float4*)&Bs[cur][kk][tx*4];
            float av[8] = {x0.x,x0.y,x0.z,x0.w,x1.x,x1.y,x1.z,x1.w};
            float bv[4] = {y.x,y.y,y.z,y.w};
#pragma unroll
            for (int i = 0; i < 8; i++)
#pragma unroll
                for (int j = 0; j < 4; j++) acc[i][j] += av[i] * bv[j];
        }
        if (kb + 1 < NKB) {
            int nxt = cur ^ 1;
            As[nxt][ac+0][ar]=a0.x; As[nxt][ac+1][ar]=a0.y; As[nxt][ac+2][ar]=a0.z; As[nxt][ac+3][ar]=a0.w;
            As[nxt][ac+4][ar]=a1.x; As[nxt][ac+5][ar]=a1.y; As[nxt][ac+6][ar]=a1.z; As[nxt][ac+7][ar]=a1.w;
            Bs[nxt][bc+0][br]=b0.x; Bs[nxt][bc+1][br]=b0.y; Bs[nxt][bc+2][br]=b0.z; Bs[nxt][bc+3][br]=b0.w;
        }
        __syncthreads();
    }

    float4 bb = *(const float4*)(bias + n0 + tx*4);
    bool hk = (do_hk && z == 1);
    float hmax = -1e30f;
#pragma unroll
    for (int i = 0; i < 8; i++) {
        int m = m0 + ty*8 + i;
        float4 o;
        o.x = alpha * (acc[i][0] + bb.x);
        o.y = alpha * (acc[i][1] + bb.y);
        o.z = alpha * (acc[i][2] + bb.z);
        o.w = alpha * (acc[i][3] + bb.w);
        *(float4*)(C + (size_t)m * DM + n0 + tx*4) = o;
        if (hk) {
            float s = o.x*o.x + o.y*o.y + o.z*o.z + o.w*o.w;
#pragma unroll
            for (int off = 1; off < 16; off <<= 1) s += __shfl_xor_sync(0xffffffffu, s, off);
            float hv = -0.5f * s;   // same value on all 16 lanes of the row group
            if (tx == 0) g_hk[(size_t)blockIdx.x * L + m] = hv;  // head = blockIdx.x
            hmax = fmaxf(hmax, hv);
        }
    }
    if (hk) {
#pragma unroll
        for (int off = 16; off; off >>= 1) hmax = fmaxf(hmax, __shfl_xor_sync(0xffffffffu, hmax, off));
        if ((tid & 31) == 0) red[tid >> 5] = hmax;
        __syncthreads();
        if (tid == 0) {
            float mx = red[0];
#pragma unroll
            for (int i = 1; i < 8; i++) mx = fmaxf(mx, red[i]);
            atomicMax(&g_kstab, enc_f(mx));
        }
    }
}

// ---------------- rf projection + featurize fused ----------------
// z in 0..15: head = z&7, src = (z<8 ? q : k). out = q' / k'.
// A row stride DM (head column slice), B = rf in native (d,m) layout,
// C = g_pq/g_pk [h*L + l][m]. M=2048, N=128, K=64. Tiles 128x64, BK=16.
__global__ __launch_bounds__(256) void rf_proj(const float* __restrict__ rf)
{
    __shared__ float As[2][16][128];
    __shared__ float Bs[2][16][64];
    int z = blockIdx.z;
    int h = z & 7;
    bool isq = z < 8;
    const float* A = (isq ? g_q : g_k) + h * DH;
    float* C = (isq ? g_pq : g_pk) + (size_t)h * L * MF;
    int m0 = blockIdx.y * 128, n0 = blockIdx.x * 64;
    int tid = threadIdx.x;

    int ar = tid >> 1, ac = (tid & 1) * 8;
    int kB = tid >> 4, nB = (tid & 15) * 4;
    const float* Ap = A + (size_t)(m0 + ar) * DM + ac;
    const float* Bp = rf + (size_t)kB * MF + n0 + nB;

    float4 a0 = *(const float4*)(Ap);
    float4 a1 = *(const float4*)(Ap + 4);
    float4 b0 = *(const float4*)(Bp);
    As[0][ac+0][ar]=a0.x; As[0][ac+1][ar]=a0.y; As[0][ac+2][ar]=a0.z; As[0][ac+3][ar]=a0.w;
    As[0][ac+4][ar]=a1.x; As[0][ac+5][ar]=a1.y; As[0][ac+6][ar]=a1.z; As[0][ac+7][ar]=a1.w;
    *(float4*)&Bs[0][kB][nB] = b0;
    __syncthreads();

    int ty = tid >> 4, tx = tid & 15;
    float acc[8][4];
#pragma unroll
    for (int i = 0; i < 8; i++)
#pragma unroll
        for (int j = 0; j < 4; j++) acc[i][j] = 0.f;

    const int NKB = DH / 16;   // 4
    for (int kb = 0; kb < NKB; kb++) {
        int cur = kb & 1;
        if (kb + 1 < NKB) {
            a0 = *(const float4*)(Ap + (kb+1)*16);
            a1 = *(const float4*)(Ap + (kb+1)*16 + 4);
            b0 = *(const float4*)(Bp + (size_t)(kb+1)*16 * MF);
        }
#pragma unroll
        for (int kk = 0; kk < 16; kk++) {
            float4 x0 = *(const float4*)&As[cur][kk][ty*8];
            float4 x1 = *(const float4*)&As[cur][kk][ty*8+4];
            float4 y  = *(const float4*)&Bs[cur][kk][tx*4];
            float av[8] = {x0.x,x0.y,x0.z,x0.w,x1.x,x1.y,x1.z,x1.w};
            float bv[4] = {y.x,y.y,y.z,y.w};
#pragma unroll
            for (int i = 0; i < 8; i++)
#pragma unroll
                for (int j = 0; j < 4; j++) acc[i][j] += av[i] * bv[j];
        }
        if (kb + 1 < NKB) {
            int nxt = cur ^ 1;
            As[nxt][ac+0][ar]=a0.x; As[nxt][ac+1][ar]=a0.y; As[nxt][ac+2][ar]=a0.z; As[nxt][ac+3][ar]=a0.w;
            As[nxt][ac+4][ar]=a1.x; As[nxt][ac+5][ar]=a1.y; As[nxt][ac+6][ar]=a1.z; As[nxt][ac+7][ar]=a1.w;
            *(float4*)&Bs[nxt][kB][nB] = b0;
        }
        __syncthreads();
    }

    float kst = isq ? 0.f : dec_f(g_kstab);
#pragma unroll
    for (int i = 0; i < 8; i++) {
        int m = m0 + ty*8 + i;
        float off = isq ? 0.f : (g_hk[(size_t)h * L + m] - kst);
        float4 o;
        o.x = NC_COEF * (__expf(acc[i][0] + off) + KEPS);
        o.y = NC_COEF * (__expf(acc[i][1] + off) + KEPS);
        o.z = NC_COEF * (__expf(acc[i][2] + off) + KEPS);
        o.w = NC_COEF * (__expf(acc[i][3] + off) + KEPS);
        *(float4*)(C + (size_t)m * MF + n0 + tx*4) = o;
    }
}

// ---------------- per-(head,chunk) state: S = K'^T V, z = sum k' ----------------
__global__ void chunk_state(){
    __shared__ float Ks[32][128];
    __shared__ float Vs[32][64];
    int c = blockIdx.x, h = blockIdx.y;
    int tid = threadIdx.x;
    int l0 = c * CHK;
    int d = tid & 63, mg = tid >> 6;
    float acc[32];
#pragma unroll
    for (int j = 0; j < 32; j++) acc[j] = 0.f;
    float zacc = 0.f;

    for (int half = 0; half < 2; half++) {
        int lb = l0 + half * 32;
        const float4* srck = (const float4*)(g_pk + ((size_t)h * L + lb) * MF);
        float4* dstk = (float4*)&Ks[0][0];
        for (int i = tid; i < 1024; i += 256) dstk[i] = srck[i];
        for (int i = tid; i < 512; i += 256) {
            int r = i >> 4, c4 = (i & 15) * 4;
            *(float4*)&Vs[r][c4] = *(const float4*)(g_v + (size_t)(lb + r) * DM + h * DH + c4);
        }
        __syncthreads();
        for (int l = 0; l < 32; l++) {
            float vv = Vs[l][d];
#pragma unroll
            for (int j = 0; j < 32; j++) acc[j] += Ks[l][mg + 4*j] * vv;
        }
        if (tid < 128) {
            float s = 0.f;
            for (int l = 0; l < 32; l++) s += Ks[l][tid];
            zacc += s;
        }
        __syncthreads();
    }
    size_t base = ((size_t)(h * NC + c) * MF) * DH;
#pragma unroll
    for (int j = 0; j < 32; j++) g_S[base + (size_t)(mg + 4*j) * DH + d] = acc[j];
    if (tid < 128) g_z[(size_t)(h * NC + c) * MF + tid] = zacc;
}

// ---------------- exclusive prefix over chunks ----------------
__global__ void prefix_scan(){
    int h = blockIdx.y;
    int idx = blockIdx.x * 256 + threadIdx.x;
    if (idx < MF * DH) {
        float* p = g_S + (size_t)h * NC * MF * DH + idx;
        float prev = 0.f;
#pragma unroll
        for (int c = 0; c < NC; c++) {
            float cur = p[(size_t)c * MF * DH];
            p[(size_t)c * MF * DH] = prev;
            prev += cur;
        }
    } else if (idx < MF * DH + MF) {
        int m = idx - MF * DH;
        float* p = g_z + (size_t)h * NC * MF + m;
        float prev = 0.f;
#pragma unroll
        for (int c = 0; c < NC; c++) {
            float cur = p[c * MF];
            p[c * MF] = prev;
            prev += cur;
        }
    }
}

// ---------------- per-(head,chunk) output ----------------
#define SQ 129
#define SK 129
#define SA 65
#define CO_SMEM_FLOATS (64*SQ + 64*SK + 64*64 + 128*64 + 64*SA + 128 + 64)
__global__ void chunk_out(){
    extern __shared__ float sm[];
    float* Qs = sm;
    float* Ks = Qs + 64*SQ;
    float* Vs = Ks + 64*SK;
    float* Ss = Vs + 64*64;
    float* As = Ss + 128*64;
    float* zs = As + 64*SA;
    float* rs = zs + 128;

    int c = blockIdx.x, h = blockIdx.y;
    int tid = threadIdx.x;
    int l0 = c * CHK;

    {
        const float4* srcq = (const float4*)(g_pq + ((size_t)h * L + l0) * MF);
        const float4* srck = (const float4*)(g_pk + ((size_t)h * L + l0) * MF);
        for (int i = tid; i < 2048; i += 256) {
            int r = i >> 5, m4 = (i & 31) * 4;
            float4 a = srcq[i];
            Qs[r*SQ+m4] = a.x; Qs[r*SQ+m4+1] = a.y; Qs[r*SQ+m4+2] = a.z; Qs[r*SQ+m4+3] = a.w;
            float4 b = srck[i];
            Ks[r*SK+m4] = b.x; Ks[r*SK+m4+1] = b.y; Ks[r*SK+m4+2] = b.z; Ks[r*SK+m4+3] = b.w;
        }
        for (int i = tid; i < 1024; i += 256) {
            int r = i >> 4, c4 = (i & 15) * 4;
            *(float4*)&Vs[r*64 + c4] = *(const float4*)(g_v + (size_t)(l0 + r) * DM + h * DH + c4);
        }
        const float4* srcs = (const float4*)(g_S + (size_t)(h * NC + c) * MF * DH);
        float4* dsts = (float4*)Ss;
        for (int i = tid; i < 2048; i += 256) dsts[i] = srcs[i];
        if (tid < 128) zs[tid] = g_z[(size_t)(h * NC + c) * MF + tid];
    }
    __syncthreads();

    int ty = tid >> 4, tx = tid & 15;

    float acc[4][4];
#pragma unroll
    for (int ii = 0; ii < 4; ii++)
#pragma unroll
        for (int jj = 0; jj < 4; jj++) acc[ii][jj] = 0.f;

#pragma unroll 4
    for (int m = 0; m < 128; m++) {
        float qa[4], kb[4];
#pragma unroll
        for (int ii = 0; ii < 4; ii++) qa[ii] = Qs[(ty + 16*ii)*SQ + m];
#pragma unroll
        for (int jj = 0; jj < 4; jj++) kb[jj] = Ks[(tx + 16*jj)*SK + m];
#pragma unroll
        for (int ii = 0; ii < 4; ii++)
#pragma unroll
            for (int jj = 0; jj < 4; jj++) acc[ii][jj] += qa[ii] * kb[jj];
    }
#pragma unroll
    for (int ii = 0; ii < 4; ii++)
#pragma unroll
        for (int jj = 0; jj < 4; jj++) {
            int i = ty + 16*ii, j = tx + 16*jj;
            As[i*SA + j] = (j <= i) ? acc[ii][jj] : 0.f;
        }
    __syncthreads();

    if (tid < 64) {
        float s = 0.f;
        for (int j = 0; j < 64; j++) s += As[tid*SA + j];
        for (int m = 0; m < 128; m++) s += Qs[tid*SQ + m] * zs[m];
        rs[tid] = s + DEPS;
    }
    __syncthreads();

    float4 o[4];
#pragma unroll
    for (int ii = 0; ii < 4; ii++) { o[ii].x = 0.f; o[ii].y = 0.f; o[ii].z = 0.f; o[ii].w = 0.f; }

#pragma unroll 2
    for (int j = 0; j < 64; j++) {
        float4 v4 = *(float4*)&Vs[j*64 + tx*4];
#pragma unroll
        for (int ii = 0; ii < 4; ii++) {
            float aa = As[(ty + 16*ii)*SA + j];
            o[ii].x += aa * v4.x; o[ii].y += aa * v4.y; o[ii].z += aa * v4.z; o[ii].w += aa * v4.w;
        }
    }
#pragma unroll 2
    for (int m = 0; m < 128; m++) {
        float4 s4 = *(float4*)&Ss[m*64 + tx*4];
#pragma unroll
        for (int ii = 0; ii < 4; ii++) {
            float qv = Qs[(ty + 16*ii)*SQ + m];
            o[ii].x += qv * s4.x; o[ii].y += qv * s4.y; o[ii].z += qv * s4.z; o[ii].w += qv * s4.w;
        }
    }
#pragma unroll
    for (int ii = 0; ii < 4; ii++) {
        int i = ty + 16*ii;
        float inv = 1.0f / rs[i];
        float4 w;
        w.x = o[ii].x * inv; w.y = o[ii].y * inv; w.z = o[ii].z * inv; w.w = o[ii].w * inv;
        *(float4*)(g_ctx + (size_t)(l0 + i) * DM + h * DH + tx*4) = w;
    }
}

// ---------------- launcher ----------------
extern "C" void kernel_launch(void* const* d_in, const int* in_sizes, int n_in,
                              void* d_out, int out_size)
{
    const float* query = (const float*)d_in[0];
    const float* key_i = (const float*)d_in[1];
    const float* value = (const float*)d_in[2];
    const float* Wq = (const float*)d_in[3];
    const float* bq = (const float*)d_in[4];
    const float* Wk = (const float*)d_in[5];
    const float* bk = (const float*)d_in[6];
    const float* Wv = (const float*)d_in[7];
    const float* bv = (const float*)d_in[8];
    const float* Wo = (const float*)d_in[9];
    const float* bo = (const float*)d_in[10];
    const float* rf = (const float*)d_in[11];
    float* out = (float*)d_out;

    void* p;
    cudaGetSymbolAddress(&p, g_q);   float* q   = (float*)p;
    cudaGetSymbolAddress(&p, g_k);   float* k   = (float*)p;
    cudaGetSymbolAddress(&p, g_v);   float* v   = (float*)p;
    cudaGetSymbolAddress(&p, g_ctx); float* ctx = (float*)p;

    reset_kstab<<<1, 1>>>();

    // fused q/k/v projections (+ h_k and stabilizer from z==1)
    G3 gq;
    gq.A[0] = query; gq.W[0] = Wq; gq.Bv[0] = bq; gq.C[0] = q; gq.alpha[0] = SCALE_QK;
    gq.A[1] = key_i; gq.W[1] = Wk; gq.Bv[1] = bk; gq.C[1] = k; gq.alpha[1] = SCALE_QK;
    gq.A[2] = value; gq.W[2] = Wv; gq.Bv[2] = bv; gq.C[2] = v; gq.alpha[2] = 1.0f;
    gemm_big<<<dim3(DM/64, L/128, 3), 256>>>(gq, 1);

    // rf projections + featurize (16 batches: 8 heads x {q,k})
    rf_proj<<<dim3(MF/64, L/128, 16), 256>>>(rf);

    // chunked causal linear attention
    chunk_state<<<dim3(NC, NH), 256>>>();
    prefix_scan<<<dim3((MF*DH + MF + 255)/256, NH), 256>>>();
    cudaFuncSetAttribute(chunk_out, cudaFuncAttributeMaxDynamicSharedMemorySize, CO_SMEM_FLOATS * 4);
    chunk_out<<<dim3(NC, NH), 256, CO_SMEM_FLOATS * 4>>>();

    // output projection
    G3 go;
    go.A[0] = ctx; go.W[0] = Wo; go.Bv[0] = bo; go.C[0] = out; go.alpha[0] = 1.0f;
    go.A[1] = ctx; go.W[1] = Wo; go.Bv[1] = bo; go.C[1] = out; go.alpha[1] = 1.0f;
    go.A[2] = ctx; go.W[2] = Wo; go.Bv[2] = bo; go.C[2] = out; go.alpha[2] = 1.0f;
    gemm_big<<<dim3(DM/64, L/128, 1), 256>>>(go, 0);
}

// round 5
// speedup vs baseline: 2.6393x; 1.3683x over previous
#include <cuda_runtime.h>
#include <cuda_bf16.h>
#include <math.h>
#include <stdint.h>

#define L 2048
#define DM 512
#define NH 8
#define DH 64
#define MF 128
#define CHK 64
#define NC (L/CHK)   // 32

#define SCALE_QK 0.2102241038134287f     // 512^-0.25
#define NC_COEF  0.08838834764831845f    // 128^-0.5
#define KEPS 1e-4f
#define DEPS 1e-6f

// ---------------- device scratch ----------------
__device__ float g_q[L*DM];
__device__ float g_k[L*DM];
__device__ float g_v[L*DM];
__device__ float g_pq[NH*L*MF];
__device__ float g_pk[NH*L*MF];
__device__ float g_hk[NH*L];
__device__ unsigned g_kstab;
__device__ float g_S[NH*NC*MF*DH];
__device__ float g_z[NH*NC*MF];
__device__ float g_ctx[L*DM];

// split-bf16 buffers
__device__ __nv_bfloat16 g_bhi_in[3][L*DM];
__device__ __nv_bfloat16 g_blo_in[3][L*DM];
__device__ __nv_bfloat16 g_bhi_w[4][DM*DM];
__device__ __nv_bfloat16 g_blo_w[4][DM*DM];
__device__ __nv_bfloat16 g_bhi_ctx[L*DM];
__device__ __nv_bfloat16 g_blo_ctx[L*DM];

__device__ __forceinline__ unsigned enc_f(float f){
    unsigned u = __float_as_uint(f);
    return (u & 0x80000000u) ? ~u : (u | 0x80000000u);
}
__device__ __forceinline__ float dec_f(unsigned k){
    unsigned u = (k & 0x80000000u) ? (k ^ 0x80000000u) : ~k;
    return __uint_as_float(u);
}

__global__ void reset_kstab(){ g_kstab = 0u; }

__device__ __forceinline__ uint32_t smem_u32(const void* p) {
    uint32_t a;
    asm("{ .reg .u64 t; cvta.to.shared.u64 t, %1; cvt.u32.u64 %0, t; }" : "=r"(a) : "l"(p));
    return a;
}

#define CP_ASYNC16(sa, gp) asm volatile("cp.async.cg.shared.global [%0], [%1], 16;" :: "r"(sa), "l"(gp))
#define CP_COMMIT()        asm volatile("cp.async.commit_group;")
#define CP_WAIT1()         asm volatile("cp.async.wait_group 1;")
#define CP_WAIT0()         asm volatile("cp.async.wait_group 0;")

#define LDSM4(r0,r1,r2,r3,a) \
    asm volatile("ldmatrix.sync.aligned.m8n8.x4.shared.b16 {%0,%1,%2,%3}, [%4];" \
        : "=r"(r0),"=r"(r1),"=r"(r2),"=r"(r3) : "r"(a))

#define MMA16816(d,a,b0,b1) \
    asm volatile("mma.sync.aligned.m16n8k16.row.col.f32.bf16.bf16.f32 " \
        "{%0,%1,%2,%3},{%4,%5,%6,%7},{%8,%9},{%0,%1,%2,%3};" \
        : "+f"((d)[0]),"+f"((d)[1]),"+f"((d)[2]),"+f"((d)[3]) \
        : "r"((a)[0]),"r"((a)[1]),"r"((a)[2]),"r"((a)[3]),"r"(b0),"r"(b1))

// ---------------- fp32 -> (bf16 hi, bf16 lo) converter ----------------
struct CV { const float* src[8]; __nv_bfloat16* hi[8]; __nv_bfloat16* lo[8]; int n[8]; int cnt; };
__global__ void convert_split(CV cv){
    int t = blockIdx.y;
    if (t >= cv.cnt) return;
    int n = cv.n[t];
    const float* s = cv.src[t];
    __nv_bfloat16* ph = cv.hi[t];
    __nv_bfloat16* pl = cv.lo[t];
    int i0 = blockIdx.x * 1024 + threadIdx.x;
#pragma unroll
    for (int j = 0; j < 4; j++) {
        int i = i0 + j * 256;
        if (i < n) {
            float x = s[i];
            __nv_bfloat16 h = __float2bfloat16(x);
            ph[i] = h;
            pl[i] = __float2bfloat16(x - __bfloat162float(h));
        }
    }
}

// ---------------- split-bf16 HMMA GEMM ----------------
// C = alpha*(A@W^T + bias). M=2048, N=512, K=512 (or z-batched).
// Tile 128x128, BK=32, 8 warps (2Mx4N), mma.m16n8k16, cp.async double buffer.
#define PITCH_B 80            // bytes per smem row (40 bf16)
#define TILE_BYTES (128*PITCH_B)     // 10240
#define STAGE_BYTES (4*TILE_BYTES)   // Ahi,Alo,Bhi,Blo = 40960
#define HG_SMEM (2*STAGE_BYTES)      // 81920
#define NKC 16                // 512/32

struct MMArgs {
    const __nv_bfloat16* Ahi[3]; const __nv_bfloat16* Alo[3];
    const __nv_bfloat16* Whi[3]; const __nv_bfloat16* Wlo[3];
    const float* bias[3]; float* C[3]; float alpha[3];
};

__global__ __launch_bounds__(256) void hmma_gemm(MMArgs ga)
{
    extern __shared__ char smem[];
    uint32_t sb = smem_u32(smem);
    int tid = threadIdx.x;
    int lane = tid & 31, wid = tid >> 5;
    int warp_m = wid & 1, warp_n = wid >> 1;
    int z = blockIdx.z;
    int m0 = blockIdx.y * 128, n0 = blockIdx.x * 128;

    const __nv_bfloat16* Ahi = ga.Ahi[z] + (size_t)m0 * DM;
    const __nv_bfloat16* Alo = ga.Alo[z] + (size_t)m0 * DM;
    const __nv_bfloat16* Whi = ga.Whi[z] + (size_t)n0 * DM;
    const __nv_bfloat16* Wlo = ga.Wlo[z] + (size_t)n0 * DM;
    const float* bias = ga.bias[z];
    float* C = ga.C[z];
    float alpha = ga.alpha[z];

    // per-thread load slice: 8 x 16B per stage. idx -> tile, row, 16B-chunk
    int lrow = (tid >> 2) & 127 ? 0 : 0; (void)lrow;

    // fragment address offsets (within a tile)
    uint32_t a_off = (uint32_t)(warp_m*64 + (lane & 15)) * PITCH_B + (lane >> 4) * 16;
    uint32_t b_off = (uint32_t)(warp_n*32 + (lane & 7) + (lane >> 4) * 8) * PITCH_B + ((lane >> 3) & 1) * 16;

    float acc[4][4][4];
#pragma unroll
    for (int i = 0; i < 4; i++)
#pragma unroll
        for (int j = 0; j < 4; j++)
#pragma unroll
            for (int r = 0; r < 4; r++) acc[i][j][r] = 0.f;

    // prologue: stage 0
    {
        int k0 = 0;
#pragma unroll
        for (int j = 0; j < 8; j++) {
            int idx = tid + j * 256;
            int tile = idx >> 9;
            int w = idx & 511;
            int r = w >> 2, c = w & 3;
            const __nv_bfloat16* gp =
                (tile == 0) ? (Ahi + (size_t)r * DM + k0 + c*8) :
                (tile == 1) ? (Alo + (size_t)r * DM + k0 + c*8) :
                (tile == 2) ? (Whi + (size_t)r * DM + k0 + c*8) :
                              (Wlo + (size_t)r * DM + k0 + c*8);
            uint32_t sp = sb + tile * TILE_BYTES + (uint32_t)r * PITCH_B + c * 16;
            CP_ASYNC16(sp, gp);
        }
        CP_COMMIT();
    }

    for (int kc = 0; kc < NKC; kc++) {
        if (kc + 1 < NKC) {
            int k0 = (kc + 1) * 32;
            uint32_t stb = sb + ((kc + 1) & 1) * STAGE_BYTES;
#pragma unroll
            for (int j = 0; j < 8; j++) {
                int idx = tid + j * 256;
                int tile = idx >> 9;
                int w = idx & 511;
                int r = w >> 2, c = w & 3;
                const __nv_bfloat16* gp =
                    (tile == 0) ? (Ahi + (size_t)r * DM + k0 + c*8) :
                    (tile == 1) ? (Alo + (size_t)r * DM + k0 + c*8) :
                    (tile == 2) ? (Whi + (size_t)r * DM + k0 + c*8) :
                                  (Wlo + (size_t)r * DM + k0 + c*8);
                uint32_t sp = stb + tile * TILE_BYTES + (uint32_t)r * PITCH_B + c * 16;
                CP_ASYNC16(sp, gp);
            }
            CP_COMMIT();
            CP_WAIT1();
        } else {
            CP_WAIT0();
        }
        __syncthreads();

        uint32_t st = sb + (kc & 1) * STAGE_BYTES;
        uint32_t sAhi = st + a_off;
        uint32_t sAlo = st + TILE_BYTES + a_off;
        uint32_t sBhi = st + 2*TILE_BYTES + b_off;
        uint32_t sBlo = st + 3*TILE_BYTES + b_off;

#pragma unroll
        for (int ks = 0; ks < 2; ks++) {
            uint32_t ah[4][4], al[4][4], bh[2][4], bl[2][4];
#pragma unroll
            for (int mi = 0; mi < 4; mi++) {
                LDSM4(ah[mi][0], ah[mi][1], ah[mi][2], ah[mi][3], sAhi + mi*16*PITCH_B + ks*32);
                LDSM4(al[mi][0], al[mi][1], al[mi][2], al[mi][3], sAlo + mi*16*PITCH_B + ks*32);
            }
#pragma unroll
            for (int nb = 0; nb < 2; nb++) {
                LDSM4(bh[nb][0], bh[nb][1], bh[nb][2], bh[nb][3], sBhi + nb*16*PITCH_B + ks*32);
                LDSM4(bl[nb][0], bl[nb][1], bl[nb][2], bl[nb][3], sBlo + nb*16*PITCH_B + ks*32);
            }
#pragma unroll
            for (int mi = 0; mi < 4; mi++)
#pragma unroll
                for (int nb = 0; nb < 2; nb++) {
                    // hi*hi
                    MMA16816(acc[mi][nb*2+0], ah[mi], bh[nb][0], bh[nb][1]);
                    MMA16816(acc[mi][nb*2+1], ah[mi], bh[nb][2], bh[nb][3]);
                    // hi*lo
                    MMA16816(acc[mi][nb*2+0], ah[mi], bl[nb][0], bl[nb][1]);
                    MMA16816(acc[mi][nb*2+1], ah[mi], bl[nb][2], bl[nb][3]);
                    // lo*hi
                    MMA16816(acc[mi][nb*2+0], al[mi], bh[nb][0], bh[nb][1]);
                    MMA16816(acc[mi][nb*2+1], al[mi], bh[nb][2], bh[nb][3]);
                }
        }
        __syncthreads();
    }

    // epilogue: direct float2 stores
    int g = lane >> 2, t = lane & 3;
#pragma unroll
    for (int mi = 0; mi < 4; mi++) {
        int row = m0 + warp_m*64 + mi*16 + g;
#pragma unroll
        for (int nj = 0; nj < 4; nj++) {
            int col = n0 + warp_n*32 + nj*8 + t*2;
            float2 bb = *(const float2*)(bias + col);
            float2 o0, o1;
            o0.x = alpha * (acc[mi][nj][0] + bb.x);
            o0.y = alpha * (acc[mi][nj][1] + bb.y);
            o1.x = alpha * (acc[mi][nj][2] + bb.x);
            o1.y = alpha * (acc[mi][nj][3] + bb.y);
            *(float2*)(C + (size_t)row * DM + col) = o0;
            *(float2*)(C + (size_t)(row + 8) * DM + col) = o1;
        }
    }
}

// ---------------- h_k per (head,row) + global max ----------------
__global__ void hk_max(){
    int l = blockIdx.x;
    int w = threadIdx.x >> 5, lane = threadIdx.x & 31;
    const float* kr = g_k + (size_t)l * DM + w * DH;
    float x0 = kr[lane], x1 = kr[lane + 32];
    float ss = x0*x0 + x1*x1;
#pragma unroll
    for (int o = 16; o; o >>= 1) ss += __shfl_xor_sync(0xffffffffu, ss, o);
    __shared__ float wm[8];
    if (lane == 0) { float hv = -0.5f * ss; g_hk[(size_t)w * L + l] = hv; wm[w] = hv; }
    __syncthreads();
    if (threadIdx.x == 0) {
        float mx = wm[0];
#pragma unroll
        for (int i = 1; i < 8; i++) mx = fmaxf(mx, wm[i]);
        atomicMax(&g_kstab, enc_f(mx));
    }
}

// ---------------- rf projection + featurize fused (SIMT) ----------------
__global__ __launch_bounds__(256) void rf_proj(const float* __restrict__ rf)
{
    __shared__ float As[2][16][128];
    __shared__ float Bs[2][16][64];
    int z = blockIdx.z;
    int h = z & 7;
    bool isq = z < 8;
    const float* A = (isq ? g_q : g_k) + h * DH;
    float* C = (isq ? g_pq : g_pk) + (size_t)h * L * MF;
    int m0 = blockIdx.y * 128, n0 = blockIdx.x * 64;
    int tid = threadIdx.x;

    int ar = tid >> 1, ac = (tid & 1) * 8;
    int kB = tid >> 4, nB = (tid & 15) * 4;
    const float* Ap = A + (size_t)(m0 + ar) * DM + ac;
    const float* Bp = rf + (size_t)kB * MF + n0 + nB;

    float4 a0 = *(const float4*)(Ap);
    float4 a1 = *(const float4*)(Ap + 4);
    float4 b0 = *(const float4*)(Bp);
    As[0][ac+0][ar]=a0.x; As[0][ac+1][ar]=a0.y; As[0][ac+2][ar]=a0.z; As[0][ac+3][ar]=a0.w;
    As[0][ac+4][ar]=a1.x; As[0][ac+5][ar]=a1.y; As[0][ac+6][ar]=a1.z; As[0][ac+7][ar]=a1.w;
    *(float4*)&Bs[0][kB][nB] = b0;
    __syncthreads();

    int ty = tid >> 4, tx = tid & 15;
    float acc[8][4];
#pragma unroll
    for (int i = 0; i < 8; i++)
#pragma unroll
        for (int j = 0; j < 4; j++) acc[i][j] = 0.f;

    const int NKB = DH / 16;   // 4
    for (int kb = 0; kb < NKB; kb++) {
        int cur = kb & 1;
        if (kb + 1 < NKB) {
            a0 = *(const float4*)(Ap + (kb+1)*16);
            a1 = *(const float4*)(Ap + (kb+1)*16 + 4);
            b0 = *(const float4*)(Bp + (size_t)(kb+1)*16 * MF);
        }
#pragma unroll
        for (int kk = 0; kk < 16; kk++) {
            float4 x0 = *(const float4*)&As[cur][kk][ty*8];
            float4 x1 = *(const float4*)&As[cur][kk][ty*8+4];
            float4 y  = *(const float4*)&Bs[cur][kk][tx*4];
            float av[8] = {x0.x,x0.y,x0.z,x0.w,x1.x,x1.y,x1.z,x1.w};
            float bv[4] = {y.x,y.y,y.z,y.w};
#pragma unroll
            for (int i = 0; i < 8; i++)
#pragma unroll
                for (int j = 0; j < 4; j++) acc[i][j] += av[i] * bv[j];
        }
        if (kb + 1 < NKB) {
            int nxt = cur ^ 1;
            As[nxt][ac+0][ar]=a0.x; As[nxt][ac+1][ar]=a0.y; As[nxt][ac+2][ar]=a0.z; As[nxt][ac+3][ar]=a0.w;
            As[nxt][ac+4][ar]=a1.x; As[nxt][ac+5][ar]=a1.y; As[nxt][ac+6][ar]=a1.z; As[nxt][ac+7][ar]=a1.w;
            *(float4*)&Bs[nxt][kB][nB] = b0;
        }
        __syncthreads();
    }

    float kst = isq ? 0.f : dec_f(g_kstab);
#pragma unroll
    for (int i = 0; i < 8; i++) {
        int m = m0 + ty*8 + i;
        float off = isq ? 0.f : (g_hk[(size_t)h * L + m] - kst);
        float4 o;
        o.x = NC_COEF * (__expf(acc[i][0] + off) + KEPS);
        o.y = NC_COEF * (__expf(acc[i][1] + off) + KEPS);
        o.z = NC_COEF * (__expf(acc[i][2] + off) + KEPS);
        o.w = NC_COEF * (__expf(acc[i][3] + off) + KEPS);
        *(float4*)(C + (size_t)m * MF + n0 + tx*4) = o;
    }
}

// ---------------- per-(head,chunk) state: S = K'^T V, z = sum k' ----------------
__global__ void chunk_state(){
    __shared__ float Ks[32][128];
    __shared__ float Vs[32][64];
    int c = blockIdx.x, h = blockIdx.y;
    int tid = threadIdx.x;
    int l0 = c * CHK;
    int d = tid & 63, mg = tid >> 6;
    float acc[32];
#pragma unroll
    for (int j = 0; j < 32; j++) acc[j] = 0.f;
    float zacc = 0.f;

    for (int half = 0; half < 2; half++) {
        int lb = l0 + half * 32;
        const float4* srck = (const float4*)(g_pk + ((size_t)h * L + lb) * MF);
        float4* dstk = (float4*)&Ks[0][0];
        for (int i = tid; i < 1024; i += 256) dstk[i] = srck[i];
        for (int i = tid; i < 512; i += 256) {
            int r = i >> 4, c4 = (i & 15) * 4;
            *(float4*)&Vs[r][c4] = *(const float4*)(g_v + (size_t)(lb + r) * DM + h * DH + c4);
        }
        __syncthreads();
        for (int l = 0; l < 32; l++) {
            float vv = Vs[l][d];
#pragma unroll
            for (int jb = 0; jb < 8; jb++) {
                float4 kk = *(const float4*)&Ks[l][mg*32 + jb*4];
                acc[jb*4+0] += kk.x * vv;
                acc[jb*4+1] += kk.y * vv;
                acc[jb*4+2] += kk.z * vv;
                acc[jb*4+3] += kk.w * vv;
            }
        }
        if (tid < 128) {
            float s = 0.f;
            for (int l = 0; l < 32; l++) s += Ks[l][tid];
            zacc += s;
        }
        __syncthreads();
    }
    size_t base = ((size_t)(h * NC + c) * MF) * DH;
#pragma unroll
    for (int j = 0; j < 32; j++) g_S[base + (size_t)(mg*32 + j) * DH + d] = acc[j];
    if (tid < 128) g_z[(size_t)(h * NC + c) * MF + tid] = zacc;
}

// ---------------- exclusive prefix over chunks ----------------
__global__ void prefix_scan(){
    int h = blockIdx.y;
    int idx = blockIdx.x * 256 + threadIdx.x;
    if (idx < MF * DH) {
        float* p = g_S + (size_t)h * NC * MF * DH + idx;
        float prev = 0.f;
#pragma unroll
        for (int c = 0; c < NC; c++) {
            float cur = p[(size_t)c * MF * DH];
            p[(size_t)c * MF * DH] = prev;
            prev += cur;
        }
    } else if (idx < MF * DH + MF) {
        int m = idx - MF * DH;
        float* p = g_z + (size_t)h * NC * MF + m;
        float prev = 0.f;
#pragma unroll
        for (int c = 0; c < NC; c++) {
            float cur = p[c * MF];
            p[c * MF] = prev;
            prev += cur;
        }
    }
}

// ---------------- per-(head,chunk) output ----------------
#define SQ 129
#define SK 129
#define SA 65
#define CO_SMEM_FLOATS (64*SQ + 64*SK + 64*64 + 128*64 + 64*SA + 128 + 64)
__global__ void chunk_out(){
    extern __shared__ float sm[];
    float* Qs = sm;
    float* Ks = Qs + 64*SQ;
    float* Vs = Ks + 64*SK;
    float* Ss = Vs + 64*64;
    float* As = Ss + 128*64;
    float* zs = As + 64*SA;
    float* rs = zs + 128;

    int c = blockIdx.x, h = blockIdx.y;
    int tid = threadIdx.x;
    int l0 = c * CHK;

    {
        const float4* srcq = (const float4*)(g_pq + ((size_t)h * L + l0) * MF);
        const float4* srck = (const float4*)(g_pk + ((size_t)h * L + l0) * MF);
        for (int i = tid; i < 2048; i += 256) {
            int r = i >> 5, m4 = (i & 31) * 4;
            float4 a = srcq[i];
            Qs[r*SQ+m4] = a.x; Qs[r*SQ+m4+1] = a.y; Qs[r*SQ+m4+2] = a.z; Qs[r*SQ+m4+3] = a.w;
            float4 b = srck[i];
            Ks[r*SK+m4] = b.x; Ks[r*SK+m4+1] = b.y; Ks[r*SK+m4+2] = b.z; Ks[r*SK+m4+3] = b.w;
        }
        for (int i = tid; i < 1024; i += 256) {
            int r = i >> 4, c4 = (i & 15) * 4;
            *(float4*)&Vs[r*64 + c4] = *(const float4*)(g_v + (size_t)(l0 + r) * DM + h * DH + c4);
        }
        const float4* srcs = (const float4*)(g_S + (size_t)(h * NC + c) * MF * DH);
        float4* dsts = (float4*)Ss;
        for (int i = tid; i < 2048; i += 256) dsts[i] = srcs[i];
        if (tid < 128) zs[tid] = g_z[(size_t)(h * NC + c) * MF + tid];
    }
    __syncthreads();

    int ty = tid >> 4, tx = tid & 15;

    float acc[4][4];
#pragma unroll
    for (int ii = 0; ii < 4; ii++)
#pragma unroll
        for (int jj = 0; jj < 4; jj++) acc[ii][jj] = 0.f;

#pragma unroll 4
    for (int m = 0; m < 128; m++) {
        float qa[4], kb[4];
#pragma unroll
        for (int ii = 0; ii < 4; ii++) qa[ii] = Qs[(ty + 16*ii)*SQ + m];
#pragma unroll
        for (int jj = 0; jj < 4; jj++) kb[jj] = Ks[(tx + 16*jj)*SK + m];
#pragma unroll
        for (int ii = 0; ii < 4; ii++)
#pragma unroll
            for (int jj = 0; jj < 4; jj++) acc[ii][jj] += qa[ii] * kb[jj];
    }
#pragma unroll
    for (int ii = 0; ii < 4; ii++)
#pragma unroll
        for (int jj = 0; jj < 4; jj++) {
            int i = ty + 16*ii, j = tx + 16*jj;
            As[i*SA + j] = (j <= i) ? acc[ii][jj] : 0.f;
        }
    __syncthreads();

    if (tid < 64) {
        float s = 0.f;
        for (int j = 0; j < 64; j++) s += As[tid*SA + j];
        for (int m = 0; m < 128; m++) s += Qs[tid*SQ + m] * zs[m];
        rs[tid] = s + DEPS;
    }
    __syncthreads();

    float4 o[4];
#pragma unroll
    for (int ii = 0; ii < 4; ii++) { o[ii].x = 0.f; o[ii].y = 0.f; o[ii].z = 0.f; o[ii].w = 0.f; }

#pragma unroll 2
    for (int j = 0; j < 64; j++) {
        float4 v4 = *(float4*)&Vs[j*64 + tx*4];
#pragma unroll
        for (int ii = 0; ii < 4; ii++) {
            float aa = As[(ty + 16*ii)*SA + j];
            o[ii].x += aa * v4.x; o[ii].y += aa * v4.y; o[ii].z += aa * v4.z; o[ii].w += aa * v4.w;
        }
    }
#pragma unroll 2
    for (int m = 0; m < 128; m++) {
        float4 s4 = *(float4*)&Ss[m*64 + tx*4];
#pragma unroll
        for (int ii = 0; ii < 4; ii++) {
            float qv = Qs[(ty + 16*ii)*SQ + m];
            o[ii].x += qv * s4.x; o[ii].y += qv * s4.y; o[ii].z += qv * s4.z; o[ii].w += qv * s4.w;
        }
    }
#pragma unroll
    for (int ii = 0; ii < 4; ii++) {
        int i = ty + 16*ii;
        float inv = 1.0f / rs[i];
        float4 w;
        w.x = o[ii].x * inv; w.y = o[ii].y * inv; w.z = o[ii].z * inv; w.w = o[ii].w * inv;
        *(float4*)(g_ctx + (size_t)(l0 + i) * DM + h * DH + tx*4) = w;
    }
}

// ---------------- launcher ----------------
extern "C" void kernel_launch(void* const* d_in, const int* in_sizes, int n_in,
                              void* d_out, int out_size)
{
    const float* query = (const float*)d_in[0];
    const float* key_i = (const float*)d_in[1];
    const float* value = (const float*)d_in[2];
    const float* Wq = (const float*)d_in[3];
    const float* bq = (const float*)d_in[4];
    const float* Wk = (const float*)d_in[5];
    const float* bk = (const float*)d_in[6];
    const float* Wv = (const float*)d_in[7];
    const float* bv = (const float*)d_in[8];
    const float* Wo = (const float*)d_in[9];
    const float* bo = (const float*)d_in[10];
    const float* rf = (const float*)d_in[11];
    float* out = (float*)d_out;

    void* p;
    cudaGetSymbolAddress(&p, g_q);       float* q   = (float*)p;
    cudaGetSymbolAddress(&p, g_k);       float* k   = (float*)p;
    cudaGetSymbolAddress(&p, g_v);       float* v   = (float*)p;
    cudaGetSymbolAddress(&p, g_ctx);     float* ctx = (float*)p;
    cudaGetSymbolAddress(&p, g_bhi_in);  __nv_bfloat16* bhi_in = (__nv_bfloat16*)p;
    cudaGetSymbolAddress(&p, g_blo_in);  __nv_bfloat16* blo_in = (__nv_bfloat16*)p;
    cudaGetSymbolAddress(&p, g_bhi_w);   __nv_bfloat16* bhi_w  = (__nv_bfloat16*)p;
    cudaGetSymbolAddress(&p, g_blo_w);   __nv_bfloat16* blo_w  = (__nv_bfloat16*)p;
    cudaGetSymbolAddress(&p, g_bhi_ctx); __nv_bfloat16* bhi_c  = (__nv_bfloat16*)p;
    cudaGetSymbolAddress(&p, g_blo_ctx); __nv_bfloat16* blo_c  = (__nv_bfloat16*)p;

    reset_kstab<<<1, 1>>>();

    // split-convert inputs + weights
    CV cv;
    cv.src[0]=query; cv.hi[0]=bhi_in;          cv.lo[0]=blo_in;          cv.n[0]=L*DM;
    cv.src[1]=key_i; cv.hi[1]=bhi_in+L*DM;     cv.lo[1]=blo_in+L*DM;     cv.n[1]=L*DM;
    cv.src[2]=value; cv.hi[2]=bhi_in+2*L*DM;   cv.lo[2]=blo_in+2*L*DM;   cv.n[2]=L*DM;
    cv.src[3]=Wq;    cv.hi[3]=bhi_w;           cv.lo[3]=blo_w;           cv.n[3]=DM*DM;
    cv.src[4]=Wk;    cv.hi[4]=bhi_w+DM*DM;     cv.lo[4]=blo_w+DM*DM;     cv.n[4]=DM*DM;
    cv.src[5]=Wv;    cv.hi[5]=bhi_w+2*DM*DM;   cv.lo[5]=blo_w+2*DM*DM;   cv.n[5]=DM*DM;
    cv.src[6]=Wo;    cv.hi[6]=bhi_w+3*DM*DM;   cv.lo[6]=blo_w+3*DM*DM;   cv.n[6]=DM*DM;
    cv.cnt = 7;
    convert_split<<<dim3((L*DM)/1024, 7), 256>>>(cv);

    cudaFuncSetAttribute(hmma_gemm, cudaFuncAttributeMaxDynamicSharedMemorySize, HG_SMEM);

    // QKV projections (HMMA split-bf16)
    MMArgs mq;
    mq.Ahi[0]=bhi_in;        mq.Alo[0]=blo_in;        mq.Whi[0]=bhi_w;        mq.Wlo[0]=blo_w;        mq.bias[0]=bq; mq.C[0]=q; mq.alpha[0]=SCALE_QK;
    mq.Ahi[1]=bhi_in+L*DM;   mq.Alo[1]=blo_in+L*DM;   mq.Whi[1]=bhi_w+DM*DM;  mq.Wlo[1]=blo_w+DM*DM;  mq.bias[1]=bk; mq.C[1]=k; mq.alpha[1]=SCALE_QK;
    mq.Ahi[2]=bhi_in+2*L*DM; mq.Alo[2]=blo_in+2*L*DM; mq.Whi[2]=bhi_w+2*DM*DM;mq.Wlo[2]=blo_w+2*DM*DM;mq.bias[2]=bv; mq.C[2]=v; mq.alpha[2]=1.0f;
    hmma_gemm<<<dim3(DM/128, L/128, 3), 256, HG_SMEM>>>(mq);

    // h_k + stabilizer
    hk_max<<<L, 256>>>();

    // rf projections + featurize
    rf_proj<<<dim3(MF/64, L/128, 16), 256>>>(rf);

    // chunked causal linear attention
    chunk_state<<<dim3(NC, NH), 256>>>();
    prefix_scan<<<dim3((MF*DH + MF + 255)/256, NH), 256>>>();
    cudaFuncSetAttribute(chunk_out, cudaFuncAttributeMaxDynamicSharedMemorySize, CO_SMEM_FLOATS * 4);
    chunk_out<<<dim3(NC, NH), 256, CO_SMEM_FLOATS * 4>>>();

    // convert ctx, then output projection
    CV cc;
    cc.src[0]=ctx; cc.hi[0]=bhi_c; cc.lo[0]=blo_c; cc.n[0]=L*DM;
    cc.cnt = 1;
    convert_split<<<dim3((L*DM)/1024, 1), 256>>>(cc);

    MMArgs mo;
    mo.Ahi[0]=bhi_c; mo.Alo[0]=blo_c; mo.Whi[0]=bhi_w+3*DM*DM; mo.Wlo[0]=blo_w+3*DM*DM; mo.bias[0]=bo; mo.C[0]=out; mo.alpha[0]=1.0f;
    mo.Ahi[1]=mo.Ahi[0]; mo.Alo[1]=mo.Alo[0]; mo.Whi[1]=mo.Whi[0]; mo.Wlo[1]=mo.Wlo[0]; mo.bias[1]=bo; mo.C[1]=out; mo.alpha[1]=1.0f;
    mo.Ahi[2]=mo.Ahi[0]; mo.Alo[2]=mo.Alo[0]; mo.Whi[2]=mo.Whi[0]; mo.Wlo[2]=mo.Wlo[0]; mo.bias[2]=bo; mo.C[2]=out; mo.alpha[2]=1.0f;
    hmma_gemm<<<dim3(DM/128, L/128, 1), 256, HG_SMEM>>>(mo);
}

// round 6
// speedup vs baseline: 3.0497x; 1.1555x over previous
#include <cuda_runtime.h>
#include <cuda_bf16.h>
#include <math.h>
#include <stdint.h>

#define L 2048
#define DM 512
#define NH 8
#define DH 64
#define MF 128
#define CHK 64
#define NC (L/CHK)   // 32

#define SCALE_QK 0.2102241038134287f     // 512^-0.25
#define NC_COEF  0.08838834764831845f    // 128^-0.5
#define KEPS 1e-4f
#define DEPS 1e-6f

// ---------------- device scratch ----------------
__device__ float g_v[L*DM];
__device__ float g_pq[NH*L*MF];
__device__ float g_pk[NH*L*MF];
__device__ float g_hk[NH*L];
__device__ unsigned g_kstab;
__device__ float g_S[NH*NC*MF*DH];
__device__ float g_z[NH*NC*MF];
__device__ float g_ctx[L*DM];

// split-bf16 buffers
__device__ __nv_bfloat16 g_bhi_in[3][L*DM];
__device__ __nv_bfloat16 g_blo_in[3][L*DM];
__device__ __nv_bfloat16 g_bhi_w[4][DM*DM];
__device__ __nv_bfloat16 g_blo_w[4][DM*DM];
__device__ __nv_bfloat16 g_bhi_ctx[L*DM];
__device__ __nv_bfloat16 g_blo_ctx[L*DM];
__device__ __nv_bfloat16 g_qhi[L*DM];
__device__ __nv_bfloat16 g_qlo[L*DM];
__device__ __nv_bfloat16 g_khi[L*DM];
__device__ __nv_bfloat16 g_klo[L*DM];
__device__ __nv_bfloat16 g_rfthi[MF*DH];
__device__ __nv_bfloat16 g_rftlo[MF*DH];

__device__ __forceinline__ unsigned enc_f(float f){
    unsigned u = __float_as_uint(f);
    return (u & 0x80000000u) ? ~u : (u | 0x80000000u);
}
__device__ __forceinline__ float dec_f(unsigned k){
    unsigned u = (k & 0x80000000u) ? (k ^ 0x80000000u) : ~k;
    return __uint_as_float(u);
}

__global__ void reset_kstab(){ g_kstab = 0u; }

__device__ __forceinline__ uint32_t smem_u32(const void* p) {
    uint32_t a;
    asm("{ .reg .u64 t; cvta.to.shared.u64 t, %1; cvt.u32.u64 %0, t; }" : "=r"(a) : "l"(p));
    return a;
}

#define CP_ASYNC16(sa, gp) asm volatile("cp.async.cg.shared.global [%0], [%1], 16;" :: "r"(sa), "l"(gp))
#define CP_COMMIT()        asm volatile("cp.async.commit_group;")
#define CP_WAIT1()         asm volatile("cp.async.wait_group 1;")
#define CP_WAIT0()         asm volatile("cp.async.wait_group 0;")

#define LDSM4(r0,r1,r2,r3,a) \
    asm volatile("ldmatrix.sync.aligned.m8n8.x4.shared.b16 {%0,%1,%2,%3}, [%4];" \
        : "=r"(r0),"=r"(r1),"=r"(r2),"=r"(r3) : "r"(a))

#define MMA16816(d,a,b0,b1) \
    asm volatile("mma.sync.aligned.m16n8k16.row.col.f32.bf16.bf16.f32 " \
        "{%0,%1,%2,%3},{%4,%5,%6,%7},{%8,%9},{%0,%1,%2,%3};" \
        : "+f"((d)[0]),"+f"((d)[1]),"+f"((d)[2]),"+f"((d)[3]) \
        : "r"((a)[0]),"r"((a)[1]),"r"((a)[2]),"r"((a)[3]),"r"(b0),"r"(b1))

// ---------------- fp32 -> (bf16 hi, bf16 lo) converter ----------------
struct CV { const float* src[8]; __nv_bfloat16* hi[8]; __nv_bfloat16* lo[8]; int n[8]; int cnt; };
__global__ void convert_split(CV cv){
    int t = blockIdx.y;
    if (t >= cv.cnt) return;
    int n = cv.n[t];
    const float* s = cv.src[t];
    __nv_bfloat16* ph = cv.hi[t];
    __nv_bfloat16* pl = cv.lo[t];
    int i0 = blockIdx.x * 1024 + threadIdx.x;
#pragma unroll
    for (int j = 0; j < 4; j++) {
        int i = i0 + j * 256;
        if (i < n) {
            float x = s[i];
            __nv_bfloat16 h = __float2bfloat16(x);
            ph[i] = h;
            pl[i] = __float2bfloat16(x - __bfloat162float(h));
        }
    }
}

// rf (d,m) fp32 -> rft (m,d) bf16 hi/lo
__global__ void rf_convert(const float* __restrict__ rf){
    int i = blockIdx.x * 256 + threadIdx.x;
    if (i < MF * DH) {
        int m = i >> 6, d = i & 63;
        float x = rf[(size_t)d * MF + m];
        __nv_bfloat16 h = __float2bfloat16(x);
        g_rfthi[(size_t)m * DH + d] = h;
        g_rftlo[(size_t)m * DH + d] = __float2bfloat16(x - __bfloat162float(h));
    }
}

// ---------------- split-bf16 HMMA GEMM ----------------
// Tile 128x128, BK=32, 8 warps (2Mx4N), mma.m16n8k16, cp.async double buffer.
#define PITCH_B 80
#define TILE_BYTES (128*PITCH_B)
#define STAGE_BYTES (4*TILE_BYTES)
#define HG_SMEM (2*STAGE_BYTES)
#define NKC 16

struct MMArgs {
    const __nv_bfloat16* Ahi[3]; const __nv_bfloat16* Alo[3];
    const __nv_bfloat16* Whi[3]; const __nv_bfloat16* Wlo[3];
    const float* bias[3]; float* C[3];
    __nv_bfloat16* Chi[3]; __nv_bfloat16* Clo[3];
    float alpha[3];
};

__global__ __launch_bounds__(256) void hmma_gemm(MMArgs ga)
{
    extern __shared__ char smem[];
    uint32_t sb = smem_u32(smem);
    int tid = threadIdx.x;
    int lane = tid & 31, wid = tid >> 5;
    int warp_m = wid & 1, warp_n = wid >> 1;
    int z = blockIdx.z;
    int m0 = blockIdx.y * 128, n0 = blockIdx.x * 128;

    const __nv_bfloat16* Ahi = ga.Ahi[z] + (size_t)m0 * DM;
    const __nv_bfloat16* Alo = ga.Alo[z] + (size_t)m0 * DM;
    const __nv_bfloat16* Whi = ga.Whi[z] + (size_t)n0 * DM;
    const __nv_bfloat16* Wlo = ga.Wlo[z] + (size_t)n0 * DM;
    const float* bias = ga.bias[z];
    float alpha = ga.alpha[z];

    uint32_t a_off = (uint32_t)(warp_m*64 + (lane & 15)) * PITCH_B + (lane >> 4) * 16;
    uint32_t b_off = (uint32_t)(warp_n*32 + (lane & 7) + (lane >> 4) * 8) * PITCH_B + ((lane >> 3) & 1) * 16;

    float acc[4][4][4];
#pragma unroll
    for (int i = 0; i < 4; i++)
#pragma unroll
        for (int j = 0; j < 4; j++)
#pragma unroll
            for (int r = 0; r < 4; r++) acc[i][j][r] = 0.f;

    {
#pragma unroll
        for (int j = 0; j < 8; j++) {
            int idx = tid + j * 256;
            int tile = idx >> 9;
            int w = idx & 511;
            int r = w >> 2, c = w & 3;
            const __nv_bfloat16* gp =
                (tile == 0) ? (Ahi + (size_t)r * DM + c*8) :
                (tile == 1) ? (Alo + (size_t)r * DM + c*8) :
                (tile == 2) ? (Whi + (size_t)r * DM + c*8) :
                              (Wlo + (size_t)r * DM + c*8);
            uint32_t sp = sb + tile * TILE_BYTES + (uint32_t)r * PITCH_B + c * 16;
            CP_ASYNC16(sp, gp);
        }
        CP_COMMIT();
    }

    for (int kc = 0; kc < NKC; kc++) {
        if (kc + 1 < NKC) {
            int k0 = (kc + 1) * 32;
            uint32_t stb = sb + ((kc + 1) & 1) * STAGE_BYTES;
#pragma unroll
            for (int j = 0; j < 8; j++) {
                int idx = tid + j * 256;
                int tile = idx >> 9;
                int w = idx & 511;
                int r = w >> 2, c = w & 3;
                const __nv_bfloat16* gp =
                    (tile == 0) ? (Ahi + (size_t)r * DM + k0 + c*8) :
                    (tile == 1) ? (Alo + (size_t)r * DM + k0 + c*8) :
                    (tile == 2) ? (Whi + (size_t)r * DM + k0 + c*8) :
                                  (Wlo + (size_t)r * DM + k0 + c*8);
                uint32_t sp = stb + tile * TILE_BYTES + (uint32_t)r * PITCH_B + c * 16;
                CP_ASYNC16(sp, gp);
            }
            CP_COMMIT();
            CP_WAIT1();
        } else {
            CP_WAIT0();
        }
        __syncthreads();

        uint32_t st = sb + (kc & 1) * STAGE_BYTES;
        uint32_t sAhi = st + a_off;
        uint32_t sAlo = st + TILE_BYTES + a_off;
        uint32_t sBhi = st + 2*TILE_BYTES + b_off;
        uint32_t sBlo = st + 3*TILE_BYTES + b_off;

#pragma unroll
        for (int ks = 0; ks < 2; ks++) {
            uint32_t ah[4][4], al[4][4], bh[2][4], bl[2][4];
#pragma unroll
            for (int mi = 0; mi < 4; mi++) {
                LDSM4(ah[mi][0], ah[mi][1], ah[mi][2], ah[mi][3], sAhi + mi*16*PITCH_B + ks*32);
                LDSM4(al[mi][0], al[mi][1], al[mi][2], al[mi][3], sAlo + mi*16*PITCH_B + ks*32);
            }
#pragma unroll
            for (int nb = 0; nb < 2; nb++) {
                LDSM4(bh[nb][0], bh[nb][1], bh[nb][2], bh[nb][3], sBhi + nb*16*PITCH_B + ks*32);
                LDSM4(bl[nb][0], bl[nb][1], bl[nb][2], bl[nb][3], sBlo + nb*16*PITCH_B + ks*32);
            }
#pragma unroll
            for (int mi = 0; mi < 4; mi++)
#pragma unroll
                for (int nb = 0; nb < 2; nb++) {
                    MMA16816(acc[mi][nb*2+0], ah[mi], bh[nb][0], bh[nb][1]);
                    MMA16816(acc[mi][nb*2+1], ah[mi], bh[nb][2], bh[nb][3]);
                    MMA16816(acc[mi][nb*2+0], ah[mi], bl[nb][0], bl[nb][1]);
                    MMA16816(acc[mi][nb*2+1], ah[mi], bl[nb][2], bl[nb][3]);
                    MMA16816(acc[mi][nb*2+0], al[mi], bh[nb][0], bh[nb][1]);
                    MMA16816(acc[mi][nb*2+1], al[mi], bh[nb][2], bh[nb][3]);
                }
        }
        __syncthreads();
    }

    int g = lane >> 2, t = lane & 3;
    __nv_bfloat16* Chi = ga.Chi[z];
    if (Chi) {
        __nv_bfloat16* Clo = ga.Clo[z];
#pragma unroll
        for (int mi = 0; mi < 4; mi++) {
            int row = m0 + warp_m*64 + mi*16 + g;
#pragma unroll
            for (int nj = 0; nj < 4; nj++) {
                int col = n0 + warp_n*32 + nj*8 + t*2;
                float2 bb = *(const float2*)(bias + col);
#pragma unroll
                for (int half = 0; half < 2; half++) {
                    int r = row + half*8;
                    float ox = alpha * (acc[mi][nj][half*2+0] + bb.x);
                    float oy = alpha * (acc[mi][nj][half*2+1] + bb.y);
                    __nv_bfloat16 hx = __float2bfloat16(ox);
                    __nv_bfloat16 hy = __float2bfloat16(oy);
                    __nv_bfloat162 hv; hv.x = hx; hv.y = hy;
                    __nv_bfloat162 lv;
                    lv.x = __float2bfloat16(ox - __bfloat162float(hx));
                    lv.y = __float2bfloat16(oy - __bfloat162float(hy));
                    *(__nv_bfloat162*)(Chi + (size_t)r * DM + col) = hv;
                    *(__nv_bfloat162*)(Clo + (size_t)r * DM + col) = lv;
                }
            }
        }
    } else {
        float* C = ga.C[z];
#pragma unroll
        for (int mi = 0; mi < 4; mi++) {
            int row = m0 + warp_m*64 + mi*16 + g;
#pragma unroll
            for (int nj = 0; nj < 4; nj++) {
                int col = n0 + warp_n*32 + nj*8 + t*2;
                float2 bb = *(const float2*)(bias + col);
                float2 o0, o1;
                o0.x = alpha * (acc[mi][nj][0] + bb.x);
                o0.y = alpha * (acc[mi][nj][1] + bb.y);
                o1.x = alpha * (acc[mi][nj][2] + bb.x);
                o1.y = alpha * (acc[mi][nj][3] + bb.y);
                *(float2*)(C + (size_t)row * DM + col) = o0;
                *(float2*)(C + (size_t)(row + 8) * DM + col) = o1;
            }
        }
    }
}

// ---------------- h_k per (head,row) + global max (from bf16 k) ----------------
__global__ void hk_max(){
    int l = blockIdx.x;
    int w = threadIdx.x >> 5, lane = threadIdx.x & 31;
    size_t base = (size_t)l * DM + w * DH;
    float x0 = __bfloat162float(g_khi[base + lane]) + __bfloat162float(g_klo[base + lane]);
    float x1 = __bfloat162float(g_khi[base + lane + 32]) + __bfloat162float(g_klo[base + lane + 32]);
    float ss = x0*x0 + x1*x1;
#pragma unroll
    for (int o = 16; o; o >>= 1) ss += __shfl_xor_sync(0xffffffffu, ss, o);
    __shared__ float wm[8];
    if (lane == 0) { float hv = -0.5f * ss; g_hk[(size_t)w * L + l] = hv; wm[w] = hv; }
    __syncthreads();
    if (threadIdx.x == 0) {
        float mx = wm[0];
#pragma unroll
        for (int i = 1; i < 8; i++) mx = fmaxf(mx, wm[i]);
        atomicMax(&g_kstab, enc_f(mx));
    }
}

// ---------------- rf projection + featurize (HMMA split-bf16) ----------------
// M=2048 (per z), N=128, K=64; z: head = z&7, q if z<8 else k.
#define PITCH2 144
#define TILE2 (128*PITCH2)      // 18432
#define RF_SMEM (4*TILE2)       // 73728

__global__ __launch_bounds__(256) void rf_proj_hmma()
{
    extern __shared__ char smem[];
    uint32_t sb = smem_u32(smem);
    int tid = threadIdx.x;
    int lane = tid & 31, wid = tid >> 5;
    int warp_m = wid & 1, warp_n = wid >> 1;
    int z = blockIdx.z;
    int h = z & 7;
    bool isq = z < 8;
    int m0 = blockIdx.y * 128;

    const __nv_bfloat16* Ahi = (isq ? g_qhi : g_khi) + (size_t)m0 * DM + h * DH;
    const __nv_bfloat16* Alo = (isq ? g_qlo : g_klo) + (size_t)m0 * DM + h * DH;
    float* C = (isq ? g_pq : g_pk) + (size_t)h * L * MF;

    // load 4 tiles (A hi/lo 128x64, B=rft hi/lo 128x64), single stage
#pragma unroll
    for (int j = 0; j < 16; j++) {
        int idx = tid + j * 256;      // 4096 chunks
        int tile = idx >> 10;
        int w = idx & 1023;
        int r = w >> 3, c = w & 7;
        const __nv_bfloat16* gp =
            (tile == 0) ? (Ahi + (size_t)r * DM + c*8) :
            (tile == 1) ? (Alo + (size_t)r * DM + c*8) :
            (tile == 2) ? (g_rfthi + (size_t)r * DH + c*8) :
                          (g_rftlo + (size_t)r * DH + c*8);
        uint32_t sp = sb + tile * TILE2 + (uint32_t)r * PITCH2 + c * 16;
        CP_ASYNC16(sp, gp);
    }
    CP_COMMIT();
    CP_WAIT0();
    __syncthreads();

    uint32_t a_off = (uint32_t)(warp_m*64 + (lane & 15)) * PITCH2 + (lane >> 4) * 16;
    uint32_t b_off = (uint32_t)(warp_n*32 + (lane & 7) + (lane >> 4) * 8) * PITCH2 + ((lane >> 3) & 1) * 16;
    uint32_t sAhi = sb + a_off;
    uint32_t sAlo = sb + TILE2 + a_off;
    uint32_t sBhi = sb + 2*TILE2 + b_off;
    uint32_t sBlo = sb + 3*TILE2 + b_off;

    float acc[4][4][4];
#pragma unroll
    for (int i = 0; i < 4; i++)
#pragma unroll
        for (int j = 0; j < 4; j++)
#pragma unroll
            for (int r = 0; r < 4; r++) acc[i][j][r] = 0.f;

#pragma unroll
    for (int ks = 0; ks < 4; ks++) {
        uint32_t ah[4][4], al[4][4], bh[2][4], bl[2][4];
#pragma unroll
        for (int mi = 0; mi < 4; mi++) {
            LDSM4(ah[mi][0], ah[mi][1], ah[mi][2], ah[mi][3], sAhi + mi*16*PITCH2 + ks*32);
            LDSM4(al[mi][0], al[mi][1], al[mi][2], al[mi][3], sAlo + mi*16*PITCH2 + ks*32);
        }
#pragma unroll
        for (int nb = 0; nb < 2; nb++) {
            LDSM4(bh[nb][0], bh[nb][1], bh[nb][2], bh[nb][3], sBhi + nb*16*PITCH2 + ks*32);
            LDSM4(bl[nb][0], bl[nb][1], bl[nb][2], bl[nb][3], sBlo + nb*16*PITCH2 + ks*32);
        }
#pragma unroll
        for (int mi = 0; mi < 4; mi++)
#pragma unroll
            for (int nb = 0; nb < 2; nb++) {
                MMA16816(acc[mi][nb*2+0], ah[mi], bh[nb][0], bh[nb][1]);
                MMA16816(acc[mi][nb*2+1], ah[mi], bh[nb][2], bh[nb][3]);
                MMA16816(acc[mi][nb*2+0], ah[mi], bl[nb][0], bl[nb][1]);
                MMA16816(acc[mi][nb*2+1], ah[mi], bl[nb][2], bl[nb][3]);
                MMA16816(acc[mi][nb*2+0], al[mi], bh[nb][0], bh[nb][1]);
                MMA16816(acc[mi][nb*2+1], al[mi], bh[nb][2], bh[nb][3]);
            }
    }

    // featurize epilogue
    float kst = isq ? 0.f : dec_f(g_kstab);
    int g = lane >> 2, t = lane & 3;
#pragma unroll
    for (int mi = 0; mi < 4; mi++) {
#pragma unroll
        for (int half = 0; half < 2; half++) {
            int row = m0 + warp_m*64 + mi*16 + g + half*8;
            float off = isq ? 0.f : (g_hk[(size_t)h * L + row] - kst);
#pragma unroll
            for (int nj = 0; nj < 4; nj++) {
                int col = warp_n*32 + nj*8 + t*2;
                float2 o;
                o.x = NC_COEF * (__expf(acc[mi][nj][half*2+0] + off) + KEPS);
                o.y = NC_COEF * (__expf(acc[mi][nj][half*2+1] + off) + KEPS);
                *(float2*)(C + (size_t)row * MF + col) = o;
            }
        }
    }
}

// ---------------- per-(head,chunk) state: S = K'^T V, z = sum k' ----------------
__global__ void chunk_state(){
    __shared__ float Ks[32][128];
    __shared__ float Vs[32][64];
    int c = blockIdx.x, h = blockIdx.y;
    int tid = threadIdx.x;
    int l0 = c * CHK;
    int d = tid & 63, mg = tid >> 6;
    float acc[32];
#pragma unroll
    for (int j = 0; j < 32; j++) acc[j] = 0.f;
    float zacc = 0.f;

    for (int half = 0; half < 2; half++) {
        int lb = l0 + half * 32;
        const float4* srck = (const float4*)(g_pk + ((size_t)h * L + lb) * MF);
        float4* dstk = (float4*)&Ks[0][0];
        for (int i = tid; i < 1024; i += 256) dstk[i] = srck[i];
        for (int i = tid; i < 512; i += 256) {
            int r = i >> 4, c4 = (i & 15) * 4;
            *(float4*)&Vs[r][c4] = *(const float4*)(g_v + (size_t)(lb + r) * DM + h * DH + c4);
        }
        __syncthreads();
        for (int l = 0; l < 32; l++) {
            float vv = Vs[l][d];
#pragma unroll
            for (int jb = 0; jb < 8; jb++) {
                float4 kk = *(const float4*)&Ks[l][mg*32 + jb*4];
                acc[jb*4+0] += kk.x * vv;
                acc[jb*4+1] += kk.y * vv;
                acc[jb*4+2] += kk.z * vv;
                acc[jb*4+3] += kk.w * vv;
            }
        }
        if (tid < 128) {
            float s = 0.f;
            for (int l = 0; l < 32; l++) s += Ks[l][tid];
            zacc += s;
        }
        __syncthreads();
    }
    size_t base = ((size_t)(h * NC + c) * MF) * DH;
#pragma unroll
    for (int j = 0; j < 32; j++) g_S[base + (size_t)(mg*32 + j) * DH + d] = acc[j];
    if (tid < 128) g_z[(size_t)(h * NC + c) * MF + tid] = zacc;
}

// ---------------- exclusive prefix over chunks ----------------
__global__ void prefix_scan(){
    int h = blockIdx.y;
    int idx = blockIdx.x * 256 + threadIdx.x;
    if (idx < MF * DH) {
        float* p = g_S + (size_t)h * NC * MF * DH + idx;
        float prev = 0.f;
#pragma unroll
        for (int c = 0; c < NC; c++) {
            float cur = p[(size_t)c * MF * DH];
            p[(size_t)c * MF * DH] = prev;
            prev += cur;
        }
    } else if (idx < MF * DH + MF) {
        int m = idx - MF * DH;
        float* p = g_z + (size_t)h * NC * MF + m;
        float prev = 0.f;
#pragma unroll
        for (int c = 0; c < NC; c++) {
            float cur = p[c * MF];
            p[c * MF] = prev;
            prev += cur;
        }
    }
}

// ---------------- per-(head,chunk) output ----------------
#define SQ 132
#define SK 132
#define SA 68
#define CO_SMEM_FLOATS (64*SQ + 64*SK + 64*64 + 128*64 + 64*SA + 128 + 64)
__global__ void chunk_out(){
    extern __shared__ float sm[];
    float* Qs = sm;
    float* Ks = Qs + 64*SQ;
    float* Vs = Ks + 64*SK;
    float* Ss = Vs + 64*64;
    float* As = Ss + 128*64;
    float* zs = As + 64*SA;
    float* rs = zs + 128;

    int c = blockIdx.x, h = blockIdx.y;
    int tid = threadIdx.x;
    int l0 = c * CHK;

    {
        const float4* srcq = (const float4*)(g_pq + ((size_t)h * L + l0) * MF);
        const float4* srck = (const float4*)(g_pk + ((size_t)h * L + l0) * MF);
        for (int i = tid; i < 2048; i += 256) {
            int r = i >> 5, m4 = (i & 31) * 4;
            *(float4*)&Qs[r*SQ+m4] = srcq[i];
            *(float4*)&Ks[r*SK+m4] = srck[i];
        }
        for (int i = tid; i < 1024; i += 256) {
            int r = i >> 4, c4 = (i & 15) * 4;
            *(float4*)&Vs[r*64 + c4] = *(const float4*)(g_v + (size_t)(l0 + r) * DM + h * DH + c4);
        }
        const float4* srcs = (const float4*)(g_S + (size_t)(h * NC + c) * MF * DH);
        float4* dsts = (float4*)Ss;
        for (int i = tid; i < 2048; i += 256) dsts[i] = srcs[i];
        if (tid < 128) zs[tid] = g_z[(size_t)(h * NC + c) * MF + tid];
    }
    __syncthreads();

    int ty = tid >> 4, tx = tid & 15;

    float acc[4][4];
#pragma unroll
    for (int ii = 0; ii < 4; ii++)
#pragma unroll
        for (int jj = 0; jj < 4; jj++) acc[ii][jj] = 0.f;

#pragma unroll 2
    for (int m = 0; m < 128; m += 4) {
        float4 qa[4], kb[4];
#pragma unroll
        for (int ii = 0; ii < 4; ii++) qa[ii] = *(const float4*)&Qs[(ty + 16*ii)*SQ + m];
#pragma unroll
        for (int jj = 0; jj < 4; jj++) kb[jj] = *(const float4*)&Ks[(tx + 16*jj)*SK + m];
#pragma unroll
        for (int ii = 0; ii < 4; ii++)
#pragma unroll
            for (int jj = 0; jj < 4; jj++)
                acc[ii][jj] += qa[ii].x*kb[jj].x + qa[ii].y*kb[jj].y + qa[ii].z*kb[jj].z + qa[ii].w*kb[jj].w;
    }
#pragma unroll
    for (int ii = 0; ii < 4; ii++)
#pragma unroll
        for (int jj = 0; jj < 4; jj++) {
            int i = ty + 16*ii, j = tx + 16*jj;
            As[i*SA + j] = (j <= i) ? acc[ii][jj] : 0.f;
        }
    __syncthreads();

    if (tid < 64) {
        float s = 0.f;
        for (int j = 0; j < 64; j++) s += As[tid*SA + j];
        for (int m = 0; m < 128; m += 4) {
            float4 q4 = *(const float4*)&Qs[tid*SQ + m];
            float4 z4 = *(const float4*)&zs[m];
            s += q4.x*z4.x + q4.y*z4.y + q4.z*z4.z + q4.w*z4.w;
        }
        rs[tid] = s + DEPS;
    }
    __syncthreads();

    float4 o[4];
#pragma unroll
    for (int ii = 0; ii < 4; ii++) { o[ii].x = 0.f; o[ii].y = 0.f; o[ii].z = 0.f; o[ii].w = 0.f; }

#pragma unroll 2
    for (int j = 0; j < 64; j++) {
        float4 v4 = *(float4*)&Vs[j*64 + tx*4];
#pragma unroll
        for (int ii = 0; ii < 4; ii++) {
            float aa = As[(ty + 16*ii)*SA + j];
            o[ii].x += aa * v4.x; o[ii].y += aa * v4.y; o[ii].z += aa * v4.z; o[ii].w += aa * v4.w;
        }
    }
#pragma unroll 2
    for (int m = 0; m < 128; m++) {
        float4 s4 = *(float4*)&Ss[m*64 + tx*4];
#pragma unroll
        for (int ii = 0; ii < 4; ii++) {
            float qv = Qs[(ty + 16*ii)*SQ + m];
            o[ii].x += qv * s4.x; o[ii].y += qv * s4.y; o[ii].z += qv * s4.z; o[ii].w += qv * s4.w;
        }
    }
#pragma unroll
    for (int ii = 0; ii < 4; ii++) {
        int i = ty + 16*ii;
        float inv = 1.0f / rs[i];
        float4 w;
        w.x = o[ii].x * inv; w.y = o[ii].y * inv; w.z = o[ii].z * inv; w.w = o[ii].w * inv;
        *(float4*)(g_ctx + (size_t)(l0 + i) * DM + h * DH + tx*4) = w;
    }
}

// ---------------- launcher ----------------
extern "C" void kernel_launch(void* const* d_in, const int* in_sizes, int n_in,
                              void* d_out, int out_size)
{
    const float* query = (const float*)d_in[0];
    const float* key_i = (const float*)d_in[1];
    const float* value = (const float*)d_in[2];
    const float* Wq = (const float*)d_in[3];
    const float* bq = (const float*)d_in[4];
    const float* Wk = (const float*)d_in[5];
    const float* bk = (const float*)d_in[6];
    const float* Wv = (const float*)d_in[7];
    const float* bv = (const float*)d_in[8];
    const float* Wo = (const float*)d_in[9];
    const float* bo = (const float*)d_in[10];
    const float* rf = (const float*)d_in[11];
    float* out = (float*)d_out;

    void* p;
    cudaGetSymbolAddress(&p, g_v);       float* v   = (float*)p;
    cudaGetSymbolAddress(&p, g_ctx);     float* ctx = (float*)p;
    cudaGetSymbolAddress(&p, g_bhi_in);  __nv_bfloat16* bhi_in = (__nv_bfloat16*)p;
    cudaGetSymbolAddress(&p, g_blo_in);  __nv_bfloat16* blo_in = (__nv_bfloat16*)p;
    cudaGetSymbolAddress(&p, g_bhi_w);   __nv_bfloat16* bhi_w  = (__nv_bfloat16*)p;
    cudaGetSymbolAddress(&p, g_blo_w);   __nv_bfloat16* blo_w  = (__nv_bfloat16*)p;
    cudaGetSymbolAddress(&p, g_bhi_ctx); __nv_bfloat16* bhi_c  = (__nv_bfloat16*)p;
    cudaGetSymbolAddress(&p, g_blo_ctx); __nv_bfloat16* blo_c  = (__nv_bfloat16*)p;
    cudaGetSymbolAddress(&p, g_qhi);     __nv_bfloat16* qhi    = (__nv_bfloat16*)p;
    cudaGetSymbolAddress(&p, g_qlo);     __nv_bfloat16* qlo    = (__nv_bfloat16*)p;
    cudaGetSymbolAddress(&p, g_khi);     __nv_bfloat16* khi    = (__nv_bfloat16*)p;
    cudaGetSymbolAddress(&p, g_klo);     __nv_bfloat16* klo    = (__nv_bfloat16*)p;

    reset_kstab<<<1, 1>>>();

    CV cv;
    cv.src[0]=query; cv.hi[0]=bhi_in;          cv.lo[0]=blo_in;          cv.n[0]=L*DM;
    cv.src[1]=key_i; cv.hi[1]=bhi_in+L*DM;     cv.lo[1]=blo_in+L*DM;     cv.n[1]=L*DM;
    cv.src[2]=value; cv.hi[2]=bhi_in+2*L*DM;   cv.lo[2]=blo_in+2*L*DM;   cv.n[2]=L*DM;
    cv.src[3]=Wq;    cv.hi[3]=bhi_w;           cv.lo[3]=blo_w;           cv.n[3]=DM*DM;
    cv.src[4]=Wk;    cv.hi[4]=bhi_w+DM*DM;     cv.lo[4]=blo_w+DM*DM;     cv.n[4]=DM*DM;
    cv.src[5]=Wv;    cv.hi[5]=bhi_w+2*DM*DM;   cv.lo[5]=blo_w+2*DM*DM;   cv.n[5]=DM*DM;
    cv.src[6]=Wo;    cv.hi[6]=bhi_w+3*DM*DM;   cv.lo[6]=blo_w+3*DM*DM;   cv.n[6]=DM*DM;
    cv.cnt = 7;
    convert_split<<<dim3((L*DM)/1024, 7), 256>>>(cv);
    rf_convert<<<(MF*DH + 255)/256, 256>>>(rf);

    cudaFuncSetAttribute(hmma_gemm, cudaFuncAttributeMaxDynamicSharedMemorySize, HG_SMEM);
    cudaFuncSetAttribute(rf_proj_hmma, cudaFuncAttributeMaxDynamicSharedMemorySize, RF_SMEM);

    // QKV projections: q,k -> bf16 hi/lo; v -> fp32
    MMArgs mq;
    mq.Ahi[0]=bhi_in;        mq.Alo[0]=blo_in;        mq.Whi[0]=bhi_w;        mq.Wlo[0]=blo_w;        mq.bias[0]=bq; mq.C[0]=nullptr; mq.Chi[0]=qhi; mq.Clo[0]=qlo; mq.alpha[0]=SCALE_QK;
    mq.Ahi[1]=bhi_in+L*DM;   mq.Alo[1]=blo_in+L*DM;   mq.Whi[1]=bhi_w+DM*DM;  mq.Wlo[1]=blo_w+DM*DM;  mq.bias[1]=bk; mq.C[1]=nullptr; mq.Chi[1]=khi; mq.Clo[1]=klo; mq.alpha[1]=SCALE_QK;
    mq.Ahi[2]=bhi_in+2*L*DM; mq.Alo[2]=blo_in+2*L*DM; mq.Whi[2]=bhi_w+2*DM*DM;mq.Wlo[2]=blo_w+2*DM*DM;mq.bias[2]=bv; mq.C[2]=v;       mq.Chi[2]=nullptr; mq.Clo[2]=nullptr; mq.alpha[2]=1.0f;
    hmma_gemm<<<dim3(DM/128, L/128, 3), 256, HG_SMEM>>>(mq);

    hk_max<<<L, 256>>>();

    // rf projections + featurize (HMMA)
    rf_proj_hmma<<<dim3(1, L/128, 16), 256, RF_SMEM>>>();

    // chunked causal linear attention
    chunk_state<<<dim3(NC, NH), 256>>>();
    prefix_scan<<<dim3((MF*DH + MF + 255)/256, NH), 256>>>();
    cudaFuncSetAttribute(chunk_out, cudaFuncAttributeMaxDynamicSharedMemorySize, CO_SMEM_FLOATS * 4);
    chunk_out<<<dim3(NC, NH), 256, CO_SMEM_FLOATS * 4>>>();

    // convert ctx, then output projection
    CV cc;
    cc.src[0]=ctx; cc.hi[0]=bhi_c; cc.lo[0]=blo_c; cc.n[0]=L*DM;
    cc.cnt = 1;
    convert_split<<<dim3((L*DM)/1024, 1), 256>>>(cc);

    MMArgs mo;
    mo.Ahi[0]=bhi_c; mo.Alo[0]=blo_c; mo.Whi[0]=bhi_w+3*DM*DM; mo.Wlo[0]=blo_w+3*DM*DM; mo.bias[0]=bo; mo.C[0]=out; mo.Chi[0]=nullptr; mo.Clo[0]=nullptr; mo.alpha[0]=1.0f;
    mo.Ahi[1]=mo.Ahi[0]; mo.Alo[1]=mo.Alo[0]; mo.Whi[1]=mo.Whi[0]; mo.Wlo[1]=mo.Wlo[0]; mo.bias[1]=bo; mo.C[1]=out; mo.Chi[1]=nullptr; mo.Clo[1]=nullptr; mo.alpha[1]=1.0f;
    mo.Ahi[2]=mo.Ahi[0]; mo.Alo[2]=mo.Alo[0]; mo.Whi[2]=mo.Whi[0]; mo.Wlo[2]=mo.Wlo[0]; mo.bias[2]=bo; mo.C[2]=out; mo.Chi[2]=nullptr; mo.Clo[2]=nullptr; mo.alpha[2]=1.0f;
    hmma_gemm<<<dim3(DM/128, L/128, 1), 256, HG_SMEM>>>(mo);
}

// round 7
// speedup vs baseline: 3.2136x; 1.0537x over previous
#include <cuda_runtime.h>
#include <cuda_bf16.h>
#include <math.h>
#include <stdint.h>

#define L 2048
#define DM 512
#define NH 8
#define DH 64
#define MF 128
#define CHK 64
#define NC (L/CHK)   // 32

#define SCALE_QK 0.2102241038134287f
#define NC_COEF  0.08838834764831845f
#define KEPS 1e-4f
#define DEPS 1e-6f

// ---------------- device scratch ----------------
__device__ float g_v[L*DM];
__device__ float g_pk[NH*L*MF];
__device__ float g_hk[NH*L];
__device__ unsigned g_kstab;
__device__ float g_S[NH*NC*MF*DH];
__device__ float g_z[NH*NC*MF];

__device__ __nv_bfloat16 g_bhi_in[3][L*DM];
__device__ __nv_bfloat16 g_blo_in[3][L*DM];
__device__ __nv_bfloat16 g_bhi_w[4][DM*DM];
__device__ __nv_bfloat16 g_blo_w[4][DM*DM];
__device__ __nv_bfloat16 g_bhi_ctx[L*DM];
__device__ __nv_bfloat16 g_blo_ctx[L*DM];
__device__ __nv_bfloat16 g_qhi[L*DM];
__device__ __nv_bfloat16 g_qlo[L*DM];
__device__ __nv_bfloat16 g_khi[L*DM];
__device__ __nv_bfloat16 g_klo[L*DM];
__device__ __nv_bfloat16 g_rfthi[MF*DH];
__device__ __nv_bfloat16 g_rftlo[MF*DH];
__device__ __nv_bfloat16 g_pqhi[NH*L*MF];
__device__ __nv_bfloat16 g_pqlo[NH*L*MF];
__device__ __nv_bfloat16 g_pkhi[NH*L*MF];
__device__ __nv_bfloat16 g_pklo[NH*L*MF];
__device__ __nv_bfloat16 g_vhi[L*DM];
__device__ __nv_bfloat16 g_vlo[L*DM];
__device__ __nv_bfloat16 g_Shi[NH*NC*MF*DH];
__device__ __nv_bfloat16 g_Slo[NH*NC*MF*DH];

__device__ __forceinline__ unsigned enc_f(float f){
    unsigned u = __float_as_uint(f);
    return (u & 0x80000000u) ? ~u : (u | 0x80000000u);
}
__device__ __forceinline__ float dec_f(unsigned k){
    unsigned u = (k & 0x80000000u) ? (k ^ 0x80000000u) : ~k;
    return __uint_as_float(u);
}

__global__ void reset_kstab(){ g_kstab = 0u; }

__device__ __forceinline__ uint32_t smem_u32(const void* p) {
    uint32_t a;
    asm("{ .reg .u64 t; cvta.to.shared.u64 t, %1; cvt.u32.u64 %0, t; }" : "=r"(a) : "l"(p));
    return a;
}

#define CP_ASYNC16(sa, gp) asm volatile("cp.async.cg.shared.global [%0], [%1], 16;" :: "r"(sa), "l"(gp))
#define CP_COMMIT()        asm volatile("cp.async.commit_group;")
#define CP_WAIT1()         asm volatile("cp.async.wait_group 1;")
#define CP_WAIT0()         asm volatile("cp.async.wait_group 0;")

#define LDSM4(r0,r1,r2,r3,a) \
    asm volatile("ldmatrix.sync.aligned.m8n8.x4.shared.b16 {%0,%1,%2,%3}, [%4];" \
        : "=r"(r0),"=r"(r1),"=r"(r2),"=r"(r3) : "r"(a))
#define LDSM4T(r0,r1,r2,r3,a) \
    asm volatile("ldmatrix.sync.aligned.m8n8.x4.trans.shared.b16 {%0,%1,%2,%3}, [%4];" \
        : "=r"(r0),"=r"(r1),"=r"(r2),"=r"(r3) : "r"(a))

#define MMA16816(d,a,b0,b1) \
    asm volatile("mma.sync.aligned.m16n8k16.row.col.f32.bf16.bf16.f32 " \
        "{%0,%1,%2,%3},{%4,%5,%6,%7},{%8,%9},{%0,%1,%2,%3};" \
        : "+f"((d)[0]),"+f"((d)[1]),"+f"((d)[2]),"+f"((d)[3]) \
        : "r"((a)[0]),"r"((a)[1]),"r"((a)[2]),"r"((a)[3]),"r"(b0),"r"(b1))

__device__ __forceinline__ void split2(float x, float y, __nv_bfloat162& hv, __nv_bfloat162& lv){
    __nv_bfloat16 hx = __float2bfloat16(x);
    __nv_bfloat16 hy = __float2bfloat16(y);
    hv.x = hx; hv.y = hy;
    lv.x = __float2bfloat16(x - __bfloat162float(hx));
    lv.y = __float2bfloat16(y - __bfloat162float(hy));
}

// ---------------- fp32 -> (bf16 hi, bf16 lo) converter ----------------
struct CV { const float* src[8]; __nv_bfloat16* hi[8]; __nv_bfloat16* lo[8]; int n[8]; int cnt; };
__global__ void convert_split(CV cv){
    int t = blockIdx.y;
    if (t >= cv.cnt) return;
    int n = cv.n[t];
    const float* s = cv.src[t];
    __nv_bfloat16* ph = cv.hi[t];
    __nv_bfloat16* pl = cv.lo[t];
    int i0 = blockIdx.x * 1024 + threadIdx.x;
#pragma unroll
    for (int j = 0; j < 4; j++) {
        int i = i0 + j * 256;
        if (i < n) {
            float x = s[i];
            __nv_bfloat16 h = __float2bfloat16(x);
            ph[i] = h;
            pl[i] = __float2bfloat16(x - __bfloat162float(h));
        }
    }
}

__global__ void rf_convert(const float* __restrict__ rf){
    int i = blockIdx.x * 256 + threadIdx.x;
    if (i < MF * DH) {
        int m = i >> 6, d = i & 63;
        float x = rf[(size_t)d * MF + m];
        __nv_bfloat16 h = __float2bfloat16(x);
        g_rfthi[(size_t)m * DH + d] = h;
        g_rftlo[(size_t)m * DH + d] = __float2bfloat16(x - __bfloat162float(h));
    }
}

// ---------------- split-bf16 HMMA GEMM (tile 128x128, BK=32) ----------------
#define PITCH_B 80
#define TILE_BYTES (128*PITCH_B)
#define STAGE_BYTES (4*TILE_BYTES)
#define HG_SMEM (2*STAGE_BYTES)
#define NKC 16

struct MMArgs {
    const __nv_bfloat16* Ahi[3]; const __nv_bfloat16* Alo[3];
    const __nv_bfloat16* Whi[3]; const __nv_bfloat16* Wlo[3];
    const float* bias[3]; float* C[3];
    __nv_bfloat16* Chi[3]; __nv_bfloat16* Clo[3];
    float alpha[3];
};

__global__ __launch_bounds__(256) void hmma_gemm(MMArgs ga)
{
    extern __shared__ char smem[];
    uint32_t sb = smem_u32(smem);
    int tid = threadIdx.x;
    int lane = tid & 31, wid = tid >> 5;
    int warp_m = wid & 1, warp_n = wid >> 1;
    int z = blockIdx.z;
    int m0 = blockIdx.y * 128, n0 = blockIdx.x * 128;

    const __nv_bfloat16* Ahi = ga.Ahi[z] + (size_t)m0 * DM;
    const __nv_bfloat16* Alo = ga.Alo[z] + (size_t)m0 * DM;
    const __nv_bfloat16* Whi = ga.Whi[z] + (size_t)n0 * DM;
    const __nv_bfloat16* Wlo = ga.Wlo[z] + (size_t)n0 * DM;
    const float* bias = ga.bias[z];
    float alpha = ga.alpha[z];

    uint32_t a_off = (uint32_t)(warp_m*64 + (lane & 15)) * PITCH_B + (lane >> 4) * 16;
    uint32_t b_off = (uint32_t)(warp_n*32 + (lane & 7) + (lane >> 4) * 8) * PITCH_B + ((lane >> 3) & 1) * 16;

    float acc[4][4][4];
#pragma unroll
    for (int i = 0; i < 4; i++)
#pragma unroll
        for (int j = 0; j < 4; j++)
#pragma unroll
            for (int r = 0; r < 4; r++) acc[i][j][r] = 0.f;

    {
#pragma unroll
        for (int j = 0; j < 8; j++) {
            int idx = tid + j * 256;
            int tile = idx >> 9;
            int w = idx & 511;
            int r = w >> 2, c = w & 3;
            const __nv_bfloat16* gp =
                (tile == 0) ? (Ahi + (size_t)r * DM + c*8) :
                (tile == 1) ? (Alo + (size_t)r * DM + c*8) :
                (tile == 2) ? (Whi + (size_t)r * DM + c*8) :
                              (Wlo + (size_t)r * DM + c*8);
            uint32_t sp = sb + tile * TILE_BYTES + (uint32_t)r * PITCH_B + c * 16;
            CP_ASYNC16(sp, gp);
        }
        CP_COMMIT();
    }

    for (int kc = 0; kc < NKC; kc++) {
        if (kc + 1 < NKC) {
            int k0 = (kc + 1) * 32;
            uint32_t stb = sb + ((kc + 1) & 1) * STAGE_BYTES;
#pragma unroll
            for (int j = 0; j < 8; j++) {
                int idx = tid + j * 256;
                int tile = idx >> 9;
                int w = idx & 511;
                int r = w >> 2, c = w & 3;
                const __nv_bfloat16* gp =
                    (tile == 0) ? (Ahi + (size_t)r * DM + k0 + c*8) :
                    (tile == 1) ? (Alo + (size_t)r * DM + k0 + c*8) :
                    (tile == 2) ? (Whi + (size_t)r * DM + k0 + c*8) :
                                  (Wlo + (size_t)r * DM + k0 + c*8);
                uint32_t sp = stb + tile * TILE_BYTES + (uint32_t)r * PITCH_B + c * 16;
                CP_ASYNC16(sp, gp);
            }
            CP_COMMIT();
            CP_WAIT1();
        } else {
            CP_WAIT0();
        }
        __syncthreads();

        uint32_t st = sb + (kc & 1) * STAGE_BYTES;
        uint32_t sAhi = st + a_off;
        uint32_t sAlo = st + TILE_BYTES + a_off;
        uint32_t sBhi = st + 2*TILE_BYTES + b_off;
        uint32_t sBlo = st + 3*TILE_BYTES + b_off;

#pragma unroll
        for (int ks = 0; ks < 2; ks++) {
            uint32_t ah[4][4], al[4][4], bh[2][4], bl[2][4];
#pragma unroll
            for (int mi = 0; mi < 4; mi++) {
                LDSM4(ah[mi][0], ah[mi][1], ah[mi][2], ah[mi][3], sAhi + mi*16*PITCH_B + ks*32);
                LDSM4(al[mi][0], al[mi][1], al[mi][2], al[mi][3], sAlo + mi*16*PITCH_B + ks*32);
            }
#pragma unroll
            for (int nb = 0; nb < 2; nb++) {
                LDSM4(bh[nb][0], bh[nb][1], bh[nb][2], bh[nb][3], sBhi + nb*16*PITCH_B + ks*32);
                LDSM4(bl[nb][0], bl[nb][1], bl[nb][2], bl[nb][3], sBlo + nb*16*PITCH_B + ks*32);
            }
#pragma unroll
            for (int mi = 0; mi < 4; mi++)
#pragma unroll
                for (int nb = 0; nb < 2; nb++) {
                    MMA16816(acc[mi][nb*2+0], ah[mi], bh[nb][0], bh[nb][1]);
                    MMA16816(acc[mi][nb*2+1], ah[mi], bh[nb][2], bh[nb][3]);
                    MMA16816(acc[mi][nb*2+0], ah[mi], bl[nb][0], bl[nb][1]);
                    MMA16816(acc[mi][nb*2+1], ah[mi], bl[nb][2], bl[nb][3]);
                    MMA16816(acc[mi][nb*2+0], al[mi], bh[nb][0], bh[nb][1]);
                    MMA16816(acc[mi][nb*2+1], al[mi], bh[nb][2], bh[nb][3]);
                }
        }
        __syncthreads();
    }

    int g = lane >> 2, t = lane & 3;
    __nv_bfloat16* Chi = ga.Chi[z];
    float* C = ga.C[z];
#pragma unroll
    for (int mi = 0; mi < 4; mi++) {
        int row = m0 + warp_m*64 + mi*16 + g;
#pragma unroll
        for (int nj = 0; nj < 4; nj++) {
            int col = n0 + warp_n*32 + nj*8 + t*2;
            float2 bb = *(const float2*)(bias + col);
#pragma unroll
            for (int half = 0; half < 2; half++) {
                int r = row + half*8;
                float ox = alpha * (acc[mi][nj][half*2+0] + bb.x);
                float oy = alpha * (acc[mi][nj][half*2+1] + bb.y);
                if (C) *(float2*)(C + (size_t)r * DM + col) = make_float2(ox, oy);
                if (Chi) {
                    __nv_bfloat162 hv, lv;
                    split2(ox, oy, hv, lv);
                    *(__nv_bfloat162*)(Chi + (size_t)r * DM + col) = hv;
                    *(__nv_bfloat162*)(ga.Clo[z] + (size_t)r * DM + col) = lv;
                }
            }
        }
    }
}

// ---------------- h_k + global max (from bf16 k) ----------------
__global__ void hk_max(){
    int l = blockIdx.x;
    int w = threadIdx.x >> 5, lane = threadIdx.x & 31;
    size_t base = (size_t)l * DM + w * DH;
    float x0 = __bfloat162float(g_khi[base + lane]) + __bfloat162float(g_klo[base + lane]);
    float x1 = __bfloat162float(g_khi[base + lane + 32]) + __bfloat162float(g_klo[base + lane + 32]);
    float ss = x0*x0 + x1*x1;
#pragma unroll
    for (int o = 16; o; o >>= 1) ss += __shfl_xor_sync(0xffffffffu, ss, o);
    __shared__ float wm[8];
    if (lane == 0) { float hv = -0.5f * ss; g_hk[(size_t)w * L + l] = hv; wm[w] = hv; }
    __syncthreads();
    if (threadIdx.x == 0) {
        float mx = wm[0];
#pragma unroll
        for (int i = 1; i < 8; i++) mx = fmaxf(mx, wm[i]);
        atomicMax(&g_kstab, enc_f(mx));
    }
}

// ---------------- rf projection + featurize (HMMA split-bf16) ----------------
#define PITCH2 144
#define TILE2 (128*PITCH2)
#define RF_SMEM (4*TILE2)

__global__ __launch_bounds__(256) void rf_proj_hmma()
{
    extern __shared__ char smem[];
    uint32_t sb = smem_u32(smem);
    int tid = threadIdx.x;
    int lane = tid & 31, wid = tid >> 5;
    int warp_m = wid & 1, warp_n = wid >> 1;
    int z = blockIdx.z;
    int h = z & 7;
    bool isq = z < 8;
    int m0 = blockIdx.y * 128;

    const __nv_bfloat16* Ahi = (isq ? g_qhi : g_khi) + (size_t)m0 * DM + h * DH;
    const __nv_bfloat16* Alo = (isq ? g_qlo : g_klo) + (size_t)m0 * DM + h * DH;

#pragma unroll
    for (int j = 0; j < 16; j++) {
        int idx = tid + j * 256;
        int tile = idx >> 10;
        int w = idx & 1023;
        int r = w >> 3, c = w & 7;
        const __nv_bfloat16* gp =
            (tile == 0) ? (Ahi + (size_t)r * DM + c*8) :
            (tile == 1) ? (Alo + (size_t)r * DM + c*8) :
            (tile == 2) ? (g_rfthi + (size_t)r * DH + c*8) :
                          (g_rftlo + (size_t)r * DH + c*8);
        uint32_t sp = sb + tile * TILE2 + (uint32_t)r * PITCH2 + c * 16;
        CP_ASYNC16(sp, gp);
    }
    CP_COMMIT();
    CP_WAIT0();
    __syncthreads();

    uint32_t a_off = (uint32_t)(warp_m*64 + (lane & 15)) * PITCH2 + (lane >> 4) * 16;
    uint32_t b_off = (uint32_t)(warp_n*32 + (lane & 7) + (lane >> 4) * 8) * PITCH2 + ((lane >> 3) & 1) * 16;
    uint32_t sAhi = sb + a_off;
    uint32_t sAlo = sb + TILE2 + a_off;
    uint32_t sBhi = sb + 2*TILE2 + b_off;
    uint32_t sBlo = sb + 3*TILE2 + b_off;

    float acc[4][4][4];
#pragma unroll
    for (int i = 0; i < 4; i++)
#pragma unroll
        for (int j = 0; j < 4; j++)
#pragma unroll
            for (int r = 0; r < 4; r++) acc[i][j][r] = 0.f;

#pragma unroll
    for (int ks = 0; ks < 4; ks++) {
        uint32_t ah[4][4], al[4][4], bh[2][4], bl[2][4];
#pragma unroll
        for (int mi = 0; mi < 4; mi++) {
            LDSM4(ah[mi][0], ah[mi][1], ah[mi][2], ah[mi][3], sAhi + mi*16*PITCH2 + ks*32);
            LDSM4(al[mi][0], al[mi][1], al[mi][2], al[mi][3], sAlo + mi*16*PITCH2 + ks*32);
        }
#pragma unroll
        for (int nb = 0; nb < 2; nb++) {
            LDSM4(bh[nb][0], bh[nb][1], bh[nb][2], bh[nb][3], sBhi + nb*16*PITCH2 + ks*32);
            LDSM4(bl[nb][0], bl[nb][1], bl[nb][2], bl[nb][3], sBlo + nb*16*PITCH2 + ks*32);
        }
#pragma unroll
        for (int mi = 0; mi < 4; mi++)
#pragma unroll
            for (int nb = 0; nb < 2; nb++) {
                MMA16816(acc[mi][nb*2+0], ah[mi], bh[nb][0], bh[nb][1]);
                MMA16816(acc[mi][nb*2+1], ah[mi], bh[nb][2], bh[nb][3]);
                MMA16816(acc[mi][nb*2+0], ah[mi], bl[nb][0], bl[nb][1]);
                MMA16816(acc[mi][nb*2+1], ah[mi], bl[nb][2], bl[nb][3]);
                MMA16816(acc[mi][nb*2+0], al[mi], bh[nb][0], bh[nb][1]);
                MMA16816(acc[mi][nb*2+1], al[mi], bh[nb][2], bh[nb][3]);
            }
    }

    float kst = isq ? 0.f : dec_f(g_kstab);
    int g = lane >> 2, t = lane & 3;
    __nv_bfloat16* Ph = (isq ? g_pqhi : g_pkhi) + (size_t)h * L * MF;
    __nv_bfloat16* Pl = (isq ? g_pqlo : g_pklo) + (size_t)h * L * MF;
    float* Pf = g_pk + (size_t)h * L * MF;
#pragma unroll
    for (int mi = 0; mi < 4; mi++) {
#pragma unroll
        for (int half = 0; half < 2; half++) {
            int row = m0 + warp_m*64 + mi*16 + g + half*8;
            float off = isq ? 0.f : (g_hk[(size_t)h * L + row] - kst);
#pragma unroll
            for (int nj = 0; nj < 4; nj++) {
                int col = warp_n*32 + nj*8 + t*2;
                float ox = NC_COEF * (__expf(acc[mi][nj][half*2+0] + off) + KEPS);
                float oy = NC_COEF * (__expf(acc[mi][nj][half*2+1] + off) + KEPS);
                __nv_bfloat162 hv, lv;
                split2(ox, oy, hv, lv);
                *(__nv_bfloat162*)(Ph + (size_t)row * MF + col) = hv;
                *(__nv_bfloat162*)(Pl + (size_t)row * MF + col) = lv;
                if (!isq) *(float2*)(Pf + (size_t)row * MF + col) = make_float2(ox, oy);
            }
        }
    }
}

// ---------------- per-(head,chunk) state: S = K'^T V, z = sum k' ----------------
__global__ void chunk_state(){
    __shared__ float Ks[32][128];
    __shared__ float Vs[32][64];
    int c = blockIdx.x, h = blockIdx.y;
    int tid = threadIdx.x;
    int l0 = c * CHK;
    int d = tid & 63, mg = tid >> 6;
    float acc[32];
#pragma unroll
    for (int j = 0; j < 32; j++) acc[j] = 0.f;
    float zacc = 0.f;

    for (int half = 0; half < 2; half++) {
        int lb = l0 + half * 32;
        const float4* srck = (const float4*)(g_pk + ((size_t)h * L + lb) * MF);
        float4* dstk = (float4*)&Ks[0][0];
        for (int i = tid; i < 1024; i += 256) dstk[i] = srck[i];
        for (int i = tid; i < 512; i += 256) {
            int r = i >> 4, c4 = (i & 15) * 4;
            *(float4*)&Vs[r][c4] = *(const float4*)(g_v + (size_t)(lb + r) * DM + h * DH + c4);
        }
        __syncthreads();
        for (int l = 0; l < 32; l++) {
            float vv = Vs[l][d];
#pragma unroll
            for (int jb = 0; jb < 8; jb++) {
                float4 kk = *(const float4*)&Ks[l][mg*32 + jb*4];
                acc[jb*4+0] += kk.x * vv;
                acc[jb*4+1] += kk.y * vv;
                acc[jb*4+2] += kk.z * vv;
                acc[jb*4+3] += kk.w * vv;
            }
        }
        if (tid < 128) {
            float s = 0.f;
            for (int l = 0; l < 32; l++) s += Ks[l][tid];
            zacc += s;
        }
        __syncthreads();
    }
    size_t base = ((size_t)(h * NC + c) * MF) * DH;
#pragma unroll
    for (int j = 0; j < 32; j++) g_S[base + (size_t)(mg*32 + j) * DH + d] = acc[j];
    if (tid < 128) g_z[(size_t)(h * NC + c) * MF + tid] = zacc;
}

// ---------------- exclusive prefix over chunks; S emitted as bf16 hi/lo ----------------
__global__ void prefix_scan(){
    int h = blockIdx.y;
    int idx = blockIdx.x * 256 + threadIdx.x;
    if (idx < MF * DH) {
        const float* p = g_S + (size_t)h * NC * MF * DH + idx;
        __nv_bfloat16* ph = g_Shi + (size_t)h * NC * MF * DH + idx;
        __nv_bfloat16* pl = g_Slo + (size_t)h * NC * MF * DH + idx;
        float prev = 0.f;
#pragma unroll
        for (int c = 0; c < NC; c++) {
            float cur = p[(size_t)c * MF * DH];
            __nv_bfloat16 hh = __float2bfloat16(prev);
            ph[(size_t)c * MF * DH] = hh;
            pl[(size_t)c * MF * DH] = __float2bfloat16(prev - __bfloat162float(hh));
            prev += cur;
        }
    } else if (idx < MF * DH + MF) {
        int m = idx - MF * DH;
        float* p = g_z + (size_t)h * NC * MF + m;
        float prev = 0.f;
#pragma unroll
        for (int c = 0; c < NC; c++) {
            float cur = p[c * MF];
            p[c * MF] = prev;
            prev += cur;
        }
    }
}

// ---------------- chunk_out via HMMA ----------------
// Phase1: A = tril(Q'K'^T) (64x64, K=128). Phase2: O = A@V + Q'@S_prev.
// Denominator: rowsum(tril A) + q'.z_prev.
#define PQ 272
#define PV 144
#define CO_QH 0
#define CO_QL (CO_QH + 64*PQ)
#define CO_KH (CO_QL + 64*PQ)
#define CO_KL (CO_KH + 64*PQ)
#define CO_VH (CO_KL + 64*PQ)
#define CO_VL (CO_VH + 64*PV)
#define CO_SH (CO_VL + 64*PV)
#define CO_SL (CO_SH + 128*PV)
#define CO_AH (CO_SL + 128*PV)
#define CO_AL (CO_AH + 64*PV)
#define CO_ZB (CO_AL + 64*PV)
#define CO_PR (CO_ZB + 512)
#define CO_RS (CO_PR + 64*4*4)
#define CO_TOTAL (CO_RS + 256)

__global__ __launch_bounds__(256) void chunk_out_hmma(){
    extern __shared__ char smc[];
    uint32_t sb = smem_u32(smc);
    int c = blockIdx.x, h = blockIdx.y;
    int tid = threadIdx.x, lane = tid & 31, wid = tid >> 5;
    int warp_m = wid & 1, warp_n = wid >> 1;
    int l0 = c * CHK;

    {
        const __nv_bfloat16* pqh = g_pqhi + ((size_t)h * L + l0) * MF;
        const __nv_bfloat16* pql = g_pqlo + ((size_t)h * L + l0) * MF;
        const __nv_bfloat16* pkh = g_pkhi + ((size_t)h * L + l0) * MF;
        const __nv_bfloat16* pkl = g_pklo + ((size_t)h * L + l0) * MF;
        for (int i = tid; i < 1024; i += 256) {
            int r = i >> 4, cc = i & 15;
            CP_ASYNC16(sb + CO_QH + r*PQ + cc*16, pqh + (size_t)r*MF + cc*8);
            CP_ASYNC16(sb + CO_QL + r*PQ + cc*16, pql + (size_t)r*MF + cc*8);
            CP_ASYNC16(sb + CO_KH + r*PQ + cc*16, pkh + (size_t)r*MF + cc*8);
            CP_ASYNC16(sb + CO_KL + r*PQ + cc*16, pkl + (size_t)r*MF + cc*8);
        }
        for (int i = tid; i < 512; i += 256) {
            int r = i >> 3, cc = i & 7;
            CP_ASYNC16(sb + CO_VH + r*PV + cc*16, g_vhi + (size_t)(l0 + r)*DM + h*DH + cc*8);
            CP_ASYNC16(sb + CO_VL + r*PV + cc*16, g_vlo + (size_t)(l0 + r)*DM + h*DH + cc*8);
        }
        const __nv_bfloat16* sh = g_Shi + (size_t)(h*NC + c)*MF*DH;
        const __nv_bfloat16* sl = g_Slo + (size_t)(h*NC + c)*MF*DH;
        for (int i = tid; i < 1024; i += 256) {
            int r = i >> 3, cc = i & 7;
            CP_ASYNC16(sb + CO_SH + r*PV + cc*16, sh + (size_t)r*DH + cc*8);
            CP_ASYNC16(sb + CO_SL + r*PV + cc*16, sl + (size_t)r*DH + cc*8);
        }
        if (tid < 32) CP_ASYNC16(sb + CO_ZB + tid*16, g_z + (size_t)(h*NC + c)*MF + tid*4);
        CP_COMMIT(); CP_WAIT0();
    }
    __syncthreads();

    uint32_t a_off = (uint32_t)(warp_m*32 + (lane & 15)) * PQ + (lane >> 4) * 16;
    uint32_t b_off = (uint32_t)(warp_n*16 + (lane & 7) + (lane >> 4) * 8) * PQ + ((lane >> 3) & 1) * 16;

    // ---- Phase 1: A = Q' K'^T ----
    float acc[2][2][4];
#pragma unroll
    for (int i = 0; i < 2; i++)
#pragma unroll
        for (int j = 0; j < 2; j++)
#pragma unroll
            for (int r = 0; r < 4; r++) acc[i][j][r] = 0.f;

#pragma unroll
    for (int ks = 0; ks < 8; ks++) {
        uint32_t ah[2][4], al[2][4], bh[4], bl[4];
#pragma unroll
        for (int mi = 0; mi < 2; mi++) {
            LDSM4(ah[mi][0], ah[mi][1], ah[mi][2], ah[mi][3], sb + CO_QH + a_off + mi*16*PQ + ks*32);
            LDSM4(al[mi][0], al[mi][1], al[mi][2], al[mi][3], sb + CO_QL + a_off + mi*16*PQ + ks*32);
        }
        LDSM4(bh[0], bh[1], bh[2], bh[3], sb + CO_KH + b_off + ks*32);
        LDSM4(bl[0], bl[1], bl[2], bl[3], sb + CO_KL + b_off + ks*32);
#pragma unroll
        for (int mi = 0; mi < 2; mi++) {
            MMA16816(acc[mi][0], ah[mi], bh[0], bh[1]);
            MMA16816(acc[mi][1], ah[mi], bh[2], bh[3]);
            MMA16816(acc[mi][0], ah[mi], bl[0], bl[1]);
            MMA16816(acc[mi][1], ah[mi], bl[2], bl[3]);
            MMA16816(acc[mi][0], al[mi], bh[0], bh[1]);
            MMA16816(acc[mi][1], al[mi], bh[2], bh[3]);
        }
    }

    // mask tril, partial row sums, store A hi/lo to smem
    int g = lane >> 2, t = lane & 3;
    float* pr = (float*)(smc + CO_PR);
#pragma unroll
    for (int mi = 0; mi < 2; mi++) {
#pragma unroll
        for (int half = 0; half < 2; half++) {
            int row = warp_m*32 + mi*16 + g + half*8;
            float rsum = 0.f;
#pragma unroll
            for (int nj = 0; nj < 2; nj++) {
                int col = warp_n*16 + nj*8 + t*2;
                float x = (col     <= row) ? acc[mi][nj][half*2+0] : 0.f;
                float y = (col + 1 <= row) ? acc[mi][nj][half*2+1] : 0.f;
                rsum += x + y;
                __nv_bfloat162 hv, lv;
                split2(x, y, hv, lv);
                *(__nv_bfloat162*)(smc + CO_AH + row*PV + col*2) = hv;
                *(__nv_bfloat162*)(smc + CO_AL + row*PV + col*2) = lv;
            }
            rsum += __shfl_xor_sync(0xffffffffu, rsum, 1);
            rsum += __shfl_xor_sync(0xffffffffu, rsum, 2);
            if (t == 0) pr[row*4 + warp_n] = rsum;
        }
    }
    __syncthreads();

    // denominators (threads 0..63)
    if (tid < 64) {
        float s = pr[tid*4+0] + pr[tid*4+1] + pr[tid*4+2] + pr[tid*4+3];
        const float* zf = (const float*)(smc + CO_ZB);
#pragma unroll 8
        for (int m2 = 0; m2 < 64; m2++) {
            __nv_bfloat162 qh2 = *(const __nv_bfloat162*)(smc + CO_QH + tid*PQ + m2*4);
            __nv_bfloat162 ql2 = *(const __nv_bfloat162*)(smc + CO_QL + tid*PQ + m2*4);
            float2 z2 = *(const float2*)(zf + m2*2);
            s += (__bfloat162float(qh2.x) + __bfloat162float(ql2.x)) * z2.x
               + (__bfloat162float(qh2.y) + __bfloat162float(ql2.y)) * z2.y;
        }
        ((float*)(smc + CO_RS))[tid] = s + DEPS;
    }

    // ---- Phase 2: O = A@V + Q'@S_prev ----
    float o[2][2][4];
#pragma unroll
    for (int i = 0; i < 2; i++)
#pragma unroll
        for (int j = 0; j < 2; j++)
#pragma unroll
            for (int r = 0; r < 4; r++) o[i][j][r] = 0.f;

    uint32_t a2_off = (uint32_t)(warp_m*32 + (lane & 15)) * PV + (lane >> 4) * 16;
    uint32_t bt_off = (uint32_t)(lane & 15) * PV + (warp_n*16 + (lane >> 4) * 8) * 2;

#pragma unroll
    for (int ks = 0; ks < 4; ks++) {
        uint32_t ah[2][4], al[2][4], bh[4], bl[4];
#pragma unroll
        for (int mi = 0; mi < 2; mi++) {
            LDSM4(ah[mi][0], ah[mi][1], ah[mi][2], ah[mi][3], sb + CO_AH + a2_off + mi*16*PV + ks*32);
            LDSM4(al[mi][0], al[mi][1], al[mi][2], al[mi][3], sb + CO_AL + a2_off + mi*16*PV + ks*32);
        }
        LDSM4T(bh[0], bh[1], bh[2], bh[3], sb + CO_VH + bt_off + ks*16*PV);
        LDSM4T(bl[0], bl[1], bl[2], bl[3], sb + CO_VL + bt_off + ks*16*PV);
#pragma unroll
        for (int mi = 0; mi < 2; mi++) {
            MMA16816(o[mi][0], ah[mi], bh[0], bh[1]);
            MMA16816(o[mi][1], ah[mi], bh[2], bh[3]);
            MMA16816(o[mi][0], ah[mi], bl[0], bl[1]);
            MMA16816(o[mi][1], ah[mi], bl[2], bl[3]);
            MMA16816(o[mi][0], al[mi], bh[0], bh[1]);
            MMA16816(o[mi][1], al[mi], bh[2], bh[3]);
        }
    }
#pragma unroll
    for (int ks = 0; ks < 8; ks++) {
        uint32_t ah[2][4], al[2][4], bh[4], bl[4];
#pragma unroll
        for (int mi = 0; mi < 2; mi++) {
            LDSM4(ah[mi][0], ah[mi][1], ah[mi][2], ah[mi][3], sb + CO_QH + a_off + mi*16*PQ + ks*32);
            LDSM4(al[mi][0], al[mi][1], al[mi][2], al[mi][3], sb + CO_QL + a_off + mi*16*PQ + ks*32);
        }
        LDSM4T(bh[0], bh[1], bh[2], bh[3], sb + CO_SH + bt_off + ks*16*PV);
        LDSM4T(bl[0], bl[1], bl[2], bl[3], sb + CO_SL + bt_off + ks*16*PV);
#pragma unroll
        for (int mi = 0; mi < 2; mi++) {
            MMA16816(o[mi][0], ah[mi], bh[0], bh[1]);
            MMA16816(o[mi][1], ah[mi], bh[2], bh[3]);
            MMA16816(o[mi][0], ah[mi], bl[0], bl[1]);
            MMA16816(o[mi][1], ah[mi], bl[2], bl[3]);
            MMA16816(o[mi][0], al[mi], bh[0], bh[1]);
            MMA16816(o[mi][1], al[mi], bh[2], bh[3]);
        }
    }
    __syncthreads();

    // epilogue: divide by denominator, write ctx as bf16 hi/lo
    const float* rs = (const float*)(smc + CO_RS);
#pragma unroll
    for (int mi = 0; mi < 2; mi++) {
#pragma unroll
        for (int half = 0; half < 2; half++) {
            int row = warp_m*32 + mi*16 + g + half*8;
            float inv = 1.0f / rs[row];
#pragma unroll
            for (int nj = 0; nj < 2; nj++) {
                int col = warp_n*16 + nj*8 + t*2;
                float ox = o[mi][nj][half*2+0] * inv;
                float oy = o[mi][nj][half*2+1] * inv;
                __nv_bfloat162 hv, lv;
                split2(ox, oy, hv, lv);
                size_t off = (size_t)(l0 + row) * DM + h*DH + col;
                *(__nv_bfloat162*)(g_bhi_ctx + off) = hv;
                *(__nv_bfloat162*)(g_blo_ctx + off) = lv;
            }
        }
    }
}

// ---------------- launcher ----------------
extern "C" void kernel_launch(void* const* d_in, const int* in_sizes, int n_in,
                              void* d_out, int out_size)
{
    const float* query = (const float*)d_in[0];
    const float* key_i = (const float*)d_in[1];
    const float* value = (const float*)d_in[2];
    const float* Wq = (const float*)d_in[3];
    const float* bq = (const float*)d_in[4];
    const float* Wk = (const float*)d_in[5];
    const float* bk = (const float*)d_in[6];
    const float* Wv = (const float*)d_in[7];
    const float* bv = (const float*)d_in[8];
    const float* Wo = (const float*)d_in[9];
    const float* bo = (const float*)d_in[10];
    const float* rf = (const float*)d_in[11];
    float* out = (float*)d_out;

    void* p;
    cudaGetSymbolAddress(&p, g_v);       float* v = (float*)p;
    cudaGetSymbolAddress(&p, g_bhi_in);  __nv_bfloat16* bhi_in = (__nv_bfloat16*)p;
    cudaGetSymbolAddress(&p, g_blo_in);  __nv_bfloat16* blo_in = (__nv_bfloat16*)p;
    cudaGetSymbolAddress(&p, g_bhi_w);   __nv_bfloat16* bhi_w  = (__nv_bfloat16*)p;
    cudaGetSymbolAddress(&p, g_blo_w);   __nv_bfloat16* blo_w  = (__nv_bfloat16*)p;
    cudaGetSymbolAddress(&p, g_bhi_ctx); __nv_bfloat16* bhi_c  = (__nv_bfloat16*)p;
    cudaGetSymbolAddress(&p, g_blo_ctx); __nv_bfloat16* blo_c  = (__nv_bfloat16*)p;
    cudaGetSymbolAddress(&p, g_qhi);     __nv_bfloat16* qhi    = (__nv_bfloat16*)p;
    cudaGetSymbolAddress(&p, g_qlo);     __nv_bfloat16* qlo    = (__nv_bfloat16*)p;
    cudaGetSymbolAddress(&p, g_khi);     __nv_bfloat16* khi    = (__nv_bfloat16*)p;
    cudaGetSymbolAddress(&p, g_klo);     __nv_bfloat16* klo    = (__nv_bfloat16*)p;
    cudaGetSymbolAddress(&p, g_vhi);     __nv_bfloat16* vhi    = (__nv_bfloat16*)p;
    cudaGetSymbolAddress(&p, g_vlo);     __nv_bfloat16* vlo    = (__nv_bfloat16*)p;

    reset_kstab<<<1, 1>>>();

    CV cv;
    cv.src[0]=query; cv.hi[0]=bhi_in;          cv.lo[0]=blo_in;          cv.n[0]=L*DM;
    cv.src[1]=key_i; cv.hi[1]=bhi_in+L*DM;     cv.lo[1]=blo_in+L*DM;     cv.n[1]=L*DM;
    cv.src[2]=value; cv.hi[2]=bhi_in+2*L*DM;   cv.lo[2]=blo_in+2*L*DM;   cv.n[2]=L*DM;
    cv.src[3]=Wq;    cv.hi[3]=bhi_w;           cv.lo[3]=blo_w;           cv.n[3]=DM*DM;
    cv.src[4]=Wk;    cv.hi[4]=bhi_w+DM*DM;     cv.lo[4]=blo_w+DM*DM;     cv.n[4]=DM*DM;
    cv.src[5]=Wv;    cv.hi[5]=bhi_w+2*DM*DM;   cv.lo[5]=blo_w+2*DM*DM;   cv.n[5]=DM*DM;
    cv.src[6]=Wo;    cv.hi[6]=bhi_w+3*DM*DM;   cv.lo[6]=blo_w+3*DM*DM;   cv.n[6]=DM*DM;
    cv.cnt = 7;
    convert_split<<<dim3((L*DM)/1024, 7), 256>>>(cv);
    rf_convert<<<(MF*DH + 255)/256, 256>>>(rf);

    cudaFuncSetAttribute(hmma_gemm, cudaFuncAttributeMaxDynamicSharedMemorySize, HG_SMEM);
    cudaFuncSetAttribute(rf_proj_hmma, cudaFuncAttributeMaxDynamicSharedMemorySize, RF_SMEM);
    cudaFuncSetAttribute(chunk_out_hmma, cudaFuncAttributeMaxDynamicSharedMemorySize, CO_TOTAL);

    // QKV projections: q,k -> hi/lo; v -> fp32 + hi/lo
    MMArgs mq;
    mq.Ahi[0]=bhi_in;        mq.Alo[0]=blo_in;        mq.Whi[0]=bhi_w;        mq.Wlo[0]=blo_w;        mq.bias[0]=bq; mq.C[0]=nullptr; mq.Chi[0]=qhi; mq.Clo[0]=qlo; mq.alpha[0]=SCALE_QK;
    mq.Ahi[1]=bhi_in+L*DM;   mq.Alo[1]=blo_in+L*DM;   mq.Whi[1]=bhi_w+DM*DM;  mq.Wlo[1]=blo_w+DM*DM;  mq.bias[1]=bk; mq.C[1]=nullptr; mq.Chi[1]=khi; mq.Clo[1]=klo; mq.alpha[1]=SCALE_QK;
    mq.Ahi[2]=bhi_in+2*L*DM; mq.Alo[2]=blo_in+2*L*DM; mq.Whi[2]=bhi_w+2*DM*DM;mq.Wlo[2]=blo_w+2*DM*DM;mq.bias[2]=bv; mq.C[2]=v;       mq.Chi[2]=vhi; mq.Clo[2]=vlo; mq.alpha[2]=1.0f;
    hmma_gemm<<<dim3(DM/128, L/128, 3), 256, HG_SMEM>>>(mq);

    hk_max<<<L, 256>>>();
    rf_proj_hmma<<<dim3(1, L/128, 16), 256, RF_SMEM>>>();

    chunk_state<<<dim3(NC, NH), 256>>>();
    prefix_scan<<<dim3((MF*DH + MF + 255)/256, NH), 256>>>();
    chunk_out_hmma<<<dim3(NC, NH), 256, CO_TOTAL>>>();

    // output projection (reads ctx hi/lo written by chunk_out)
    MMArgs mo;
    mo.Ahi[0]=bhi_c; mo.Alo[0]=blo_c; mo.Whi[0]=bhi_w+3*DM*DM; mo.Wlo[0]=blo_w+3*DM*DM; mo.bias[0]=bo; mo.C[0]=out; mo.Chi[0]=nullptr; mo.Clo[0]=nullptr; mo.alpha[0]=1.0f;
    mo.Ahi[1]=mo.Ahi[0]; mo.Alo[1]=mo.Alo[0]; mo.Whi[1]=mo.Whi[0]; mo.Wlo[1]=mo.Wlo[0]; mo.bias[1]=bo; mo.C[1]=out; mo.Chi[1]=nullptr; mo.Clo[1]=nullptr; mo.alpha[1]=1.0f;
    mo.Ahi[2]=mo.Ahi[0]; mo.Alo[2]=mo.Alo[0]; mo.Whi[2]=mo.Whi[0]; mo.Wlo[2]=mo.Wlo[0]; mo.bias[2]=bo; mo.C[2]=out; mo.Chi[2]=nullptr; mo.Clo[2]=nullptr; mo.alpha[2]=1.0f;
    hmma_gemm<<<dim3(DM/128, L/128, 1), 256, HG_SMEM>>>(mo);
}

// round 8
// speedup vs baseline: 4.1026x; 1.2766x over previous
#include <cuda_runtime.h>
#include <cuda_bf16.h>
#include <math.h>
#include <stdint.h>

#define L 2048
#define DM 512
#define NH 8
#define DH 64
#define MF 128
#define CHK 64
#define NC (L/CHK)   // 32

#define SCALE_QK 0.2102241038134287f
#define NC_COEF  0.08838834764831845f
#define KEPS 1e-4f
#define DEPS 1e-6f

// ---------------- device scratch ----------------
__device__ float g_hk[NH*L];
__device__ unsigned g_kstab;
__device__ float g_S[NH*NC*MF*DH];
__device__ float g_z[NH*NC*MF];

__device__ __nv_bfloat16 g_bhi_in[3][L*DM];
__device__ __nv_bfloat16 g_blo_in[3][L*DM];
__device__ __nv_bfloat16 g_bhi_w[4][DM*DM];
__device__ __nv_bfloat16 g_blo_w[4][DM*DM];
__device__ __nv_bfloat16 g_bhi_ctx[L*DM];
__device__ __nv_bfloat16 g_blo_ctx[L*DM];
__device__ __nv_bfloat16 g_qhi[L*DM];
__device__ __nv_bfloat16 g_qlo[L*DM];
__device__ __nv_bfloat16 g_khi[L*DM];
__device__ __nv_bfloat16 g_klo[L*DM];
__device__ __nv_bfloat16 g_rfthi[MF*DH];
__device__ __nv_bfloat16 g_rftlo[MF*DH];
__device__ __nv_bfloat16 g_pqhi[NH*L*MF];
__device__ __nv_bfloat16 g_pqlo[NH*L*MF];
__device__ __nv_bfloat16 g_pkhi[NH*L*MF];
__device__ __nv_bfloat16 g_pklo[NH*L*MF];
__device__ __nv_bfloat16 g_vhi[L*DM];
__device__ __nv_bfloat16 g_vlo[L*DM];
__device__ __nv_bfloat16 g_Shi[NH*NC*MF*DH];
__device__ __nv_bfloat16 g_Slo[NH*NC*MF*DH];

__device__ __forceinline__ unsigned enc_f(float f){
    unsigned u = __float_as_uint(f);
    return (u & 0x80000000u) ? ~u : (u | 0x80000000u);
}
__device__ __forceinline__ float dec_f(unsigned k){
    unsigned u = (k & 0x80000000u) ? (k ^ 0x80000000u) : ~k;
    return __uint_as_float(u);
}

__global__ void reset_kstab(){ g_kstab = 0u; }

__device__ __forceinline__ uint32_t smem_u32(const void* p) {
    uint32_t a;
    asm("{ .reg .u64 t; cvta.to.shared.u64 t, %1; cvt.u32.u64 %0, t; }" : "=r"(a) : "l"(p));
    return a;
}

#define CP_ASYNC16(sa, gp) asm volatile("cp.async.cg.shared.global [%0], [%1], 16;" :: "r"(sa), "l"(gp))
#define CP_COMMIT()        asm volatile("cp.async.commit_group;")
#define CP_WAIT1()         asm volatile("cp.async.wait_group 1;")
#define CP_WAIT0()         asm volatile("cp.async.wait_group 0;")

#define LDSM4(r0,r1,r2,r3,a) \
    asm volatile("ldmatrix.sync.aligned.m8n8.x4.shared.b16 {%0,%1,%2,%3}, [%4];" \
        : "=r"(r0),"=r"(r1),"=r"(r2),"=r"(r3) : "r"(a))
#define LDSM4T(r0,r1,r2,r3,a) \
    asm volatile("ldmatrix.sync.aligned.m8n8.x4.trans.shared.b16 {%0,%1,%2,%3}, [%4];" \
        : "=r"(r0),"=r"(r1),"=r"(r2),"=r"(r3) : "r"(a))

#define MMA16816(d,a,b0,b1) \
    asm volatile("mma.sync.aligned.m16n8k16.row.col.f32.bf16.bf16.f32 " \
        "{%0,%1,%2,%3},{%4,%5,%6,%7},{%8,%9},{%0,%1,%2,%3};" \
        : "+f"((d)[0]),"+f"((d)[1]),"+f"((d)[2]),"+f"((d)[3]) \
        : "r"((a)[0]),"r"((a)[1]),"r"((a)[2]),"r"((a)[3]),"r"(b0),"r"(b1))

__device__ __forceinline__ void split2(float x, float y, __nv_bfloat162& hv, __nv_bfloat162& lv){
    __nv_bfloat16 hx = __float2bfloat16(x);
    __nv_bfloat16 hy = __float2bfloat16(y);
    hv.x = hx; hv.y = hy;
    lv.x = __float2bfloat16(x - __bfloat162float(hx));
    lv.y = __float2bfloat16(y - __bfloat162float(hy));
}

// ---------------- fp32 -> (bf16 hi, bf16 lo) converter ----------------
struct CV { const float* src[8]; __nv_bfloat16* hi[8]; __nv_bfloat16* lo[8]; int n[8]; int cnt; };
__global__ void convert_split(CV cv){
    int t = blockIdx.y;
    if (t >= cv.cnt) return;
    int n = cv.n[t];
    const float* s = cv.src[t];
    __nv_bfloat16* ph = cv.hi[t];
    __nv_bfloat16* pl = cv.lo[t];
    int i0 = blockIdx.x * 1024 + threadIdx.x;
#pragma unroll
    for (int j = 0; j < 4; j++) {
        int i = i0 + j * 256;
        if (i < n) {
            float x = s[i];
            __nv_bfloat16 h = __float2bfloat16(x);
            ph[i] = h;
            pl[i] = __float2bfloat16(x - __bfloat162float(h));
        }
    }
}

__global__ void rf_convert(const float* __restrict__ rf){
    int i = blockIdx.x * 256 + threadIdx.x;
    if (i < MF * DH) {
        int m = i >> 6, d = i & 63;
        float x = rf[(size_t)d * MF + m];
        __nv_bfloat16 h = __float2bfloat16(x);
        g_rfthi[(size_t)m * DH + d] = h;
        g_rftlo[(size_t)m * DH + d] = __float2bfloat16(x - __bfloat162float(h));
    }
}

// ---------------- split-bf16 HMMA GEMM (tile 64x128, BK=32, 2 CTAs/SM) ----------------
#define PITCH_B 80
#define A_TILE (64*PITCH_B)          // 5120
#define B_TILE (128*PITCH_B)         // 10240
#define STAGE_BYTES (2*A_TILE + 2*B_TILE)  // 30720
#define HG_SMEM (2*STAGE_BYTES)      // 61440
#define NKC 16

struct MMArgs {
    const __nv_bfloat16* Ahi[3]; const __nv_bfloat16* Alo[3];
    const __nv_bfloat16* Whi[3]; const __nv_bfloat16* Wlo[3];
    const float* bias[3]; float* C[3];
    __nv_bfloat16* Chi[3]; __nv_bfloat16* Clo[3];
    float alpha[3];
};

__global__ __launch_bounds__(256, 2) void hmma_gemm(MMArgs ga)
{
    extern __shared__ char smem[];
    uint32_t sb = smem_u32(smem);
    int tid = threadIdx.x;
    int lane = tid & 31, wid = tid >> 5;
    int warp_m = wid & 1, warp_n = wid >> 1;      // 2M x 4N, warp tile 32x32
    int z = blockIdx.z;
    int m0 = blockIdx.y * 64, n0 = blockIdx.x * 128;

    const __nv_bfloat16* Ahi = ga.Ahi[z] + (size_t)m0 * DM;
    const __nv_bfloat16* Alo = ga.Alo[z] + (size_t)m0 * DM;
    const __nv_bfloat16* Whi = ga.Whi[z] + (size_t)n0 * DM;
    const __nv_bfloat16* Wlo = ga.Wlo[z] + (size_t)n0 * DM;
    const float* bias = ga.bias[z];
    float alpha = ga.alpha[z];

    uint32_t a_off = (uint32_t)(warp_m*32 + (lane & 15)) * PITCH_B + (lane >> 4) * 16;
    uint32_t b_off = (uint32_t)(warp_n*32 + (lane & 7) + (lane >> 4) * 8) * PITCH_B + ((lane >> 3) & 1) * 16;

    float acc[2][4][4];
#pragma unroll
    for (int i = 0; i < 2; i++)
#pragma unroll
        for (int j = 0; j < 4; j++)
#pragma unroll
            for (int r = 0; r < 4; r++) acc[i][j][r] = 0.f;

    // prologue stage 0
    {
#pragma unroll
        for (int j = 0; j < 6; j++) {
            int idx = tid + j * 256;
            const __nv_bfloat16* gp;
            uint32_t sp;
            if (idx < 512) {
                int t2 = idx >> 8;
                int w = idx & 255;
                int r = w >> 2, cc = w & 3;
                gp = (t2 ? Alo : Ahi) + (size_t)r * DM + cc*8;
                sp = sb + t2*A_TILE + (uint32_t)r * PITCH_B + cc*16;
            } else {
                int w = idx - 512;
                int t2 = w >> 9;
                w &= 511;
                int r = w >> 2, cc = w & 3;
                gp = (t2 ? Wlo : Whi) + (size_t)r * DM + cc*8;
                sp = sb + 2*A_TILE + t2*B_TILE + (uint32_t)r * PITCH_B + cc*16;
            }
            CP_ASYNC16(sp, gp);
        }
        CP_COMMIT();
    }

    for (int kc = 0; kc < NKC; kc++) {
        if (kc + 1 < NKC) {
            int k0 = (kc + 1) * 32;
            uint32_t stb = sb + ((kc + 1) & 1) * STAGE_BYTES;
#pragma unroll
            for (int j = 0; j < 6; j++) {
                int idx = tid + j * 256;
                const __nv_bfloat16* gp;
                uint32_t sp;
                if (idx < 512) {
                    int t2 = idx >> 8;
                    int w = idx & 255;
                    int r = w >> 2, cc = w & 3;
                    gp = (t2 ? Alo : Ahi) + (size_t)r * DM + k0 + cc*8;
                    sp = stb + t2*A_TILE + (uint32_t)r * PITCH_B + cc*16;
                } else {
                    int w = idx - 512;
                    int t2 = w >> 9;
                    w &= 511;
                    int r = w >> 2, cc = w & 3;
                    gp = (t2 ? Wlo : Whi) + (size_t)r * DM + k0 + cc*8;
                    sp = stb + 2*A_TILE + t2*B_TILE + (uint32_t)r * PITCH_B + cc*16;
                }
                CP_ASYNC16(sp, gp);
            }
            CP_COMMIT();
            CP_WAIT1();
        } else {
            CP_WAIT0();
        }
        __syncthreads();

        uint32_t st = sb + (kc & 1) * STAGE_BYTES;
        uint32_t sAhi = st + a_off;
        uint32_t sAlo = st + A_TILE + a_off;
        uint32_t sBhi = st + 2*A_TILE + b_off;
        uint32_t sBlo = st + 2*A_TILE + B_TILE + b_off;

#pragma unroll
        for (int ks = 0; ks < 2; ks++) {
            uint32_t ah[2][4], al[2][4], bh[2][4], bl[2][4];
#pragma unroll
            for (int mi = 0; mi < 2; mi++) {
                LDSM4(ah[mi][0], ah[mi][1], ah[mi][2], ah[mi][3], sAhi + mi*16*PITCH_B + ks*32);
                LDSM4(al[mi][0], al[mi][1], al[mi][2], al[mi][3], sAlo + mi*16*PITCH_B + ks*32);
            }
#pragma unroll
            for (int nb = 0; nb < 2; nb++) {
                LDSM4(bh[nb][0], bh[nb][1], bh[nb][2], bh[nb][3], sBhi + nb*16*PITCH_B + ks*32);
                LDSM4(bl[nb][0], bl[nb][1], bl[nb][2], bl[nb][3], sBlo + nb*16*PITCH_B + ks*32);
            }
#pragma unroll
            for (int mi = 0; mi < 2; mi++)
#pragma unroll
                for (int nb = 0; nb < 2; nb++) {
                    MMA16816(acc[mi][nb*2+0], ah[mi], bh[nb][0], bh[nb][1]);
                    MMA16816(acc[mi][nb*2+1], ah[mi], bh[nb][2], bh[nb][3]);
                    MMA16816(acc[mi][nb*2+0], ah[mi], bl[nb][0], bl[nb][1]);
                    MMA16816(acc[mi][nb*2+1], ah[mi], bl[nb][2], bl[nb][3]);
                    MMA16816(acc[mi][nb*2+0], al[mi], bh[nb][0], bh[nb][1]);
                    MMA16816(acc[mi][nb*2+1], al[mi], bh[nb][2], bh[nb][3]);
                }
        }
        __syncthreads();
    }

    int g = lane >> 2, t = lane & 3;
    __nv_bfloat16* Chi = ga.Chi[z];
    float* C = ga.C[z];
#pragma unroll
    for (int mi = 0; mi < 2; mi++) {
        int row = m0 + warp_m*32 + mi*16 + g;
#pragma unroll
        for (int nj = 0; nj < 4; nj++) {
            int col = n0 + warp_n*32 + nj*8 + t*2;
            float2 bb = *(const float2*)(bias + col);
#pragma unroll
            for (int half = 0; half < 2; half++) {
                int r = row + half*8;
                float ox = alpha * (acc[mi][nj][half*2+0] + bb.x);
                float oy = alpha * (acc[mi][nj][half*2+1] + bb.y);
                if (C) *(float2*)(C + (size_t)r * DM + col) = make_float2(ox, oy);
                if (Chi) {
                    __nv_bfloat162 hv, lv;
                    split2(ox, oy, hv, lv);
                    *(__nv_bfloat162*)(Chi + (size_t)r * DM + col) = hv;
                    *(__nv_bfloat162*)(ga.Clo[z] + (size_t)r * DM + col) = lv;
                }
            }
        }
    }
}

// ---------------- h_k + global max (from bf16 k) ----------------
__global__ void hk_max(){
    int l = blockIdx.x;
    int w = threadIdx.x >> 5, lane = threadIdx.x & 31;
    size_t base = (size_t)l * DM + w * DH;
    float x0 = __bfloat162float(g_khi[base + lane]) + __bfloat162float(g_klo[base + lane]);
    float x1 = __bfloat162float(g_khi[base + lane + 32]) + __bfloat162float(g_klo[base + lane + 32]);
    float ss = x0*x0 + x1*x1;
#pragma unroll
    for (int o = 16; o; o >>= 1) ss += __shfl_xor_sync(0xffffffffu, ss, o);
    __shared__ float wm[8];
    if (lane == 0) { float hv = -0.5f * ss; g_hk[(size_t)w * L + l] = hv; wm[w] = hv; }
    __syncthreads();
    if (threadIdx.x == 0) {
        float mx = wm[0];
#pragma unroll
        for (int i = 1; i < 8; i++) mx = fmaxf(mx, wm[i]);
        atomicMax(&g_kstab, enc_f(mx));
    }
}

// ---------------- rf projection + featurize (HMMA split-bf16) ----------------
#define PITCH2 144
#define TILE2 (128*PITCH2)
#define RF_SMEM (4*TILE2)

__global__ __launch_bounds__(256) void rf_proj_hmma()
{
    extern __shared__ char smem[];
    uint32_t sb = smem_u32(smem);
    int tid = threadIdx.x;
    int lane = tid & 31, wid = tid >> 5;
    int warp_m = wid & 1, warp_n = wid >> 1;
    int z = blockIdx.z;
    int h = z & 7;
    bool isq = z < 8;
    int m0 = blockIdx.y * 128;

    const __nv_bfloat16* Ahi = (isq ? g_qhi : g_khi) + (size_t)m0 * DM + h * DH;
    const __nv_bfloat16* Alo = (isq ? g_qlo : g_klo) + (size_t)m0 * DM + h * DH;

#pragma unroll
    for (int j = 0; j < 16; j++) {
        int idx = tid + j * 256;
        int tile = idx >> 10;
        int w = idx & 1023;
        int r = w >> 3, c = w & 7;
        const __nv_bfloat16* gp =
            (tile == 0) ? (Ahi + (size_t)r * DM + c*8) :
            (tile == 1) ? (Alo + (size_t)r * DM + c*8) :
            (tile == 2) ? (g_rfthi + (size_t)r * DH + c*8) :
                          (g_rftlo + (size_t)r * DH + c*8);
        uint32_t sp = sb + tile * TILE2 + (uint32_t)r * PITCH2 + c * 16;
        CP_ASYNC16(sp, gp);
    }
    CP_COMMIT();
    CP_WAIT0();
    __syncthreads();

    uint32_t a_off = (uint32_t)(warp_m*64 + (lane & 15)) * PITCH2 + (lane >> 4) * 16;
    uint32_t b_off = (uint32_t)(warp_n*32 + (lane & 7) + (lane >> 4) * 8) * PITCH2 + ((lane >> 3) & 1) * 16;
    uint32_t sAhi = sb + a_off;
    uint32_t sAlo = sb + TILE2 + a_off;
    uint32_t sBhi = sb + 2*TILE2 + b_off;
    uint32_t sBlo = sb + 3*TILE2 + b_off;

    float acc[4][4][4];
#pragma unroll
    for (int i = 0; i < 4; i++)
#pragma unroll
        for (int j = 0; j < 4; j++)
#pragma unroll
            for (int r = 0; r < 4; r++) acc[i][j][r] = 0.f;

#pragma unroll
    for (int ks = 0; ks < 4; ks++) {
        uint32_t ah[4][4], al[4][4], bh[2][4], bl[2][4];
#pragma unroll
        for (int mi = 0; mi < 4; mi++) {
            LDSM4(ah[mi][0], ah[mi][1], ah[mi][2], ah[mi][3], sAhi + mi*16*PITCH2 + ks*32);
            LDSM4(al[mi][0], al[mi][1], al[mi][2], al[mi][3], sAlo + mi*16*PITCH2 + ks*32);
        }
#pragma unroll
        for (int nb = 0; nb < 2; nb++) {
            LDSM4(bh[nb][0], bh[nb][1], bh[nb][2], bh[nb][3], sBhi + nb*16*PITCH2 + ks*32);
            LDSM4(bl[nb][0], bl[nb][1], bl[nb][2], bl[nb][3], sBlo + nb*16*PITCH2 + ks*32);
        }
#pragma unroll
        for (int mi = 0; mi < 4; mi++)
#pragma unroll
            for (int nb = 0; nb < 2; nb++) {
                MMA16816(acc[mi][nb*2+0], ah[mi], bh[nb][0], bh[nb][1]);
                MMA16816(acc[mi][nb*2+1], ah[mi], bh[nb][2], bh[nb][3]);
                MMA16816(acc[mi][nb*2+0], ah[mi], bl[nb][0], bl[nb][1]);
                MMA16816(acc[mi][nb*2+1], ah[mi], bl[nb][2], bl[nb][3]);
                MMA16816(acc[mi][nb*2+0], al[mi], bh[nb][0], bh[nb][1]);
                MMA16816(acc[mi][nb*2+1], al[mi], bh[nb][2], bh[nb][3]);
            }
    }

    float kst = isq ? 0.f : dec_f(g_kstab);
    int g = lane >> 2, t = lane & 3;
    __nv_bfloat16* Ph = (isq ? g_pqhi : g_pkhi) + (size_t)h * L * MF;
    __nv_bfloat16* Pl = (isq ? g_pqlo : g_pklo) + (size_t)h * L * MF;
#pragma unroll
    for (int mi = 0; mi < 4; mi++) {
#pragma unroll
        for (int half = 0; half < 2; half++) {
            int row = m0 + warp_m*64 + mi*16 + g + half*8;
            float off = isq ? 0.f : (g_hk[(size_t)h * L + row] - kst);
#pragma unroll
            for (int nj = 0; nj < 4; nj++) {
                int col = warp_n*32 + nj*8 + t*2;
                float ox = NC_COEF * (__expf(acc[mi][nj][half*2+0] + off) + KEPS);
                float oy = NC_COEF * (__expf(acc[mi][nj][half*2+1] + off) + KEPS);
                __nv_bfloat162 hv, lv;
                split2(ox, oy, hv, lv);
                *(__nv_bfloat162*)(Ph + (size_t)row * MF + col) = hv;
                *(__nv_bfloat162*)(Pl + (size_t)row * MF + col) = lv;
            }
        }
    }
}

// ---------------- chunk_state via HMMA ----------------
// S_ext[128m, 96] = K'^T[128m, 64l] @ V_ext[64l, 96]; col 64 of V_ext = 1 -> z.
#define CSP_K 272
#define CSP_V 208
#define CS_KH 0
#define CS_KL (CS_KH + 64*CSP_K)
#define CS_VH (CS_KL + 64*CSP_K)
#define CS_VL (CS_VH + 64*CSP_V)
#define CS_TOTAL (CS_VL + 64*CSP_V)

__global__ __launch_bounds__(256) void chunk_state_hmma(){
    extern __shared__ char smc[];
    uint32_t sb = smem_u32(smc);
    int c = blockIdx.x, h = blockIdx.y;
    int tid = threadIdx.x, lane = tid & 31, wid = tid >> 5;
    int warp_m = wid >> 1, warp_n = wid & 1;   // 4M x 2N, warp tile 32m x 48n
    int l0 = c * CHK;

    const __nv_bfloat16* kh = g_pkhi + ((size_t)h * L + l0) * MF;
    const __nv_bfloat16* kl = g_pklo + ((size_t)h * L + l0) * MF;
    for (int i = tid; i < 1024; i += 256) {
        int r = i >> 4, cc = i & 15;
        CP_ASYNC16(sb + CS_KH + (uint32_t)r*CSP_K + cc*16, kh + (size_t)r*MF + cc*8);
        CP_ASYNC16(sb + CS_KL + (uint32_t)r*CSP_K + cc*16, kl + (size_t)r*MF + cc*8);
    }
    for (int i = tid; i < 512; i += 256) {
        int r = i >> 3, cc = i & 7;
        CP_ASYNC16(sb + CS_VH + (uint32_t)r*CSP_V + cc*16, g_vhi + (size_t)(l0+r)*DM + h*DH + cc*8);
        CP_ASYNC16(sb + CS_VL + (uint32_t)r*CSP_V + cc*16, g_vlo + (size_t)(l0+r)*DM + h*DH + cc*8);
    }
    // extension: cols 64..95 zero, col 64 of hi = 1.0
    if (tid < 64) {
        uint4 zz = make_uint4(0u,0u,0u,0u);
#pragma unroll
        for (int q = 0; q < 4; q++) {
            *(uint4*)(smc + CS_VH + tid*CSP_V + 128 + q*16) = zz;
            *(uint4*)(smc + CS_VL + tid*CSP_V + 128 + q*16) = zz;
        }
        *((__nv_bfloat16*)(smc + CS_VH + tid*CSP_V) + 64) = __float2bfloat16(1.0f);
    }
    CP_COMMIT(); CP_WAIT0();
    __syncthreads();

    float acc[2][6][4];
#pragma unroll
    for (int i = 0; i < 2; i++)
#pragma unroll
        for (int j = 0; j < 6; j++)
#pragma unroll
            for (int r = 0; r < 4; r++) acc[i][j][r] = 0.f;

#pragma unroll
    for (int ks = 0; ks < 4; ks++) {
        uint32_t ah[2][4], al[2][4], bh[3][4], bl[3][4];
#pragma unroll
        for (int mi = 0; mi < 2; mi++) {
            uint32_t aoff = (uint32_t)(ks*16 + ((lane >> 4) & 1)*8 + (lane & 7)) * CSP_K
                          + (uint32_t)(warp_m*32 + mi*16 + ((lane >> 3) & 1)*8) * 2;
            LDSM4T(ah[mi][0], ah[mi][1], ah[mi][2], ah[mi][3], sb + CS_KH + aoff);
            LDSM4T(al[mi][0], al[mi][1], al[mi][2], al[mi][3], sb + CS_KL + aoff);
        }
#pragma unroll
        for (int nb = 0; nb < 3; nb++) {
            uint32_t boff = (uint32_t)(ks*16 + (lane & 15)) * CSP_V
                          + (uint32_t)(warp_n*48 + nb*16 + (lane >> 4)*8) * 2;
            LDSM4T(bh[nb][0], bh[nb][1], bh[nb][2], bh[nb][3], sb + CS_VH + boff);
            LDSM4T(bl[nb][0], bl[nb][1], bl[nb][2], bl[nb][3], sb + CS_VL + boff);
        }
#pragma unroll
        for (int mi = 0; mi < 2; mi++)
#pragma unroll
            for (int nb = 0; nb < 3; nb++) {
                MMA16816(acc[mi][nb*2+0], ah[mi], bh[nb][0], bh[nb][1]);
                MMA16816(acc[mi][nb*2+1], ah[mi], bh[nb][2], bh[nb][3]);
                MMA16816(acc[mi][nb*2+0], ah[mi], bl[nb][0], bl[nb][1]);
                MMA16816(acc[mi][nb*2+1], ah[mi], bl[nb][2], bl[nb][3]);
                MMA16816(acc[mi][nb*2+0], al[mi], bh[nb][0], bh[nb][1]);
                MMA16816(acc[mi][nb*2+1], al[mi], bh[nb][2], bh[nb][3]);
            }
    }

    int g = lane >> 2, t = lane & 3;
    float* Sdst = g_S + (size_t)(h*NC + c) * MF * DH;
    float* zdst = g_z + (size_t)(h*NC + c) * MF;
#pragma unroll
    for (int mi = 0; mi < 2; mi++) {
#pragma unroll
        for (int half = 0; half < 2; half++) {
            int m = warp_m*32 + mi*16 + g + half*8;
#pragma unroll
            for (int nj = 0; nj < 6; nj++) {
                int col = warp_n*48 + nj*8 + t*2;
                float x = acc[mi][nj][half*2+0];
                float y = acc[mi][nj][half*2+1];
                if (col < 64) {
                    *(float2*)(Sdst + (size_t)m * DH + col) = make_float2(x, y);
                } else if (col == 64) {
                    zdst[m] = x;
                }
            }
        }
    }
}

// ---------------- exclusive prefix over chunks; S emitted as bf16 hi/lo ----------------
__global__ void prefix_scan(){
    int h = blockIdx.y;
    int idx = blockIdx.x * 256 + threadIdx.x;
    if (idx < MF * DH) {
        const float* p = g_S + (size_t)h * NC * MF * DH + idx;
        __nv_bfloat16* ph = g_Shi + (size_t)h * NC * MF * DH + idx;
        __nv_bfloat16* pl = g_Slo + (size_t)h * NC * MF * DH + idx;
        float prev = 0.f;
#pragma unroll
        for (int c = 0; c < NC; c++) {
            float cur = p[(size_t)c * MF * DH];
            __nv_bfloat16 hh = __float2bfloat16(prev);
            ph[(size_t)c * MF * DH] = hh;
            pl[(size_t)c * MF * DH] = __float2bfloat16(prev - __bfloat162float(hh));
            prev += cur;
        }
    } else if (idx < MF * DH + MF) {
        int m = idx - MF * DH;
        float* p = g_z + (size_t)h * NC * MF + m;
        float prev = 0.f;
#pragma unroll
        for (int c = 0; c < NC; c++) {
            float cur = p[c * MF];
            p[c * MF] = prev;
            prev += cur;
        }
    }
}

// ---------------- chunk_out via HMMA ----------------
#define PQ 272
#define PV 144
#define CO_QH 0
#define CO_QL (CO_QH + 64*PQ)
#define CO_KH (CO_QL + 64*PQ)
#define CO_KL (CO_KH + 64*PQ)
#define CO_VH (CO_KL + 64*PQ)
#define CO_VL (CO_VH + 64*PV)
#define CO_SH (CO_VL + 64*PV)
#define CO_SL (CO_SH + 128*PV)
#define CO_AH (CO_SL + 128*PV)
#define CO_AL (CO_AH + 64*PV)
#define CO_ZB (CO_AL + 64*PV)
#define CO_PR (CO_ZB + 512)
#define CO_RS (CO_PR + 64*4*4)
#define CO_TOTAL (CO_RS + 256)

__global__ __launch_bounds__(256) void chunk_out_hmma(){
    extern __shared__ char smc[];
    uint32_t sb = smem_u32(smc);
    int c = blockIdx.x, h = blockIdx.y;
    int tid = threadIdx.x, lane = tid & 31, wid = tid >> 5;
    int warp_m = wid & 1, warp_n = wid >> 1;
    int l0 = c * CHK;

    {
        const __nv_bfloat16* pqh = g_pqhi + ((size_t)h * L + l0) * MF;
        const __nv_bfloat16* pql = g_pqlo + ((size_t)h * L + l0) * MF;
        const __nv_bfloat16* pkh = g_pkhi + ((size_t)h * L + l0) * MF;
        const __nv_bfloat16* pkl = g_pklo + ((size_t)h * L + l0) * MF;
        for (int i = tid; i < 1024; i += 256) {
            int r = i >> 4, cc = i & 15;
            CP_ASYNC16(sb + CO_QH + r*PQ + cc*16, pqh + (size_t)r*MF + cc*8);
            CP_ASYNC16(sb + CO_QL + r*PQ + cc*16, pql + (size_t)r*MF + cc*8);
            CP_ASYNC16(sb + CO_KH + r*PQ + cc*16, pkh + (size_t)r*MF + cc*8);
            CP_ASYNC16(sb + CO_KL + r*PQ + cc*16, pkl + (size_t)r*MF + cc*8);
        }
        for (int i = tid; i < 512; i += 256) {
            int r = i >> 3, cc = i & 7;
            CP_ASYNC16(sb + CO_VH + r*PV + cc*16, g_vhi + (size_t)(l0 + r)*DM + h*DH + cc*8);
            CP_ASYNC16(sb + CO_VL + r*PV + cc*16, g_vlo + (size_t)(l0 + r)*DM + h*DH + cc*8);
        }
        const __nv_bfloat16* sh = g_Shi + (size_t)(h*NC + c)*MF*DH;
        const __nv_bfloat16* sl = g_Slo + (size_t)(h*NC + c)*MF*DH;
        for (int i = tid; i < 1024; i += 256) {
            int r = i >> 3, cc = i & 7;
            CP_ASYNC16(sb + CO_SH + r*PV + cc*16, sh + (size_t)r*DH + cc*8);
            CP_ASYNC16(sb + CO_SL + r*PV + cc*16, sl + (size_t)r*DH + cc*8);
        }
        if (tid < 32) CP_ASYNC16(sb + CO_ZB + tid*16, g_z + (size_t)(h*NC + c)*MF + tid*4);
        CP_COMMIT(); CP_WAIT0();
    }
    __syncthreads();

    uint32_t a_off = (uint32_t)(warp_m*32 + (lane & 15)) * PQ + (lane >> 4) * 16;
    uint32_t b_off = (uint32_t)(warp_n*16 + (lane & 7) + (lane >> 4) * 8) * PQ + ((lane >> 3) & 1) * 16;

    float acc[2][2][4];
#pragma unroll
    for (int i = 0; i < 2; i++)
#pragma unroll
        for (int j = 0; j < 2; j++)
#pragma unroll
            for (int r = 0; r < 4; r++) acc[i][j][r] = 0.f;

#pragma unroll
    for (int ks = 0; ks < 8; ks++) {
        uint32_t ah[2][4], al[2][4], bh[4], bl[4];
#pragma unroll
        for (int mi = 0; mi < 2; mi++) {
            LDSM4(ah[mi][0], ah[mi][1], ah[mi][2], ah[mi][3], sb + CO_QH + a_off + mi*16*PQ + ks*32);
            LDSM4(al[mi][0], al[mi][1], al[mi][2], al[mi][3], sb + CO_QL + a_off + mi*16*PQ + ks*32);
        }
        LDSM4(bh[0], bh[1], bh[2], bh[3], sb + CO_KH + b_off + ks*32);
        LDSM4(bl[0], bl[1], bl[2], bl[3], sb + CO_KL + b_off + ks*32);
#pragma unroll
        for (int mi = 0; mi < 2; mi++) {
            MMA16816(acc[mi][0], ah[mi], bh[0], bh[1]);
            MMA16816(acc[mi][1], ah[mi], bh[2], bh[3]);
            MMA16816(acc[mi][0], ah[mi], bl[0], bl[1]);
            MMA16816(acc[mi][1], ah[mi], bl[2], bl[3]);
            MMA16816(acc[mi][0], al[mi], bh[0], bh[1]);
            MMA16816(acc[mi][1], al[mi], bh[2], bh[3]);
        }
    }

    int g = lane >> 2, t = lane & 3;
    float* pr = (float*)(smc + CO_PR);
#pragma unroll
    for (int mi = 0; mi < 2; mi++) {
#pragma unroll
        for (int half = 0; half < 2; half++) {
            int row = warp_m*32 + mi*16 + g + half*8;
            float rsum = 0.f;
#pragma unroll
            for (int nj = 0; nj < 2; nj++) {
                int col = warp_n*16 + nj*8 + t*2;
                float x = (col     <= row) ? acc[mi][nj][half*2+0] : 0.f;
                float y = (col + 1 <= row) ? acc[mi][nj][half*2+1] : 0.f;
                rsum += x + y;
                __nv_bfloat162 hv, lv;
                split2(x, y, hv, lv);
                *(__nv_bfloat162*)(smc + CO_AH + row*PV + col*2) = hv;
                *(__nv_bfloat162*)(smc + CO_AL + row*PV + col*2) = lv;
            }
            rsum += __shfl_xor_sync(0xffffffffu, rsum, 1);
            rsum += __shfl_xor_sync(0xffffffffu, rsum, 2);
            if (t == 0) pr[row*4 + warp_n] = rsum;
        }
    }
    __syncthreads();

    if (tid < 64) {
        float s = pr[tid*4+0] + pr[tid*4+1] + pr[tid*4+2] + pr[tid*4+3];
        const float* zf = (const float*)(smc + CO_ZB);
#pragma unroll 8
        for (int m2 = 0; m2 < 64; m2++) {
            __nv_bfloat162 qh2 = *(const __nv_bfloat162*)(smc + CO_QH + tid*PQ + m2*4);
            __nv_bfloat162 ql2 = *(const __nv_bfloat162*)(smc + CO_QL + tid*PQ + m2*4);
            float2 z2 = *(const float2*)(zf + m2*2);
            s += (__bfloat162float(qh2.x) + __bfloat162float(ql2.x)) * z2.x
               + (__bfloat162float(qh2.y) + __bfloat162float(ql2.y)) * z2.y;
        }
        ((float*)(smc + CO_RS))[tid] = s + DEPS;
    }

    float o[2][2][4];
#pragma unroll
    for (int i = 0; i < 2; i++)
#pragma unroll
        for (int j = 0; j < 2; j++)
#pragma unroll
            for (int r = 0; r < 4; r++) o[i][j][r] = 0.f;

    uint32_t a2_off = (uint32_t)(warp_m*32 + (lane & 15)) * PV + (lane >> 4) * 16;
    uint32_t bt_off = (uint32_t)(lane & 15) * PV + (warp_n*16 + (lane >> 4) * 8) * 2;

#pragma unroll
    for (int ks = 0; ks < 4; ks++) {
        uint32_t ah[2][4], al[2][4], bh[4], bl[4];
#pragma unroll
        for (int mi = 0; mi < 2; mi++) {
            LDSM4(ah[mi][0], ah[mi][1], ah[mi][2], ah[mi][3], sb + CO_AH + a2_off + mi*16*PV + ks*32);
            LDSM4(al[mi][0], al[mi][1], al[mi][2], al[mi][3], sb + CO_AL + a2_off + mi*16*PV + ks*32);
        }
        LDSM4T(bh[0], bh[1], bh[2], bh[3], sb + CO_VH + bt_off + ks*16*PV);
        LDSM4T(bl[0], bl[1], bl[2], bl[3], sb + CO_VL + bt_off + ks*16*PV);
#pragma unroll
        for (int mi = 0; mi < 2; mi++) {
            MMA16816(o[mi][0], ah[mi], bh[0], bh[1]);
            MMA16816(o[mi][1], ah[mi], bh[2], bh[3]);
            MMA16816(o[mi][0], ah[mi], bl[0], bl[1]);
            MMA16816(o[mi][1], ah[mi], bl[2], bl[3]);
            MMA16816(o[mi][0], al[mi], bh[0], bh[1]);
            MMA16816(o[mi][1], al[mi], bh[2], bh[3]);
        }
    }
#pragma unroll
    for (int ks = 0; ks < 8; ks++) {
        uint32_t ah[2][4], al[2][4], bh[4], bl[4];
#pragma unroll
        for (int mi = 0; mi < 2; mi++) {
            LDSM4(ah[mi][0], ah[mi][1], ah[mi][2], ah[mi][3], sb + CO_QH + a_off + mi*16*PQ + ks*32);
            LDSM4(al[mi][0], al[mi][1], al[mi][2], al[mi][3], sb + CO_QL + a_off + mi*16*PQ + ks*32);
        }
        LDSM4T(bh[0], bh[1], bh[2], bh[3], sb + CO_SH + bt_off + ks*16*PV);
        LDSM4T(bl[0], bl[1], bl[2], bl[3], sb + CO_SL + bt_off + ks*16*PV);
#pragma unroll
        for (int mi = 0; mi < 2; mi++) {
            MMA16816(o[mi][0], ah[mi], bh[0], bh[1]);
            MMA16816(o[mi][1], ah[mi], bh[2], bh[3]);
            MMA16816(o[mi][0], ah[mi], bl[0], bl[1]);
            MMA16816(o[mi][1], ah[mi], bl[2], bl[3]);
            MMA16816(o[mi][0], al[mi], bh[0], bh[1]);
            MMA16816(o[mi][1], al[mi], bh[2], bh[3]);
        }
    }
    __syncthreads();

    const float* rs = (const float*)(smc + CO_RS);
#pragma unroll
    for (int mi = 0; mi < 2; mi++) {
#pragma unroll
        for (int half = 0; half < 2; half++) {
            int row = warp_m*32 + mi*16 + g + half*8;
            float inv = 1.0f / rs[row];
#pragma unroll
            for (int nj = 0; nj < 2; nj++) {
                int col = warp_n*16 + nj*8 + t*2;
                float ox = o[mi][nj][half*2+0] * inv;
                float oy = o[mi][nj][half*2+1] * inv;
                __nv_bfloat162 hv, lv;
                split2(ox, oy, hv, lv);
                size_t off = (size_t)(l0 + row) * DM + h*DH + col;
                *(__nv_bfloat162*)(g_bhi_ctx + off) = hv;
                *(__nv_bfloat162*)(g_blo_ctx + off) = lv;
            }
        }
    }
}

// ---------------- launcher ----------------
extern "C" void kernel_launch(void* const* d_in, const int* in_sizes, int n_in,
                              void* d_out, int out_size)
{
    const float* query = (const float*)d_in[0];
    const float* key_i = (const float*)d_in[1];
    const float* value = (const float*)d_in[2];
    const float* Wq = (const float*)d_in[3];
    const float* bq = (const float*)d_in[4];
    const float* Wk = (const float*)d_in[5];
    const float* bk = (const float*)d_in[6];
    const float* Wv = (const float*)d_in[7];
    const float* bv = (const float*)d_in[8];
    const float* Wo = (const float*)d_in[9];
    const float* bo = (const float*)d_in[10];
    const float* rf = (const float*)d_in[11];
    float* out = (float*)d_out;

    void* p;
    cudaGetSymbolAddress(&p, g_bhi_in);  __nv_bfloat16* bhi_in = (__nv_bfloat16*)p;
    cudaGetSymbolAddress(&p, g_blo_in);  __nv_bfloat16* blo_in = (__nv_bfloat16*)p;
    cudaGetSymbolAddress(&p, g_bhi_w);   __nv_bfloat16* bhi_w  = (__nv_bfloat16*)p;
    cudaGetSymbolAddress(&p, g_blo_w);   __nv_bfloat16* blo_w  = (__nv_bfloat16*)p;
    cudaGetSymbolAddress(&p, g_bhi_ctx); __nv_bfloat16* bhi_c  = (__nv_bfloat16*)p;
    cudaGetSymbolAddress(&p, g_blo_ctx); __nv_bfloat16* blo_c  = (__nv_bfloat16*)p;
    cudaGetSymbolAddress(&p, g_qhi);     __nv_bfloat16* qhi    = (__nv_bfloat16*)p;
    cudaGetSymbolAddress(&p, g_qlo);     __nv_bfloat16* qlo    = (__nv_bfloat16*)p;
    cudaGetSymbolAddress(&p, g_khi);     __nv_bfloat16* khi    = (__nv_bfloat16*)p;
    cudaGetSymbolAddress(&p, g_klo);     __nv_bfloat16* klo    = (__nv_bfloat16*)p;
    cudaGetSymbolAddress(&p, g_vhi);     __nv_bfloat16* vhi    = (__nv_bfloat16*)p;
    cudaGetSymbolAddress(&p, g_vlo);     __nv_bfloat16* vlo    = (__nv_bfloat16*)p;

    reset_kstab<<<1, 1>>>();

    CV cv;
    cv.src[0]=query; cv.hi[0]=bhi_in;          cv.lo[0]=blo_in;          cv.n[0]=L*DM;
    cv.src[1]=key_i; cv.hi[1]=bhi_in+L*DM;     cv.lo[1]=blo_in+L*DM;     cv.n[1]=L*DM;
    cv.src[2]=value; cv.hi[2]=bhi_in+2*L*DM;   cv.lo[2]=blo_in+2*L*DM;   cv.n[2]=L*DM;
    cv.src[3]=Wq;    cv.hi[3]=bhi_w;           cv.lo[3]=blo_w;           cv.n[3]=DM*DM;
    cv.src[4]=Wk;    cv.hi[4]=bhi_w+DM*DM;     cv.lo[4]=blo_w+DM*DM;     cv.n[4]=DM*DM;
    cv.src[5]=Wv;    cv.hi[5]=bhi_w+2*DM*DM;   cv.lo[5]=blo_w+2*DM*DM;   cv.n[5]=DM*DM;
    cv.src[6]=Wo;    cv.hi[6]=bhi_w+3*DM*DM;   cv.lo[6]=blo_w+3*DM*DM;   cv.n[6]=DM*DM;
    cv.cnt = 7;
    convert_split<<<dim3((L*DM)/1024, 7), 256>>>(cv);
    rf_convert<<<(MF*DH + 255)/256, 256>>>(rf);

    cudaFuncSetAttribute(hmma_gemm, cudaFuncAttributeMaxDynamicSharedMemorySize, HG_SMEM);
    cudaFuncSetAttribute(rf_proj_hmma, cudaFuncAttributeMaxDynamicSharedMemorySize, RF_SMEM);
    cudaFuncSetAttribute(chunk_state_hmma, cudaFuncAttributeMaxDynamicSharedMemorySize, CS_TOTAL);
    cudaFuncSetAttribute(chunk_out_hmma, cudaFuncAttributeMaxDynamicSharedMemorySize, CO_TOTAL);

    // QKV projections: all outputs bf16 hi/lo only
    MMArgs mq;
    mq.Ahi[0]=bhi_in;        mq.Alo[0]=blo_in;        mq.Whi[0]=bhi_w;        mq.Wlo[0]=blo_w;        mq.bias[0]=bq; mq.C[0]=nullptr; mq.Chi[0]=qhi; mq.Clo[0]=qlo; mq.alpha[0]=SCALE_QK;
    mq.Ahi[1]=bhi_in+L*DM;   mq.Alo[1]=blo_in+L*DM;   mq.Whi[1]=bhi_w+DM*DM;  mq.Wlo[1]=blo_w+DM*DM;  mq.bias[1]=bk; mq.C[1]=nullptr; mq.Chi[1]=khi; mq.Clo[1]=klo; mq.alpha[1]=SCALE_QK;
    mq.Ahi[2]=bhi_in+2*L*DM; mq.Alo[2]=blo_in+2*L*DM; mq.Whi[2]=bhi_w+2*DM*DM;mq.Wlo[2]=blo_w+2*DM*DM;mq.bias[2]=bv; mq.C[2]=nullptr; mq.Chi[2]=vhi; mq.Clo[2]=vlo; mq.alpha[2]=1.0f;
    hmma_gemm<<<dim3(DM/128, L/64, 3), 256, HG_SMEM>>>(mq);

    hk_max<<<L, 256>>>();
    rf_proj_hmma<<<dim3(1, L/128, 16), 256, RF_SMEM>>>();

    chunk_state_hmma<<<dim3(NC, NH), 256, CS_TOTAL>>>();
    prefix_scan<<<dim3((MF*DH + MF + 255)/256, NH), 256>>>();
    chunk_out_hmma<<<dim3(NC, NH), 256, CO_TOTAL>>>();

    // output projection
    MMArgs mo;
    mo.Ahi[0]=bhi_c; mo.Alo[0]=blo_c; mo.Whi[0]=bhi_w+3*DM*DM; mo.Wlo[0]=blo_w+3*DM*DM; mo.bias[0]=bo; mo.C[0]=out; mo.Chi[0]=nullptr; mo.Clo[0]=nullptr; mo.alpha[0]=1.0f;
    mo.Ahi[1]=mo.Ahi[0]; mo.Alo[1]=mo.Alo[0]; mo.Whi[1]=mo.Whi[0]; mo.Wlo[1]=mo.Wlo[0]; mo.bias[1]=bo; mo.C[1]=out; mo.Chi[1]=nullptr; mo.Clo[1]=nullptr; mo.alpha[1]=1.0f;
    mo.Ahi[2]=mo.Ahi[0]; mo.Alo[2]=mo.Alo[0]; mo.Whi[2]=mo.Whi[0]; mo.Wlo[2]=mo.Wlo[0]; mo.bias[2]=bo; mo.C[2]=out; mo.Chi[2]=nullptr; mo.Clo[2]=nullptr; mo.alpha[2]=1.0f;
    hmma_gemm<<<dim3(DM/128, L/64, 1), 256, HG_SMEM>>>(mo);
}

// round 9
// speedup vs baseline: 4.3439x; 1.0588x over previous
#include <cuda_runtime.h>
#include <cuda_bf16.h>
#include <math.h>
#include <stdint.h>

#define L 2048
#define DM 512
#define NH 8
#define DH 64
#define MF 128
#define CHK 64
#define NC (L/CHK)   // 32

#define SCALE_QK 0.2102241038134287f
#define NC_COEF  0.08838834764831845f
#define KEPS 1e-4f
#define DEPS 1e-6f

// ---------------- device scratch ----------------
__device__ float g_hk[NH*L];
__device__ unsigned g_kstab;
__device__ float g_S[NH*NC*MF*DH];
__device__ float g_z[NH*NC*MF];

__device__ __nv_bfloat16 g_bhi_in[3][L*DM];
__device__ __nv_bfloat16 g_blo_in[3][L*DM];
__device__ __nv_bfloat16 g_bhi_w[4][DM*DM];
__device__ __nv_bfloat16 g_blo_w[4][DM*DM];
__device__ __nv_bfloat16 g_bhi_ctx[L*DM];
__device__ __nv_bfloat16 g_blo_ctx[L*DM];
__device__ __nv_bfloat16 g_qhi[L*DM];
__device__ __nv_bfloat16 g_qlo[L*DM];
__device__ __nv_bfloat16 g_khi[L*DM];
__device__ __nv_bfloat16 g_klo[L*DM];
__device__ __nv_bfloat16 g_rfthi[MF*DH];
__device__ __nv_bfloat16 g_rftlo[MF*DH];
__device__ __nv_bfloat16 g_pqhi[NH*L*MF];
__device__ __nv_bfloat16 g_pqlo[NH*L*MF];
__device__ __nv_bfloat16 g_pkhi[NH*L*MF];
__device__ __nv_bfloat16 g_pklo[NH*L*MF];
__device__ __nv_bfloat16 g_vhi[L*DM];
__device__ __nv_bfloat16 g_vlo[L*DM];
__device__ __nv_bfloat16 g_Shi[NH*NC*MF*DH];
__device__ __nv_bfloat16 g_Slo[NH*NC*MF*DH];

__device__ __forceinline__ unsigned enc_f(float f){
    unsigned u = __float_as_uint(f);
    return (u & 0x80000000u) ? ~u : (u | 0x80000000u);
}
__device__ __forceinline__ float dec_f(unsigned k){
    unsigned u = (k & 0x80000000u) ? (k ^ 0x80000000u) : ~k;
    return __uint_as_float(u);
}

__global__ void reset_kstab(){ g_kstab = 0u; }

__device__ __forceinline__ uint32_t smem_u32(const void* p) {
    uint32_t a;
    asm("{ .reg .u64 t; cvta.to.shared.u64 t, %1; cvt.u32.u64 %0, t; }" : "=r"(a) : "l"(p));
    return a;
}

#define CP_ASYNC16(sa, gp) asm volatile("cp.async.cg.shared.global [%0], [%1], 16;" :: "r"(sa), "l"(gp))
#define CP_COMMIT()        asm volatile("cp.async.commit_group;")
#define CP_WAIT1()         asm volatile("cp.async.wait_group 1;")
#define CP_WAIT0()         asm volatile("cp.async.wait_group 0;")

#define LDSM4(r0,r1,r2,r3,a) \
    asm volatile("ldmatrix.sync.aligned.m8n8.x4.shared.b16 {%0,%1,%2,%3}, [%4];" \
        : "=r"(r0),"=r"(r1),"=r"(r2),"=r"(r3) : "r"(a))
#define LDSM4T(r0,r1,r2,r3,a) \
    asm volatile("ldmatrix.sync.aligned.m8n8.x4.trans.shared.b16 {%0,%1,%2,%3}, [%4];" \
        : "=r"(r0),"=r"(r1),"=r"(r2),"=r"(r3) : "r"(a))

#define MMA16816(d,a,b0,b1) \
    asm volatile("mma.sync.aligned.m16n8k16.row.col.f32.bf16.bf16.f32 " \
        "{%0,%1,%2,%3},{%4,%5,%6,%7},{%8,%9},{%0,%1,%2,%3};" \
        : "+f"((d)[0]),"+f"((d)[1]),"+f"((d)[2]),"+f"((d)[3]) \
        : "r"((a)[0]),"r"((a)[1]),"r"((a)[2]),"r"((a)[3]),"r"(b0),"r"(b1))

__device__ __forceinline__ void split2(float x, float y, __nv_bfloat162& hv, __nv_bfloat162& lv){
    __nv_bfloat16 hx = __float2bfloat16(x);
    __nv_bfloat16 hy = __float2bfloat16(y);
    hv.x = hx; hv.y = hy;
    lv.x = __float2bfloat16(x - __bfloat162float(hx));
    lv.y = __float2bfloat16(y - __bfloat162float(hy));
}

// ---------------- fp32 -> (bf16 hi, bf16 lo) converter ----------------
struct CV { const float* src[8]; __nv_bfloat16* hi[8]; __nv_bfloat16* lo[8]; int n[8]; int cnt; };
__global__ void convert_split(CV cv){
    int t = blockIdx.y;
    if (t >= cv.cnt) return;
    int n = cv.n[t];
    const float* s = cv.src[t];
    __nv_bfloat16* ph = cv.hi[t];
    __nv_bfloat16* pl = cv.lo[t];
    int i0 = blockIdx.x * 1024 + threadIdx.x;
#pragma unroll
    for (int j = 0; j < 4; j++) {
        int i = i0 + j * 256;
        if (i < n) {
            float x = s[i];
            __nv_bfloat16 h = __float2bfloat16(x);
            ph[i] = h;
            pl[i] = __float2bfloat16(x - __bfloat162float(h));
        }
    }
}

__global__ void rf_convert(const float* __restrict__ rf){
    int i = blockIdx.x * 256 + threadIdx.x;
    if (i < MF * DH) {
        int m = i >> 6, d = i & 63;
        float x = rf[(size_t)d * MF + m];
        __nv_bfloat16 h = __float2bfloat16(x);
        g_rfthi[(size_t)m * DH + d] = h;
        g_rftlo[(size_t)m * DH + d] = __float2bfloat16(x - __bfloat162float(h));
    }
}

// ---------------- split-bf16 HMMA GEMM (tile 64x128, BK=64, 2 CTAs/SM) ----------------
#define PITCH_B 144
#define A_TILE (64*PITCH_B)          // 9216
#define B_TILE (128*PITCH_B)         // 18432
#define STAGE_BYTES (2*A_TILE + 2*B_TILE)  // 55296
#define HG_SMEM (2*STAGE_BYTES)      // 110592
#define NKC 8

struct MMArgs {
    const __nv_bfloat16* Ahi[3]; const __nv_bfloat16* Alo[3];
    const __nv_bfloat16* Whi[3]; const __nv_bfloat16* Wlo[3];
    const float* bias[3]; float* C[3];
    __nv_bfloat16* Chi[3]; __nv_bfloat16* Clo[3];
    float alpha[3];
};

__global__ __launch_bounds__(256, 2) void hmma_gemm(MMArgs ga, int do_hk)
{
    extern __shared__ char smem[];
    uint32_t sb = smem_u32(smem);
    int tid = threadIdx.x;
    int lane = tid & 31, wid = tid >> 5;
    int warp_m = wid & 1, warp_n = wid >> 1;      // 2M x 4N, warp tile 32x32
    int z = blockIdx.z;
    int m0 = blockIdx.y * 64, n0 = blockIdx.x * 128;

    const __nv_bfloat16* Ahi = ga.Ahi[z] + (size_t)m0 * DM;
    const __nv_bfloat16* Alo = ga.Alo[z] + (size_t)m0 * DM;
    const __nv_bfloat16* Whi = ga.Whi[z] + (size_t)n0 * DM;
    const __nv_bfloat16* Wlo = ga.Wlo[z] + (size_t)n0 * DM;
    const float* bias = ga.bias[z];
    float alpha = ga.alpha[z];

    uint32_t a_off = (uint32_t)(warp_m*32 + (lane & 15)) * PITCH_B + (lane >> 4) * 16;
    uint32_t b_off = (uint32_t)(warp_n*32 + (lane & 7) + (lane >> 4) * 8) * PITCH_B + ((lane >> 3) & 1) * 16;

    float acc[2][4][4];
#pragma unroll
    for (int i = 0; i < 2; i++)
#pragma unroll
        for (int j = 0; j < 4; j++)
#pragma unroll
            for (int r = 0; r < 4; r++) acc[i][j][r] = 0.f;

    // loads: 3072 16B chunks per stage = 12 per thread
    // prologue stage 0
    {
#pragma unroll
        for (int j = 0; j < 12; j++) {
            int idx = tid + j * 256;
            const __nv_bfloat16* gp;
            uint32_t sp;
            if (idx < 1024) {
                int t2 = idx >> 9;            // 0=Ahi 1=Alo
                int w = idx & 511;
                int r = w >> 3, cc = w & 7;
                gp = (t2 ? Alo : Ahi) + (size_t)r * DM + cc*8;
                sp = sb + t2*A_TILE + (uint32_t)r * PITCH_B + cc*16;
            } else {
                int w = idx - 1024;
                int t2 = w >> 10;             // 0=Whi 1=Wlo
                w &= 1023;
                int r = w >> 3, cc = w & 7;
                gp = (t2 ? Wlo : Whi) + (size_t)r * DM + cc*8;
                sp = sb + 2*A_TILE + t2*B_TILE + (uint32_t)r * PITCH_B + cc*16;
            }
            CP_ASYNC16(sp, gp);
        }
        CP_COMMIT();
    }

    for (int kc = 0; kc < NKC; kc++) {
        if (kc + 1 < NKC) {
            int k0 = (kc + 1) * 64;
            uint32_t stb = sb + ((kc + 1) & 1) * STAGE_BYTES;
#pragma unroll
            for (int j = 0; j < 12; j++) {
                int idx = tid + j * 256;
                const __nv_bfloat16* gp;
                uint32_t sp;
                if (idx < 1024) {
                    int t2 = idx >> 9;
                    int w = idx & 511;
                    int r = w >> 3, cc = w & 7;
                    gp = (t2 ? Alo : Ahi) + (size_t)r * DM + k0 + cc*8;
                    sp = stb + t2*A_TILE + (uint32_t)r * PITCH_B + cc*16;
                } else {
                    int w = idx - 1024;
                    int t2 = w >> 10;
                    w &= 1023;
                    int r = w >> 3, cc = w & 7;
                    gp = (t2 ? Wlo : Whi) + (size_t)r * DM + k0 + cc*8;
                    sp = stb + 2*A_TILE + t2*B_TILE + (uint32_t)r * PITCH_B + cc*16;
                }
                CP_ASYNC16(sp, gp);
            }
            CP_COMMIT();
            CP_WAIT1();
        } else {
            CP_WAIT0();
        }
        __syncthreads();

        uint32_t st = sb + (kc & 1) * STAGE_BYTES;
        uint32_t sAhi = st + a_off;
        uint32_t sAlo = st + A_TILE + a_off;
        uint32_t sBhi = st + 2*A_TILE + b_off;
        uint32_t sBlo = st + 2*A_TILE + B_TILE + b_off;

#pragma unroll
        for (int ks = 0; ks < 4; ks++) {
            uint32_t ah[2][4], al[2][4], bh[2][4], bl[2][4];
#pragma unroll
            for (int mi = 0; mi < 2; mi++) {
                LDSM4(ah[mi][0], ah[mi][1], ah[mi][2], ah[mi][3], sAhi + mi*16*PITCH_B + ks*32);
                LDSM4(al[mi][0], al[mi][1], al[mi][2], al[mi][3], sAlo + mi*16*PITCH_B + ks*32);
            }
#pragma unroll
            for (int nb = 0; nb < 2; nb++) {
                LDSM4(bh[nb][0], bh[nb][1], bh[nb][2], bh[nb][3], sBhi + nb*16*PITCH_B + ks*32);
                LDSM4(bl[nb][0], bl[nb][1], bl[nb][2], bl[nb][3], sBlo + nb*16*PITCH_B + ks*32);
            }
#pragma unroll
            for (int mi = 0; mi < 2; mi++)
#pragma unroll
                for (int nb = 0; nb < 2; nb++) {
                    MMA16816(acc[mi][nb*2+0], ah[mi], bh[nb][0], bh[nb][1]);
                    MMA16816(acc[mi][nb*2+1], ah[mi], bh[nb][2], bh[nb][3]);
                    MMA16816(acc[mi][nb*2+0], ah[mi], bl[nb][0], bl[nb][1]);
                    MMA16816(acc[mi][nb*2+1], ah[mi], bl[nb][2], bl[nb][3]);
                    MMA16816(acc[mi][nb*2+0], al[mi], bh[nb][0], bh[nb][1]);
                    MMA16816(acc[mi][nb*2+1], al[mi], bh[nb][2], bh[nb][3]);
                }
        }
        __syncthreads();
    }

    int g = lane >> 2, t = lane & 3;
    __nv_bfloat16* Chi = ga.Chi[z];
    float* C = ga.C[z];
    bool hk = (do_hk && z == 1);
    float* pr = (float*)smem;                 // 64 rows x 4 warps (reuse stage smem)
    float* red = (float*)smem + 256;

#pragma unroll
    for (int mi = 0; mi < 2; mi++) {
#pragma unroll
        for (int half = 0; half < 2; half++) {
            int row = m0 + warp_m*32 + mi*16 + g + half*8;
            float ss = 0.f;
#pragma unroll
            for (int nj = 0; nj < 4; nj++) {
                int col = n0 + warp_n*32 + nj*8 + t*2;
                float2 bb = *(const float2*)(bias + col);
                float ox = alpha * (acc[mi][nj][half*2+0] + bb.x);
                float oy = alpha * (acc[mi][nj][half*2+1] + bb.y);
                ss += ox*ox + oy*oy;
                if (C) *(float2*)(C + (size_t)row * DM + col) = make_float2(ox, oy);
                if (Chi) {
                    __nv_bfloat162 hv, lv;
                    split2(ox, oy, hv, lv);
                    *(__nv_bfloat162*)(Chi + (size_t)row * DM + col) = hv;
                    *(__nv_bfloat162*)(ga.Clo[z] + (size_t)row * DM + col) = lv;
                }
            }
            if (hk) {
                ss += __shfl_xor_sync(0xffffffffu, ss, 1);
                ss += __shfl_xor_sync(0xffffffffu, ss, 2);
                if (t == 0) pr[(warp_m*32 + mi*16 + g + half*8)*4 + warp_n] = ss;
            }
        }
    }
    if (hk) {
        __syncthreads();
        float hmax = -1e30f;
        if (tid < 128) {
            int row = tid >> 1, hd2 = tid & 1;
            float ss = pr[row*4 + hd2*2] + pr[row*4 + hd2*2 + 1];
            float hv = -0.5f * ss;
            g_hk[(size_t)((n0 >> 6) + hd2) * L + m0 + row] = hv;
            hmax = hv;
        }
#pragma unroll
        for (int o = 16; o; o >>= 1) hmax = fmaxf(hmax, __shfl_xor_sync(0xffffffffu, hmax, o));
        if (lane == 0) red[wid] = hmax;
        __syncthreads();
        if (tid == 0) {
            float mx = red[0];
#pragma unroll
            for (int i = 1; i < 8; i++) mx = fmaxf(mx, red[i]);
            atomicMax(&g_kstab, enc_f(mx));
        }
    }
}

// ---------------- rf projection + featurize (HMMA split-bf16) ----------------
#define PITCH2 144
#define TILE2 (128*PITCH2)
#define RF_SMEM (4*TILE2)

__global__ __launch_bounds__(256) void rf_proj_hmma()
{
    extern __shared__ char smem[];
    uint32_t sb = smem_u32(smem);
    int tid = threadIdx.x;
    int lane = tid & 31, wid = tid >> 5;
    int warp_m = wid & 1, warp_n = wid >> 1;
    int z = blockIdx.z;
    int h = z & 7;
    bool isq = z < 8;
    int m0 = blockIdx.y * 128;

    const __nv_bfloat16* Ahi = (isq ? g_qhi : g_khi) + (size_t)m0 * DM + h * DH;
    const __nv_bfloat16* Alo = (isq ? g_qlo : g_klo) + (size_t)m0 * DM + h * DH;

#pragma unroll
    for (int j = 0; j < 16; j++) {
        int idx = tid + j * 256;
        int tile = idx >> 10;
        int w = idx & 1023;
        int r = w >> 3, c = w & 7;
        const __nv_bfloat16* gp =
            (tile == 0) ? (Ahi + (size_t)r * DM + c*8) :
            (tile == 1) ? (Alo + (size_t)r * DM + c*8) :
            (tile == 2) ? (g_rfthi + (size_t)r * DH + c*8) :
                          (g_rftlo + (size_t)r * DH + c*8);
        uint32_t sp = sb + tile * TILE2 + (uint32_t)r * PITCH2 + c * 16;
        CP_ASYNC16(sp, gp);
    }
    CP_COMMIT();
    CP_WAIT0();
    __syncthreads();

    uint32_t a_off = (uint32_t)(warp_m*64 + (lane & 15)) * PITCH2 + (lane >> 4) * 16;
    uint32_t b_off = (uint32_t)(warp_n*32 + (lane & 7) + (lane >> 4) * 8) * PITCH2 + ((lane >> 3) & 1) * 16;
    uint32_t sAhi = sb + a_off;
    uint32_t sAlo = sb + TILE2 + a_off;
    uint32_t sBhi = sb + 2*TILE2 + b_off;
    uint32_t sBlo = sb + 3*TILE2 + b_off;

    float acc[4][4][4];
#pragma unroll
    for (int i = 0; i < 4; i++)
#pragma unroll
        for (int j = 0; j < 4; j++)
#pragma unroll
            for (int r = 0; r < 4; r++) acc[i][j][r] = 0.f;

#pragma unroll
    for (int ks = 0; ks < 4; ks++) {
        uint32_t ah[4][4], al[4][4], bh[2][4], bl[2][4];
#pragma unroll
        for (int mi = 0; mi < 4; mi++) {
            LDSM4(ah[mi][0], ah[mi][1], ah[mi][2], ah[mi][3], sAhi + mi*16*PITCH2 + ks*32);
            LDSM4(al[mi][0], al[mi][1], al[mi][2], al[mi][3], sAlo + mi*16*PITCH2 + ks*32);
        }
#pragma unroll
        for (int nb = 0; nb < 2; nb++) {
            LDSM4(bh[nb][0], bh[nb][1], bh[nb][2], bh[nb][3], sBhi + nb*16*PITCH2 + ks*32);
            LDSM4(bl[nb][0], bl[nb][1], bl[nb][2], bl[nb][3], sBlo + nb*16*PITCH2 + ks*32);
        }
#pragma unroll
        for (int mi = 0; mi < 4; mi++)
#pragma unroll
            for (int nb = 0; nb < 2; nb++) {
                MMA16816(acc[mi][nb*2+0], ah[mi], bh[nb][0], bh[nb][1]);
                MMA16816(acc[mi][nb*2+1], ah[mi], bh[nb][2], bh[nb][3]);
                MMA16816(acc[mi][nb*2+0], ah[mi], bl[nb][0], bl[nb][1]);
                MMA16816(acc[mi][nb*2+1], ah[mi], bl[nb][2], bl[nb][3]);
                MMA16816(acc[mi][nb*2+0], al[mi], bh[nb][0], bh[nb][1]);
                MMA16816(acc[mi][nb*2+1], al[mi], bh[nb][2], bh[nb][3]);
            }
    }

    float kst = isq ? 0.f : dec_f(g_kstab);
    int g = lane >> 2, t = lane & 3;
    __nv_bfloat16* Ph = (isq ? g_pqhi : g_pkhi) + (size_t)h * L * MF;
    __nv_bfloat16* Pl = (isq ? g_pqlo : g_pklo) + (size_t)h * L * MF;
#pragma unroll
    for (int mi = 0; mi < 4; mi++) {
#pragma unroll
        for (int half = 0; half < 2; half++) {
            int row = m0 + warp_m*64 + mi*16 + g + half*8;
            float off = isq ? 0.f : (g_hk[(size_t)h * L + row] - kst);
#pragma unroll
            for (int nj = 0; nj < 4; nj++) {
                int col = warp_n*32 + nj*8 + t*2;
                float ox = NC_COEF * (__expf(acc[mi][nj][half*2+0] + off) + KEPS);
                float oy = NC_COEF * (__expf(acc[mi][nj][half*2+1] + off) + KEPS);
                __nv_bfloat162 hv, lv;
                split2(ox, oy, hv, lv);
                *(__nv_bfloat162*)(Ph + (size_t)row * MF + col) = hv;
                *(__nv_bfloat162*)(Pl + (size_t)row * MF + col) = lv;
            }
        }
    }
}

// ---------------- chunk_state via HMMA ----------------
#define CSP_K 272
#define CSP_V 208
#define CS_KH 0
#define CS_KL (CS_KH + 64*CSP_K)
#define CS_VH (CS_KL + 64*CSP_K)
#define CS_VL (CS_VH + 64*CSP_V)
#define CS_TOTAL (CS_VL + 64*CSP_V)

__global__ __launch_bounds__(256) void chunk_state_hmma(){
    extern __shared__ char smc[];
    uint32_t sb = smem_u32(smc);
    int c = blockIdx.x, h = blockIdx.y;
    int tid = threadIdx.x, lane = tid & 31, wid = tid >> 5;
    int warp_m = wid >> 1, warp_n = wid & 1;
    int l0 = c * CHK;

    const __nv_bfloat16* kh = g_pkhi + ((size_t)h * L + l0) * MF;
    const __nv_bfloat16* kl = g_pklo + ((size_t)h * L + l0) * MF;
    for (int i = tid; i < 1024; i += 256) {
        int r = i >> 4, cc = i & 15;
        CP_ASYNC16(sb + CS_KH + (uint32_t)r*CSP_K + cc*16, kh + (size_t)r*MF + cc*8);
        CP_ASYNC16(sb + CS_KL + (uint32_t)r*CSP_K + cc*16, kl + (size_t)r*MF + cc*8);
    }
    for (int i = tid; i < 512; i += 256) {
        int r = i >> 3, cc = i & 7;
        CP_ASYNC16(sb + CS_VH + (uint32_t)r*CSP_V + cc*16, g_vhi + (size_t)(l0+r)*DM + h*DH + cc*8);
        CP_ASYNC16(sb + CS_VL + (uint32_t)r*CSP_V + cc*16, g_vlo + (size_t)(l0+r)*DM + h*DH + cc*8);
    }
    if (tid < 64) {
        uint4 zz = make_uint4(0u,0u,0u,0u);
#pragma unroll
        for (int q = 0; q < 4; q++) {
            *(uint4*)(smc + CS_VH + tid*CSP_V + 128 + q*16) = zz;
            *(uint4*)(smc + CS_VL + tid*CSP_V + 128 + q*16) = zz;
        }
        *((__nv_bfloat16*)(smc + CS_VH + tid*CSP_V) + 64) = __float2bfloat16(1.0f);
    }
    CP_COMMIT(); CP_WAIT0();
    __syncthreads();

    float acc[2][6][4];
#pragma unroll
    for (int i = 0; i < 2; i++)
#pragma unroll
        for (int j = 0; j < 6; j++)
#pragma unroll
            for (int r = 0; r < 4; r++) acc[i][j][r] = 0.f;

#pragma unroll
    for (int ks = 0; ks < 4; ks++) {
        uint32_t ah[2][4], al[2][4], bh[3][4], bl[3][4];
#pragma unroll
        for (int mi = 0; mi < 2; mi++) {
            uint32_t aoff = (uint32_t)(ks*16 + ((lane >> 4) & 1)*8 + (lane & 7)) * CSP_K
                          + (uint32_t)(warp_m*32 + mi*16 + ((lane >> 3) & 1)*8) * 2;
            LDSM4T(ah[mi][0], ah[mi][1], ah[mi][2], ah[mi][3], sb + CS_KH + aoff);
            LDSM4T(al[mi][0], al[mi][1], al[mi][2], al[mi][3], sb + CS_KL + aoff);
        }
#pragma unroll
        for (int nb = 0; nb < 3; nb++) {
            uint32_t boff = (uint32_t)(ks*16 + (lane & 15)) * CSP_V
                          + (uint32_t)(warp_n*48 + nb*16 + (lane >> 4)*8) * 2;
            LDSM4T(bh[nb][0], bh[nb][1], bh[nb][2], bh[nb][3], sb + CS_VH + boff);
            LDSM4T(bl[nb][0], bl[nb][1], bl[nb][2], bl[nb][3], sb + CS_VL + boff);
        }
#pragma unroll
        for (int mi = 0; mi < 2; mi++)
#pragma unroll
            for (int nb = 0; nb < 3; nb++) {
                MMA16816(acc[mi][nb*2+0], ah[mi], bh[nb][0], bh[nb][1]);
                MMA16816(acc[mi][nb*2+1], ah[mi], bh[nb][2], bh[nb][3]);
                MMA16816(acc[mi][nb*2+0], ah[mi], bl[nb][0], bl[nb][1]);
                MMA16816(acc[mi][nb*2+1], ah[mi], bl[nb][2], bl[nb][3]);
                MMA16816(acc[mi][nb*2+0], al[mi], bh[nb][0], bh[nb][1]);
                MMA16816(acc[mi][nb*2+1], al[mi], bh[nb][2], bh[nb][3]);
            }
    }

    int g = lane >> 2, t = lane & 3;
    float* Sdst = g_S + (size_t)(h*NC + c) * MF * DH;
    float* zdst = g_z + (size_t)(h*NC + c) * MF;
#pragma unroll
    for (int mi = 0; mi < 2; mi++) {
#pragma unroll
        for (int half = 0; half < 2; half++) {
            int m = warp_m*32 + mi*16 + g + half*8;
#pragma unroll
            for (int nj = 0; nj < 6; nj++) {
                int col = warp_n*48 + nj*8 + t*2;
                float x = acc[mi][nj][half*2+0];
                float y = acc[mi][nj][half*2+1];
                if (col < 64) {
                    *(float2*)(Sdst + (size_t)m * DH + col) = make_float2(x, y);
                } else if (col == 64) {
                    zdst[m] = x;
                }
            }
        }
    }
}

// ---------------- exclusive prefix over chunks; S emitted as bf16 hi/lo ----------------
__global__ void prefix_scan(){
    int h = blockIdx.y;
    int idx = blockIdx.x * 256 + threadIdx.x;
    if (idx < MF * DH) {
        const float* p = g_S + (size_t)h * NC * MF * DH + idx;
        __nv_bfloat16* ph = g_Shi + (size_t)h * NC * MF * DH + idx;
        __nv_bfloat16* pl = g_Slo + (size_t)h * NC * MF * DH + idx;
        float prev = 0.f;
#pragma unroll
        for (int c = 0; c < NC; c++) {
            float cur = p[(size_t)c * MF * DH];
            __nv_bfloat16 hh = __float2bfloat16(prev);
            ph[(size_t)c * MF * DH] = hh;
            pl[(size_t)c * MF * DH] = __float2bfloat16(prev - __bfloat162float(hh));
            prev += cur;
        }
    } else if (idx < MF * DH + MF) {
        int m = idx - MF * DH;
        float* p = g_z + (size_t)h * NC * MF + m;
        float prev = 0.f;
#pragma unroll
        for (int c = 0; c < NC; c++) {
            float cur = p[c * MF];
            p[c * MF] = prev;
            prev += cur;
        }
    }
}

// ---------------- chunk_out via HMMA ----------------
#define PQ 272
#define PV 144
#define CO_QH 0
#define CO_QL (CO_QH + 64*PQ)
#define CO_KH (CO_QL + 64*PQ)
#define CO_KL (CO_KH + 64*PQ)
#define CO_VH (CO_KL + 64*PQ)
#define CO_VL (CO_VH + 64*PV)
#define CO_SH (CO_VL + 64*PV)
#define CO_SL (CO_SH + 128*PV)
#define CO_AH (CO_SL + 128*PV)
#define CO_AL (CO_AH + 64*PV)
#define CO_ZB (CO_AL + 64*PV)
#define CO_PR (CO_ZB + 512)
#define CO_RS (CO_PR + 64*4*4)
#define CO_TOTAL (CO_RS + 256)

__global__ __launch_bounds__(256) void chunk_out_hmma(){
    extern __shared__ char smc[];
    uint32_t sb = smem_u32(smc);
    int c = blockIdx.x, h = blockIdx.y;
    int tid = threadIdx.x, lane = tid & 31, wid = tid >> 5;
    int warp_m = wid & 1, warp_n = wid >> 1;
    int l0 = c * CHK;

    {
        const __nv_bfloat16* pqh = g_pqhi + ((size_t)h * L + l0) * MF;
        const __nv_bfloat16* pql = g_pqlo + ((size_t)h * L + l0) * MF;
        const __nv_bfloat16* pkh = g_pkhi + ((size_t)h * L + l0) * MF;
        const __nv_bfloat16* pkl = g_pklo + ((size_t)h * L + l0) * MF;
        for (int i = tid; i < 1024; i += 256) {
            int r = i >> 4, cc = i & 15;
            CP_ASYNC16(sb + CO_QH + r*PQ + cc*16, pqh + (size_t)r*MF + cc*8);
            CP_ASYNC16(sb + CO_QL + r*PQ + cc*16, pql + (size_t)r*MF + cc*8);
            CP_ASYNC16(sb + CO_KH + r*PQ + cc*16, pkh + (size_t)r*MF + cc*8);
            CP_ASYNC16(sb + CO_KL + r*PQ + cc*16, pkl + (size_t)r*MF + cc*8);
        }
        for (int i = tid; i < 512; i += 256) {
            int r = i >> 3, cc = i & 7;
            CP_ASYNC16(sb + CO_VH + r*PV + cc*16, g_vhi + (size_t)(l0 + r)*DM + h*DH + cc*8);
            CP_ASYNC16(sb + CO_VL + r*PV + cc*16, g_vlo + (size_t)(l0 + r)*DM + h*DH + cc*8);
        }
        const __nv_bfloat16* sh = g_Shi + (size_t)(h*NC + c)*MF*DH;
        const __nv_bfloat16* sl = g_Slo + (size_t)(h*NC + c)*MF*DH;
        for (int i = tid; i < 1024; i += 256) {
            int r = i >> 3, cc = i & 7;
            CP_ASYNC16(sb + CO_SH + r*PV + cc*16, sh + (size_t)r*DH + cc*8);
            CP_ASYNC16(sb + CO_SL + r*PV + cc*16, sl + (size_t)r*DH + cc*8);
        }
        if (tid < 32) CP_ASYNC16(sb + CO_ZB + tid*16, g_z + (size_t)(h*NC + c)*MF + tid*4);
        CP_COMMIT(); CP_WAIT0();
    }
    __syncthreads();

    uint32_t a_off = (uint32_t)(warp_m*32 + (lane & 15)) * PQ + (lane >> 4) * 16;
    uint32_t b_off = (uint32_t)(warp_n*16 + (lane & 7) + (lane >> 4) * 8) * PQ + ((lane >> 3) & 1) * 16;

    float acc[2][2][4];
#pragma unroll
    for (int i = 0; i < 2; i++)
#pragma unroll
        for (int j = 0; j < 2; j++)
#pragma unroll
            for (int r = 0; r < 4; r++) acc[i][j][r] = 0.f;

#pragma unroll
    for (int ks = 0; ks < 8; ks++) {
        uint32_t ah[2][4], al[2][4], bh[4], bl[4];
#pragma unroll
        for (int mi = 0; mi < 2; mi++) {
            LDSM4(ah[mi][0], ah[mi][1], ah[mi][2], ah[mi][3], sb + CO_QH + a_off + mi*16*PQ + ks*32);
            LDSM4(al[mi][0], al[mi][1], al[mi][2], al[mi][3], sb + CO_QL + a_off + mi*16*PQ + ks*32);
        }
        LDSM4(bh[0], bh[1], bh[2], bh[3], sb + CO_KH + b_off + ks*32);
        LDSM4(bl[0], bl[1], bl[2], bl[3], sb + CO_KL + b_off + ks*32);
#pragma unroll
        for (int mi = 0; mi < 2; mi++) {
            MMA16816(acc[mi][0], ah[mi], bh[0], bh[1]);
            MMA16816(acc[mi][1], ah[mi], bh[2], bh[3]);
            MMA16816(acc[mi][0], ah[mi], bl[0], bl[1]);
            MMA16816(acc[mi][1], ah[mi], bl[2], bl[3]);
            MMA16816(acc[mi][0], al[mi], bh[0], bh[1]);
            MMA16816(acc[mi][1], al[mi], bh[2], bh[3]);
        }
    }

    int g = lane >> 2, t = lane & 3;
    float* pr = (float*)(smc + CO_PR);
#pragma unroll
    for (int mi = 0; mi < 2; mi++) {
#pragma unroll
        for (int half = 0; half < 2; half++) {
            int row = warp_m*32 + mi*16 + g + half*8;
            float rsum = 0.f;
#pragma unroll
            for (int nj = 0; nj < 2; nj++) {
                int col = warp_n*16 + nj*8 + t*2;
                float x = (col     <= row) ? acc[mi][nj][half*2+0] : 0.f;
                float y = (col + 1 <= row) ? acc[mi][nj][half*2+1] : 0.f;
                rsum += x + y;
                __nv_bfloat162 hv, lv;
                split2(x, y, hv, lv);
                *(__nv_bfloat162*)(smc + CO_AH + row*PV + col*2) = hv;
                *(__nv_bfloat162*)(smc + CO_AL + row*PV + col*2) = lv;
            }
            rsum += __shfl_xor_sync(0xffffffffu, rsum, 1);
            rsum += __shfl_xor_sync(0xffffffffu, rsum, 2);
            if (t == 0) pr[row*4 + warp_n] = rsum;
        }
    }
    __syncthreads();

    if (tid < 64) {
        float s = pr[tid*4+0] + pr[tid*4+1] + pr[tid*4+2] + pr[tid*4+3];
        const float* zf = (const float*)(smc + CO_ZB);
#pragma unroll 8
        for (int m2 = 0; m2 < 64; m2++) {
            __nv_bfloat162 qh2 = *(const __nv_bfloat162*)(smc + CO_QH + tid*PQ + m2*4);
            __nv_bfloat162 ql2 = *(const __nv_bfloat162*)(smc + CO_QL + tid*PQ + m2*4);
            float2 z2 = *(const float2*)(zf + m2*2);
            s += (__bfloat162float(qh2.x) + __bfloat162float(ql2.x)) * z2.x
               + (__bfloat162float(qh2.y) + __bfloat162float(ql2.y)) * z2.y;
        }
        ((float*)(smc + CO_RS))[tid] = s + DEPS;
    }

    float o[2][2][4];
#pragma unroll
    for (int i = 0; i < 2; i++)
#pragma unroll
        for (int j = 0; j < 2; j++)
#pragma unroll
            for (int r = 0; r < 4; r++) o[i][j][r] = 0.f;

    uint32_t a2_off = (uint32_t)(warp_m*32 + (lane & 15)) * PV + (lane >> 4) * 16;
    uint32_t bt_off = (uint32_t)(lane & 15) * PV + (warp_n*16 + (lane >> 4) * 8) * 2;

#pragma unroll
    for (int ks = 0; ks < 4; ks++) {
        uint32_t ah[2][4], al[2][4], bh[4], bl[4];
#pragma unroll
        for (int mi = 0; mi < 2; mi++) {
            LDSM4(ah[mi][0], ah[mi][1], ah[mi][2], ah[mi][3], sb + CO_AH + a2_off + mi*16*PV + ks*32);
            LDSM4(al[mi][0], al[mi][1], al[mi][2], al[mi][3], sb + CO_AL + a2_off + mi*16*PV + ks*32);
        }
        LDSM4T(bh[0], bh[1], bh[2], bh[3], sb + CO_VH + bt_off + ks*16*PV);
        LDSM4T(bl[0], bl[1], bl[2], bl[3], sb + CO_VL + bt_off + ks*16*PV);
#pragma unroll
        for (int mi = 0; mi < 2; mi++) {
            MMA16816(o[mi][0], ah[mi], bh[0], bh[1]);
            MMA16816(o[mi][1], ah[mi], bh[2], bh[3]);
            MMA16816(o[mi][0], ah[mi], bl[0], bl[1]);
            MMA16816(o[mi][1], ah[mi], bl[2], bl[3]);
            MMA16816(o[mi][0], al[mi], bh[0], bh[1]);
            MMA16816(o[mi][1], al[mi], bh[2], bh[3]);
        }
    }
#pragma unroll
    for (int ks = 0; ks < 8; ks++) {
        uint32_t ah[2][4], al[2][4], bh[4], bl[4];
#pragma unroll
        for (int mi = 0; mi < 2; mi++) {
            LDSM4(ah[mi][0], ah[mi][1], ah[mi][2], ah[mi][3], sb + CO_QH + a_off + mi*16*PQ + ks*32);
            LDSM4(al[mi][0], al[mi][1], al[mi][2], al[mi][3], sb + CO_QL + a_off + mi*16*PQ + ks*32);
        }
        LDSM4T(bh[0], bh[1], bh[2], bh[3], sb + CO_SH + bt_off + ks*16*PV);
        LDSM4T(bl[0], bl[1], bl[2], bl[3], sb + CO_SL + bt_off + ks*16*PV);
#pragma unroll
        for (int mi = 0; mi < 2; mi++) {
            MMA16816(o[mi][0], ah[mi], bh[0], bh[1]);
            MMA16816(o[mi][1], ah[mi], bh[2], bh[3]);
            MMA16816(o[mi][0], ah[mi], bl[0], bl[1]);
            MMA16816(o[mi][1], ah[mi], bl[2], bl[3]);
            MMA16816(o[mi][0], al[mi], bh[0], bh[1]);
            MMA16816(o[mi][1], al[mi], bh[2], bh[3]);
        }
    }
    __syncthreads();

    const float* rs = (const float*)(smc + CO_RS);
#pragma unroll
    for (int mi = 0; mi < 2; mi++) {
#pragma unroll
        for (int half = 0; half < 2; half++) {
            int row = warp_m*32 + mi*16 + g + half*8;
            float inv = 1.0f / rs[row];
#pragma unroll
            for (int nj = 0; nj < 2; nj++) {
                int col = warp_n*16 + nj*8 + t*2;
                float ox = o[mi][nj][half*2+0] * inv;
                float oy = o[mi][nj][half*2+1] * inv;
                __nv_bfloat162 hv, lv;
                split2(ox, oy, hv, lv);
                size_t off = (size_t)(l0 + row) * DM + h*DH + col;
                *(__nv_bfloat162*)(g_bhi_ctx + off) = hv;
                *(__nv_bfloat162*)(g_blo_ctx + off) = lv;
            }
        }
    }
}

// ---------------- launcher ----------------
extern "C" void kernel_launch(void* const* d_in, const int* in_sizes, int n_in,
                              void* d_out, int out_size)
{
    const float* query = (const float*)d_in[0];
    const float* key_i = (const float*)d_in[1];
    const float* value = (const float*)d_in[2];
    const float* Wq = (const float*)d_in[3];
    const float* bq = (const float*)d_in[4];
    const float* Wk = (const float*)d_in[5];
    const float* bk = (const float*)d_in[6];
    const float* Wv = (const float*)d_in[7];
    const float* bv = (const float*)d_in[8];
    const float* Wo = (const float*)d_in[9];
    const float* bo = (const float*)d_in[10];
    const float* rf = (const float*)d_in[11];
    float* out = (float*)d_out;

    void* p;
    cudaGetSymbolAddress(&p, g_bhi_in);  __nv_bfloat16* bhi_in = (__nv_bfloat16*)p;
    cudaGetSymbolAddress(&p, g_blo_in);  __nv_bfloat16* blo_in = (__nv_bfloat16*)p;
    cudaGetSymbolAddress(&p, g_bhi_w);   __nv_bfloat16* bhi_w  = (__nv_bfloat16*)p;
    cudaGetSymbolAddress(&p, g_blo_w);   __nv_bfloat16* blo_w  = (__nv_bfloat16*)p;
    cudaGetSymbolAddress(&p, g_bhi_ctx); __nv_bfloat16* bhi_c  = (__nv_bfloat16*)p;
    cudaGetSymbolAddress(&p, g_blo_ctx); __nv_bfloat16* blo_c  = (__nv_bfloat16*)p;
    cudaGetSymbolAddress(&p, g_qhi);     __nv_bfloat16* qhi    = (__nv_bfloat16*)p;
    cudaGetSymbolAddress(&p, g_qlo);     __nv_bfloat16* qlo    = (__nv_bfloat16*)p;
    cudaGetSymbolAddress(&p, g_khi);     __nv_bfloat16* khi    = (__nv_bfloat16*)p;
    cudaGetSymbolAddress(&p, g_klo);     __nv_bfloat16* klo    = (__nv_bfloat16*)p;
    cudaGetSymbolAddress(&p, g_vhi);     __nv_bfloat16* vhi    = (__nv_bfloat16*)p;
    cudaGetSymbolAddress(&p, g_vlo);     __nv_bfloat16* vlo    = (__nv_bfloat16*)p;

    reset_kstab<<<1, 1>>>();

    CV cv;
    cv.src[0]=query; cv.hi[0]=bhi_in;          cv.lo[0]=blo_in;          cv.n[0]=L*DM;
    cv.src[1]=key_i; cv.hi[1]=bhi_in+L*DM;     cv.lo[1]=blo_in+L*DM;     cv.n[1]=L*DM;
    cv.src[2]=value; cv.hi[2]=bhi_in+2*L*DM;   cv.lo[2]=blo_in+2*L*DM;   cv.n[2]=L*DM;
    cv.src[3]=Wq;    cv.hi[3]=bhi_w;           cv.lo[3]=blo_w;           cv.n[3]=DM*DM;
    cv.src[4]=Wk;    cv.hi[4]=bhi_w+DM*DM;     cv.lo[4]=blo_w+DM*DM;     cv.n[4]=DM*DM;
    cv.src[5]=Wv;    cv.hi[5]=bhi_w+2*DM*DM;   cv.lo[5]=blo_w+2*DM*DM;   cv.n[5]=DM*DM;
    cv.src[6]=Wo;    cv.hi[6]=bhi_w+3*DM*DM;   cv.lo[6]=blo_w+3*DM*DM;   cv.n[6]=DM*DM;
    cv.cnt = 7;
    convert_split<<<dim3((L*DM)/1024, 7), 256>>>(cv);
    rf_convert<<<(MF*DH + 255)/256, 256>>>(rf);

    cudaFuncSetAttribute(hmma_gemm, cudaFuncAttributeMaxDynamicSharedMemorySize, HG_SMEM);
    cudaFuncSetAttribute(rf_proj_hmma, cudaFuncAttributeMaxDynamicSharedMemorySize, RF_SMEM);
    cudaFuncSetAttribute(chunk_state_hmma, cudaFuncAttributeMaxDynamicSharedMemorySize, CS_TOTAL);
    cudaFuncSetAttribute(chunk_out_hmma, cudaFuncAttributeMaxDynamicSharedMemorySize, CO_TOTAL);

    // QKV projections (hk fused into z==1 epilogue)
    MMArgs mq;
    mq.Ahi[0]=bhi_in;        mq.Alo[0]=blo_in;        mq.Whi[0]=bhi_w;        mq.Wlo[0]=blo_w;        mq.bias[0]=bq; mq.C[0]=nullptr; mq.Chi[0]=qhi; mq.Clo[0]=qlo; mq.alpha[0]=SCALE_QK;
    mq.Ahi[1]=bhi_in+L*DM;   mq.Alo[1]=blo_in+L*DM;   mq.Whi[1]=bhi_w+DM*DM;  mq.Wlo[1]=blo_w+DM*DM;  mq.bias[1]=bk; mq.C[1]=nullptr; mq.Chi[1]=khi; mq.Clo[1]=klo; mq.alpha[1]=SCALE_QK;
    mq.Ahi[2]=bhi_in+2*L*DM; mq.Alo[2]=blo_in+2*L*DM; mq.Whi[2]=bhi_w+2*DM*DM;mq.Wlo[2]=blo_w+2*DM*DM;mq.bias[2]=bv; mq.C[2]=nullptr; mq.Chi[2]=vhi; mq.Clo[2]=vlo; mq.alpha[2]=1.0f;
    hmma_gemm<<<dim3(DM/128, L/64, 3), 256, HG_SMEM>>>(mq, 1);

    rf_proj_hmma<<<dim3(1, L/128, 16), 256, RF_SMEM>>>();

    chunk_state_hmma<<<dim3(NC, NH), 256, CS_TOTAL>>>();
    prefix_scan<<<dim3((MF*DH + MF + 255)/256, NH), 256>>>();
    chunk_out_hmma<<<dim3(NC, NH), 256, CO_TOTAL>>>();

    // output projection
    MMArgs mo;
    mo.Ahi[0]=bhi_c; mo.Alo[0]=blo_c; mo.Whi[0]=bhi_w+3*DM*DM; mo.Wlo[0]=blo_w+3*DM*DM; mo.bias[0]=bo; mo.C[0]=out; mo.Chi[0]=nullptr; mo.Clo[0]=nullptr; mo.alpha[0]=1.0f;
    mo.Ahi[1]=mo.Ahi[0]; mo.Alo[1]=mo.Alo[0]; mo.Whi[1]=mo.Whi[0]; mo.Wlo[1]=mo.Wlo[0]; mo.bias[1]=bo; mo.C[1]=out; mo.Chi[1]=nullptr; mo.Clo[1]=nullptr; mo.alpha[1]=1.0f;
    mo.Ahi[2]=mo.Ahi[0]; mo.Alo[2]=mo.Alo[0]; mo.Whi[2]=mo.Whi[0]; mo.Wlo[2]=mo.Wlo[0]; mo.bias[2]=bo; mo.C[2]=out; mo.Chi[2]=nullptr; mo.Clo[2]=nullptr; mo.alpha[2]=1.0f;
    hmma_gemm<<<dim3(DM/128, L/64, 1), 256, HG_SMEM>>>(mo, 0);
}